// round 1
// baseline (speedup 1.0000x reference)
#include <cuda_runtime.h>
#include <math.h>

#define B_  2
#define L_  8192
#define D_  64
#define CR_ 2048
#define NC_ 48
#define TE_ 512
#define NL_ 8
#define M_  1024   // NL*2*D rows of the batched cross GEMM

// ---------------- scratch (device globals; no allocation allowed) ----------------
__device__ float g_Wbig[M_*CR_];          // packed [1024, 2048] cross weights (q/k all layers)
__device__ float g_QKC [M_*B_*L_];        // cross-projection results [m][n][l]
__device__ float g_convT[NL_*5*64*64];    // conv weights transposed [i][j][c][d]
__device__ float g_qT  [NL_*64*64];       // self-part of qw, transposed [i][c][d]
__device__ float g_kT  [NL_*64*64];
__device__ float g_vT  [NL_*64*64];
__device__ float g_f1T [NL_*64*64];
__device__ float g_f2T [NL_*64*64];
__device__ float g_fra [B_*D_*L_];
__device__ float g_xq  [B_*D_*L_];
__device__ float g_xk  [B_*D_*L_];
__device__ float g_xv  [B_*D_*L_];
__device__ float g_out1[B_*D_*L_];
__device__ float g_y   [B_*D_*L_];
__device__ float g_att [B_*5*L_];
__device__ float g_part[B_*D_*32*2];
__device__ float g_norm[B_*D_*2];
__device__ float g_tproj[B_*D_];

// ---------------- shared-mem 64x64 micro-matmul (16x16 threads, 4x4 per thread) ----
__device__ __forceinline__ void mm_16x16(const float (*Ws)[64], const float (*Xs)[64],
                                         float acc[4][4], int ty4, int tx4) {
#pragma unroll 16
    for (int c = 0; c < 64; ++c) {
        const float4 a = *(const float4*)(&Ws[c][ty4]);
        const float4 b = *(const float4*)(&Xs[c][tx4]);
        acc[0][0] += a.x*b.x; acc[0][1] += a.x*b.y; acc[0][2] += a.x*b.z; acc[0][3] += a.x*b.w;
        acc[1][0] += a.y*b.x; acc[1][1] += a.y*b.y; acc[1][2] += a.y*b.z; acc[1][3] += a.y*b.w;
        acc[2][0] += a.z*b.x; acc[2][1] += a.z*b.y; acc[2][2] += a.z*b.z; acc[2][3] += a.z*b.w;
        acc[3][0] += a.w*b.x; acc[3][1] += a.w*b.y; acc[3][2] += a.w*b.z; acc[3][3] += a.w*b.w;
    }
}

// ---------------- weight packing ----------------
__global__ void pack_w_kernel(const float* __restrict__ qw, const float* __restrict__ kw) {
    int idx = blockIdx.x * 256 + threadIdx.x;       // M_*CR_ = 2097152 elements
    int m = idx >> 11, c = idx & 2047;
    int i = m >> 7, r = m & 127, s = r >> 6, d = r & 63;
    const float* src = s ? kw : qw;
    g_Wbig[idx] = src[(i*64 + d)*2112 + 64 + c];
}

__global__ void pack_small_kernel(const float* __restrict__ convw, const float* __restrict__ qw,
                                  const float* __restrict__ kw,   const float* __restrict__ vw,
                                  const float* __restrict__ f1w,  const float* __restrict__ f2w) {
    int idx = blockIdx.x * 256 + threadIdx.x;       // grid covers NL_*5*4096
    if (idx < NL_*5*64*64) {
        int d = idx & 63, c = (idx >> 6) & 63, r = idx >> 12, j = r % 5, i = r / 5;
        g_convT[idx] = convw[((i*64 + d)*64 + c)*5 + j];
    }
    if (idx < NL_*64*64) {
        int d = idx & 63, c = (idx >> 6) & 63, i = idx >> 12;
        g_qT [idx] = qw [(i*64 + d)*2112 + c];
        g_kT [idx] = kw [(i*64 + d)*2112 + c];
        g_vT [idx] = vw [(i*64 + d)*64 + c];
        g_f1T[idx] = f1w[(i*64 + d)*64 + c];
        g_f2T[idx] = f2w[(i*64 + d)*64 + c];
    }
}

// ---------------- timestep embedding MLP ----------------
__global__ void temb_kernel(const int* __restrict__ t,
                            const float* __restrict__ w1, const float* __restrict__ b1,
                            const float* __restrict__ w2, const float* __restrict__ b2,
                            const float* __restrict__ wp, const float* __restrict__ bp) {
    __shared__ float se[TE_], st[TE_];
    const int n = blockIdx.x, tid = threadIdx.x;
    const float tv = (float)t[n];
    if (tid < 256) {
        float f = expf((float)tid * (-logf(10000.0f) / 255.0f));
        float a = tv * f;
        se[tid] = sinf(a);
        se[tid + 256] = cosf(a);
    }
    __syncthreads();
    {
        float s = b1[tid];
        const float* w = w1 + tid * TE_;
        for (int c = 0; c < TE_; ++c) s += se[c] * w[c];
        st[tid] = s / (1.f + expf(-s));            // swish
    }
    __syncthreads();
    {
        float s = b2[tid];
        const float* w = w2 + tid * TE_;
        for (int c = 0; c < TE_; ++c) s += st[c] * w[c];
        se[tid] = s / (1.f + expf(-s));            // swish(temb) for the projection
    }
    __syncthreads();
    if (tid < D_) {
        float s = bp[tid];
        const float* w = wp + tid * TE_;
        for (int c = 0; c < TE_; ++c) s += se[c] * w[c];
        g_tproj[n * D_ + tid] = s;
    }
}

// ---------------- conv_in (1x1, 48->64) + time projection add ----------------
__global__ void __launch_bounds__(256) conv_in_kernel(const float* __restrict__ event,
                                                      const float* __restrict__ w,
                                                      const float* __restrict__ b) {
    __shared__ float Et[NC_][64];
    __shared__ float Wt[NC_][64];
    const int n = blockIdx.y, l0 = blockIdx.x * 64;
    const int tid = threadIdx.x, ty4 = (tid >> 4) << 2, tx4 = (tid & 15) << 2;
    for (int e = tid; e < NC_*64; e += 256) {
        int c = e >> 6, tt = e & 63;
        Et[c][tt] = event[(n*NC_ + c)*L_ + l0 + tt];
        Wt[c][tt] = w[tt*NC_ + c];
    }
    __syncthreads();
    float acc[4][4] = {};
#pragma unroll
    for (int c = 0; c < NC_; ++c) {
        const float4 a = *(const float4*)(&Wt[c][ty4]);
        const float4 x4 = *(const float4*)(&Et[c][tx4]);
        acc[0][0]+=a.x*x4.x; acc[0][1]+=a.x*x4.y; acc[0][2]+=a.x*x4.z; acc[0][3]+=a.x*x4.w;
        acc[1][0]+=a.y*x4.x; acc[1][1]+=a.y*x4.y; acc[1][2]+=a.y*x4.z; acc[1][3]+=a.y*x4.w;
        acc[2][0]+=a.z*x4.x; acc[2][1]+=a.z*x4.y; acc[2][2]+=a.z*x4.z; acc[2][3]+=a.z*x4.w;
        acc[3][0]+=a.w*x4.x; acc[3][1]+=a.w*x4.y; acc[3][2]+=a.w*x4.z; acc[3][3]+=a.w*x4.w;
    }
#pragma unroll
    for (int i = 0; i < 4; ++i)
#pragma unroll
        for (int j = 0; j < 4; ++j) {
            int d = ty4 + i, l = l0 + tx4 + j;
            g_fra[(n*D_ + d)*L_ + l] = acc[i][j] + b[d] + g_tproj[n*D_ + d];
        }
}

// ---------------- big batched cross GEMM: g_QKC = g_Wbig @ x ----------------
__global__ void __launch_bounds__(256) gemm_cross_kernel(const float* __restrict__ x) {
    __shared__ float Wt[16][64];
    __shared__ float Xt[16][128];
    const int n = blockIdx.z;
    const int m0 = blockIdx.y * 64;
    const int l0 = blockIdx.x * 128;
    const int tid = threadIdx.x, ty = tid >> 4, tx = tid & 15;
    float acc[4][8] = {};
    const float* xb = x + (size_t)n * CR_ * L_;
    const int wm = tid & 63, wk = (tid >> 6) << 2;
    for (int c0 = 0; c0 < CR_; c0 += 16) {
        float4 w4 = *(const float4*)(g_Wbig + (size_t)(m0 + wm)*CR_ + c0 + wk);
        Wt[wk+0][wm] = w4.x; Wt[wk+1][wm] = w4.y; Wt[wk+2][wm] = w4.z; Wt[wk+3][wm] = w4.w;
#pragma unroll
        for (int idx = tid; idx < 512; idx += 256) {
            int row = idx >> 5, col = (idx & 31) << 2;
            *(float4*)(&Xt[row][col]) = *(const float4*)(xb + (size_t)(c0 + row)*L_ + l0 + col);
        }
        __syncthreads();
#pragma unroll
        for (int kk = 0; kk < 16; ++kk) {
            const float4 a = *(const float4*)(&Wt[kk][ty*4]);
            const float4 p = *(const float4*)(&Xt[kk][tx*8]);
            const float4 q = *(const float4*)(&Xt[kk][tx*8 + 4]);
            float av[4] = {a.x, a.y, a.z, a.w};
            float bv[8] = {p.x, p.y, p.z, p.w, q.x, q.y, q.z, q.w};
#pragma unroll
            for (int i = 0; i < 4; ++i)
#pragma unroll
                for (int j = 0; j < 8; ++j) acc[i][j] += av[i] * bv[j];
        }
        __syncthreads();
    }
#pragma unroll
    for (int i = 0; i < 4; ++i)
#pragma unroll
        for (int j = 0; j < 8; ++j)
            g_QKC[(size_t)(m0 + ty*4 + i)*(B_*L_) + n*L_ + l0 + tx*8 + j] = acc[i][j];
}

// ---------------- per-layer: dilated conv (5 shifted matmuls) + q/k/v projections ---
__global__ void __launch_bounds__(256) layer_a_kernel(const float* __restrict__ convb,
                                                      const float* __restrict__ qb,
                                                      const float* __restrict__ kb,
                                                      const float* __restrict__ vb,
                                                      int layer, int dil) {
    __shared__ float Xs[64][64];
    __shared__ float Ws[64][64];
    const int n = blockIdx.y, l0 = blockIdx.x * 64;
    const int tid = threadIdx.x, ty4 = (tid >> 4) << 2, tx4 = (tid & 15) << 2;
    const float* fb = g_fra + (size_t)n * D_ * L_;

    // dilated conv: out1 = sum_j Wj @ shift(fra, (j-2)*dil)
    float acc[4][4] = {};
    for (int j = 0; j < 5; ++j) {
        int shift = (j - 2) * dil;
        const float* wsrc = g_convT + (size_t)(layer*5 + j) * 4096;
        for (int e = tid; e < 4096; e += 256) {
            int c = e >> 6, tt = e & 63, p = l0 + tt + shift;
            Xs[c][tt] = ((unsigned)p < (unsigned)L_) ? fb[c*L_ + p] : 0.f;
            ((float*)Ws)[e] = wsrc[e];
        }
        __syncthreads();
        mm_16x16(Ws, Xs, acc, ty4, tx4);
        __syncthreads();
    }
#pragma unroll
    for (int i = 0; i < 4; ++i)
#pragma unroll
        for (int j = 0; j < 4; ++j) {
            int d = ty4 + i, l = l0 + tx4 + j;
            g_out1[(n*D_ + d)*L_ + l] = acc[i][j] + convb[layer*64 + d];
        }

    // load the un-shifted fra tile once, reused for q/k/v self parts
    for (int e = tid; e < 4096; e += 256) {
        int c = e >> 6, tt = e & 63;
        Xs[c][tt] = fb[c*L_ + l0 + tt];
    }
    // q
    {
        const float* wsrc = g_qT + (size_t)layer * 4096;
        for (int e = tid; e < 4096; e += 256) ((float*)Ws)[e] = wsrc[e];
        __syncthreads();
        float a2[4][4] = {};
        mm_16x16(Ws, Xs, a2, ty4, tx4);
        __syncthreads();
#pragma unroll
        for (int i = 0; i < 4; ++i)
#pragma unroll
            for (int j = 0; j < 4; ++j) {
                int d = ty4 + i, l = l0 + tx4 + j;
                g_xq[(n*D_ + d)*L_ + l] = a2[i][j] + qb[layer*64 + d]
                    + g_QKC[(size_t)((layer*2)*64 + d)*(B_*L_) + n*L_ + l];
            }
    }
    // k
    {
        const float* wsrc = g_kT + (size_t)layer * 4096;
        for (int e = tid; e < 4096; e += 256) ((float*)Ws)[e] = wsrc[e];
        __syncthreads();
        float a2[4][4] = {};
        mm_16x16(Ws, Xs, a2, ty4, tx4);
        __syncthreads();
#pragma unroll
        for (int i = 0; i < 4; ++i)
#pragma unroll
            for (int j = 0; j < 4; ++j) {
                int d = ty4 + i, l = l0 + tx4 + j;
                g_xk[(n*D_ + d)*L_ + l] = a2[i][j] + kb[layer*64 + d]
                    + g_QKC[(size_t)((layer*2 + 1)*64 + d)*(B_*L_) + n*L_ + l];
            }
    }
    // v
    {
        const float* wsrc = g_vT + (size_t)layer * 4096;
        for (int e = tid; e < 4096; e += 256) ((float*)Ws)[e] = wsrc[e];
        __syncthreads();
        float a2[4][4] = {};
        mm_16x16(Ws, Xs, a2, ty4, tx4);
#pragma unroll
        for (int i = 0; i < 4; ++i)
#pragma unroll
            for (int j = 0; j < 4; ++j) {
                int d = ty4 + i, l = l0 + tx4 + j;
                g_xv[(n*D_ + d)*L_ + l] = a2[i][j] + vb[layer*64 + d];
            }
    }
}

// ---------------- attention scores (window K=5, softmax with padding mask) ----------
__global__ void attn_score_kernel(int dil) {
    const int n = blockIdx.y;
    const int l = blockIdx.x * 256 + threadIdx.x;
    const float* qb_ = g_xq + (size_t)n * D_ * L_ + l;
    const float* kb_ = g_xk + (size_t)n * D_ * L_;
    int p[5]; bool v[5];
#pragma unroll
    for (int j = 0; j < 5; ++j) { p[j] = l + (j - 2) * dil; v[j] = ((unsigned)p[j] < (unsigned)L_); }
    float dot[5] = {};
#pragma unroll 8
    for (int c = 0; c < 64; ++c) {
        float qv = qb_[c * L_];
#pragma unroll
        for (int j = 0; j < 5; ++j) if (v[j]) dot[j] += qv * kb_[c*L_ + p[j]];
    }
    const float LVALID = logf(1.0f + 1e-6f);
    const float LINV   = logf(1e-6f);
    float lg[5];
#pragma unroll
    for (int j = 0; j < 5; ++j) lg[j] = v[j] ? dot[j]*0.125f + LVALID : LINV;
    float mx = lg[0];
#pragma unroll
    for (int j = 1; j < 5; ++j) mx = fmaxf(mx, lg[j]);
    float e[5], s = 0.f;
#pragma unroll
    for (int j = 0; j < 5; ++j) { e[j] = expf(lg[j] - mx); s += e[j]; }
    float inv = 1.f / s;
#pragma unroll
    for (int j = 0; j < 5; ++j)
        g_att[(size_t)n*5*L_ + j*L_ + l] = v[j] ? e[j]*inv : 0.f;
}

// ---------------- apply attention, y = out1 + r, partial instance-norm stats --------
__global__ void attn_apply_kernel(int dil) {
    const int n = blockIdx.z, c = blockIdx.y;
    const int tid = threadIdx.x;
    const int l = blockIdx.x * 256 + tid;
    const float* vb_ = g_xv + (size_t)(n*D_ + c) * L_;
    const float* ab_ = g_att + (size_t)n * 5 * L_ + l;
    float r = 0.f;
#pragma unroll
    for (int j = 0; j < 5; ++j) {
        int pp = l + (j - 2) * dil;
        if ((unsigned)pp < (unsigned)L_) r += ab_[j * L_] * vb_[pp];
    }
    size_t o = (size_t)(n*D_ + c) * L_ + l;
    float yv = g_out1[o] + r;
    g_y[o] = yv;
    __shared__ float s1[256], s2[256];
    s1[tid] = yv; s2[tid] = yv * yv;
    __syncthreads();
    for (int st = 128; st > 0; st >>= 1) {
        if (tid < st) { s1[tid] += s1[tid + st]; s2[tid] += s2[tid + st]; }
        __syncthreads();
    }
    if (tid == 0) {
        g_part[((n*D_ + c)*32 + blockIdx.x)*2 + 0] = s1[0];
        g_part[((n*D_ + c)*32 + blockIdx.x)*2 + 1] = s2[0];
    }
}

__global__ void norm_stats_kernel() {
    int t = threadIdx.x;                       // 128 = B_*D_
    float s = 0.f, s2 = 0.f;
    for (int bq = 0; bq < 32; ++bq) {
        s  += g_part[(t*32 + bq)*2 + 0];
        s2 += g_part[(t*32 + bq)*2 + 1];
    }
    float mean = s / (float)L_;
    float var = s2 / (float)L_ - mean*mean;
    g_norm[t*2 + 0] = mean;
    g_norm[t*2 + 1] = rsqrtf(var + 1e-5f);
}

// ---------------- instance-norm + FFN + residual into fra ----------------
__global__ void __launch_bounds__(256) ffn_kernel(const float* __restrict__ f1b,
                                                  const float* __restrict__ f2b,
                                                  int layer) {
    __shared__ float Xs[64][64];
    __shared__ float Ws[64][64];
    const int n = blockIdx.y, l0 = blockIdx.x * 64;
    const int tid = threadIdx.x, ty4 = (tid >> 4) << 2, tx4 = (tid & 15) << 2;
    {
        const float* wsrc = g_f1T + (size_t)layer * 4096;
        for (int e = tid; e < 4096; e += 256) {
            int c = e >> 6, tt = e & 63;
            float mean = g_norm[(n*D_ + c)*2 + 0];
            float rstd = g_norm[(n*D_ + c)*2 + 1];
            Xs[c][tt] = (g_y[(size_t)(n*D_ + c)*L_ + l0 + tt] - mean) * rstd;
            ((float*)Ws)[e] = wsrc[e];
        }
    }
    __syncthreads();
    float acc[4][4] = {};
    mm_16x16(Ws, Xs, acc, ty4, tx4);
    __syncthreads();
    // relu(h1) back into Xs (as the new "c" dim), load f2 weights
#pragma unroll
    for (int i = 0; i < 4; ++i)
#pragma unroll
        for (int j = 0; j < 4; ++j)
            Xs[ty4 + i][tx4 + j] = fmaxf(acc[i][j] + f1b[layer*64 + ty4 + i], 0.f);
    {
        const float* wsrc = g_f2T + (size_t)layer * 4096;
        for (int e = tid; e < 4096; e += 256) ((float*)Ws)[e] = wsrc[e];
    }
    __syncthreads();
    float a2[4][4] = {};
    mm_16x16(Ws, Xs, a2, ty4, tx4);
#pragma unroll
    for (int i = 0; i < 4; ++i)
#pragma unroll
        for (int j = 0; j < 4; ++j) {
            int d = ty4 + i, l = l0 + tx4 + j;
            size_t o = (size_t)(n*D_ + d)*L_ + l;
            g_fra[o] += a2[i][j] + f2b[layer*64 + d];
        }
}

// ---------------- conv_out (1x1, 64->48) ----------------
__global__ void __launch_bounds__(256) conv_out_kernel(const float* __restrict__ w,
                                                       const float* __restrict__ b,
                                                       float* __restrict__ out) {
    __shared__ float Xs[64][64];
    __shared__ float Wt[64][NC_];
    const int n = blockIdx.y, l0 = blockIdx.x * 64;
    const int tid = threadIdx.x, ty = tid >> 4, tx = tid & 15;
    for (int e = tid; e < 4096; e += 256) {
        int c = e >> 6, tt = e & 63;
        Xs[c][tt] = g_fra[(size_t)(n*D_ + c)*L_ + l0 + tt];
    }
    for (int e = tid; e < 64*NC_; e += 256) {
        int c = e / NC_, o = e % NC_;
        Wt[c][o] = w[o*64 + c];
    }
    __syncthreads();
    if (ty < 12) {
        const int ty4 = ty*4, tx4 = tx*4;
        float acc[4][4] = {};
#pragma unroll 16
        for (int c = 0; c < 64; ++c) {
            const float4 a = *(const float4*)(&Wt[c][ty4]);
            const float4 x4 = *(const float4*)(&Xs[c][tx4]);
            acc[0][0]+=a.x*x4.x; acc[0][1]+=a.x*x4.y; acc[0][2]+=a.x*x4.z; acc[0][3]+=a.x*x4.w;
            acc[1][0]+=a.y*x4.x; acc[1][1]+=a.y*x4.y; acc[1][2]+=a.y*x4.z; acc[1][3]+=a.y*x4.w;
            acc[2][0]+=a.z*x4.x; acc[2][1]+=a.z*x4.y; acc[2][2]+=a.z*x4.z; acc[2][3]+=a.z*x4.w;
            acc[3][0]+=a.w*x4.x; acc[3][1]+=a.w*x4.y; acc[3][2]+=a.w*x4.z; acc[3][3]+=a.w*x4.w;
        }
#pragma unroll
        for (int i = 0; i < 4; ++i)
#pragma unroll
            for (int j = 0; j < 4; ++j) {
                int o = ty4 + i, l = l0 + tx4 + j;
                out[(size_t)(n*NC_ + o)*L_ + l] = acc[i][j] + b[o];
            }
    }
}

// ---------------- host side ----------------
extern "C" void kernel_launch(void* const* d_in, const int* in_sizes, int n_in,
                              void* d_out, int out_size) {
    (void)in_sizes; (void)n_in; (void)out_size;
    const float* x     = (const float*)d_in[0];
    const int*   t     = (const int*)  d_in[1];
    const float* event = (const float*)d_in[2];
    const float* tw1   = (const float*)d_in[3];
    const float* tb1   = (const float*)d_in[4];
    const float* tw2   = (const float*)d_in[5];
    const float* tb2   = (const float*)d_in[6];
    const float* tpw   = (const float*)d_in[7];
    const float* tpb   = (const float*)d_in[8];
    const float* ciw   = (const float*)d_in[9];
    const float* cib   = (const float*)d_in[10];
    const float* cow   = (const float*)d_in[11];
    const float* cob   = (const float*)d_in[12];
    const float* lcw   = (const float*)d_in[13];
    const float* lcb   = (const float*)d_in[14];
    const float* qw    = (const float*)d_in[15];
    const float* qb    = (const float*)d_in[16];
    const float* kw    = (const float*)d_in[17];
    const float* kb    = (const float*)d_in[18];
    const float* vw    = (const float*)d_in[19];
    const float* vb    = (const float*)d_in[20];
    const float* f1w   = (const float*)d_in[21];
    const float* f1b   = (const float*)d_in[22];
    const float* f2w   = (const float*)d_in[23];
    const float* f2b   = (const float*)d_in[24];

    pack_w_kernel<<<(M_*CR_)/256, 256>>>(qw, kw);
    pack_small_kernel<<<(NL_*5*64*64)/256, 256>>>(lcw, qw, kw, vw, f1w, f2w);
    temb_kernel<<<B_, TE_>>>(t, tw1, tb1, tw2, tb2, tpw, tpb);
    conv_in_kernel<<<dim3(L_/64, B_), 256>>>(event, ciw, cib);
    gemm_cross_kernel<<<dim3(L_/128, M_/64, B_), 256>>>(x);

    for (int i = 0; i < NL_; ++i) {
        int dil = 1 << i;
        layer_a_kernel<<<dim3(L_/64, B_), 256>>>(lcb, qb, kb, vb, i, dil);
        attn_score_kernel<<<dim3(L_/256, B_), 256>>>(dil);
        attn_apply_kernel<<<dim3(L_/256, D_, B_), 256>>>(dil);
        norm_stats_kernel<<<1, 128>>>();
        ffn_kernel<<<dim3(L_/64, B_), 256>>>(f1b, f2b, i);
    }
    conv_out_kernel<<<dim3(L_/64, B_), 256>>>(cow, cob, (float*)d_out);
}

// round 3
// speedup vs baseline: 1.7510x; 1.7510x over previous
#include <cuda_runtime.h>
#include <cuda_bf16.h>
#include <math.h>
#include <stdint.h>

#define B_  2
#define L_  8192
#define D_  64
#define CR_ 2048
#define NC_ 48
#define TE_ 512
#define NL_ 8
#define M_  1024        // NL*2*D rows of the batched cross GEMM
#define NCOL_ (B_*L_)   // 16384 columns
#define K6_ (3*CR_)     // 6144 augmented K (hi/hi/lo packing)

// ---------------- scratch (device globals; no allocation allowed) ----------------
__device__ __nv_bfloat16 g_Wp[(size_t)M_*K6_];        // A' = [Whi | Whi | Wlo], K-major
__device__ __nv_bfloat16 g_Xp[(size_t)NCOL_*K6_];     // B' = [Xhi ; Xlo ; Xhi], K-major per col
__device__ float g_QKC [(size_t)M_*NCOL_];            // cross-projection results [m][n*L+l]
__device__ float g_convT[NL_*5*64*64];
__device__ float g_qT  [NL_*64*64];
__device__ float g_kT  [NL_*64*64];
__device__ float g_vT  [NL_*64*64];
__device__ float g_f1T [NL_*64*64];
__device__ float g_f2T [NL_*64*64];
__device__ float g_fra [B_*D_*L_];
__device__ float g_xq  [B_*D_*L_];
__device__ float g_xk  [B_*D_*L_];
__device__ float g_xv  [B_*D_*L_];
__device__ float g_out1[B_*D_*L_];
__device__ float g_y   [B_*D_*L_];
__device__ float g_att [B_*5*L_];
__device__ float g_part[B_*D_*32*2];
__device__ float g_norm[B_*D_*2];
__device__ float g_tproj[B_*D_];

__device__ __forceinline__ uint32_t smem_u32(const void* p) {
    return (uint32_t)__cvta_generic_to_shared(p);
}

// ================== bf16 HMMA GEMM: g_QKC = A'(1024xK6) @ B'(K6 x 16384) ==================
#define GM_BM 128
#define GM_BN 128
#define GM_BK 32
#define GM_NT (K6_/GM_BK)      // 192
#define APAD 40                 // row stride in bf16 elements (80 bytes) -> conflict-free ldmatrix

__device__ __forceinline__ void ldsm_x4(uint32_t& r0, uint32_t& r1, uint32_t& r2, uint32_t& r3,
                                        uint32_t addr) {
    asm volatile("ldmatrix.sync.aligned.m8n8.x4.shared.b16 {%0,%1,%2,%3}, [%4];"
                 : "=r"(r0), "=r"(r1), "=r"(r2), "=r"(r3) : "r"(addr));
}
__device__ __forceinline__ void mma16816(float c[4], uint32_t a0, uint32_t a1, uint32_t a2,
                                         uint32_t a3, uint32_t b0, uint32_t b1) {
    asm volatile("mma.sync.aligned.m16n8k16.row.col.f32.bf16.bf16.f32 "
                 "{%0,%1,%2,%3}, {%4,%5,%6,%7}, {%8,%9}, {%0,%1,%2,%3};"
                 : "+f"(c[0]), "+f"(c[1]), "+f"(c[2]), "+f"(c[3])
                 : "r"(a0), "r"(a1), "r"(a2), "r"(a3), "r"(b0), "r"(b1));
}
__device__ __forceinline__ void cp16(uint32_t saddr, const void* gptr) {
    asm volatile("cp.async.ca.shared.global [%0], [%1], 16;" :: "r"(saddr), "l"(gptr));
}

__global__ void __launch_bounds__(256) gemm_bf16_kernel() {
    __shared__ __nv_bfloat16 As[2][GM_BM * APAD];
    __shared__ __nv_bfloat16 Bs[2][GM_BN * APAD];
    const int tid = threadIdx.x, lane = tid & 31, wid = tid >> 5;
    const int wm = wid >> 2, wn = wid & 3;            // warp tile: 64(m) x 32(n)
    const int m0 = blockIdx.x * GM_BM;                // grid.x = 8 (M blocks, fastest)
    const int col0 = blockIdx.y * GM_BN;

    // cp.async load: A/B each 128 rows x 4 chunks of 16B = 512 chunks; 2 per thread
    const int ldr = tid >> 1;                         // 0..127  (row)
    const int ldc = (tid & 1) * 2;                    // chunk 0/2 ; second chunk +1

    float acc[4][4][4];
#pragma unroll
    for (int i = 0; i < 4; ++i)
#pragma unroll
        for (int j = 0; j < 4; ++j)
#pragma unroll
            for (int q = 0; q < 4; ++q) acc[i][j][q] = 0.f;

    // per-lane ldmatrix base offsets (element units)
    const int lrow = lane & 15, lhalf = lane >> 4;    // row within 16, k-half (8 elems)

    auto load_tile = [&](int kt, int buf) {
        const size_t gk = (size_t)kt * GM_BK;
#pragma unroll
        for (int s = 0; s < 2; ++s) {
            int c = ldc + s;
            cp16(smem_u32(&As[buf][ldr * APAD + c * 8]),
                 g_Wp + (size_t)(m0 + ldr) * K6_ + gk + c * 8);
            cp16(smem_u32(&Bs[buf][ldr * APAD + c * 8]),
                 g_Xp + (size_t)(col0 + ldr) * K6_ + gk + c * 8);
        }
        asm volatile("cp.async.commit_group;");
    };

    load_tile(0, 0);
    for (int kt = 0; kt < GM_NT; ++kt) {
        const int cur = kt & 1;
        if (kt + 1 < GM_NT) {
            load_tile(kt + 1, cur ^ 1);
            asm volatile("cp.async.wait_group 1;");
        } else {
            asm volatile("cp.async.wait_group 0;");
        }
        __syncthreads();
#pragma unroll
        for (int kk2 = 0; kk2 < 2; ++kk2) {           // two k16 steps within BK=32
            uint32_t a[4][4];
#pragma unroll
            for (int mt = 0; mt < 4; ++mt) {
                uint32_t addr = smem_u32(&As[cur][(wm*64 + mt*16 + lrow) * APAD
                                                  + kk2*16 + lhalf*8]);
                ldsm_x4(a[mt][0], a[mt][1], a[mt][2], a[mt][3], addr);
            }
            uint32_t b[4][2];
#pragma unroll
            for (int nb2 = 0; nb2 < 2; ++nb2) {
                uint32_t r0, r1, r2, r3;
                uint32_t addr = smem_u32(&Bs[cur][(wn*32 + nb2*16 + lrow) * APAD
                                                  + kk2*16 + lhalf*8]);
                ldsm_x4(r0, r1, r2, r3, addr);
                b[nb2*2 + 0][0] = r0; b[nb2*2 + 0][1] = r2;
                b[nb2*2 + 1][0] = r1; b[nb2*2 + 1][1] = r3;
            }
#pragma unroll
            for (int mt = 0; mt < 4; ++mt)
#pragma unroll
                for (int nt = 0; nt < 4; ++nt)
                    mma16816(acc[mt][nt], a[mt][0], a[mt][1], a[mt][2], a[mt][3],
                             b[nt][0], b[nt][1]);
        }
        __syncthreads();
    }

    // epilogue
    const int grp = lane >> 2, qd = (lane & 3) * 2;
#pragma unroll
    for (int mt = 0; mt < 4; ++mt)
#pragma unroll
        for (int nt = 0; nt < 4; ++nt) {
            int m = m0 + wm*64 + mt*16 + grp;
            int n = col0 + wn*32 + nt*8 + qd;
            *(float2*)(g_QKC + (size_t)m * NCOL_ + n)      = make_float2(acc[mt][nt][0], acc[mt][nt][1]);
            *(float2*)(g_QKC + (size_t)(m + 8) * NCOL_ + n) = make_float2(acc[mt][nt][2], acc[mt][nt][3]);
        }
}

// ---------------- weight packing: fp32 -> bf16 hi/hi/lo augmented K ----------------
__global__ void pack_wp_kernel(const float* __restrict__ qw, const float* __restrict__ kw) {
    int idx = blockIdx.x * 256 + threadIdx.x;       // M_*CR_ elements
    int m = idx >> 11, c = idx & 2047;
    int i = m >> 7, r = m & 127, s = r >> 6, d = r & 63;
    const float* src = s ? kw : qw;
    float v = src[(i*64 + d)*2112 + 64 + c];
    __nv_bfloat16 h = __float2bfloat16(v);
    __nv_bfloat16 lo = __float2bfloat16(v - __bfloat162float(h));
    size_t base = (size_t)m * K6_ + c;
    g_Wp[base]          = h;
    g_Wp[base + CR_]    = h;
    g_Wp[base + 2*CR_]  = lo;
}

// ---------------- X transpose + bf16 hi/lo/hi augmented K ----------------
__global__ void __launch_bounds__(256) xt_kernel(const float* __restrict__ x) {
    __shared__ float ts[32][33];
    const int lb = blockIdx.x * 32, kb = blockIdx.y * 32, n = blockIdx.z;
    const int tx = threadIdx.x & 31, ty = threadIdx.x >> 5;     // 32 x 8
#pragma unroll
    for (int r = ty; r < 32; r += 8)
        ts[r][tx] = x[((size_t)n * CR_ + kb + r) * L_ + lb + tx];
    __syncthreads();
#pragma unroll
    for (int r = ty; r < 32; r += 8) {
        float v = ts[tx][r];
        __nv_bfloat16 h = __float2bfloat16(v);
        __nv_bfloat16 lo = __float2bfloat16(v - __bfloat162float(h));
        size_t base = (size_t)(n * L_ + lb + r) * K6_ + kb + tx;
        g_Xp[base]          = h;
        g_Xp[base + CR_]    = lo;
        g_Xp[base + 2*CR_]  = h;
    }
}

// ---------------- shared-mem 64x64 micro-matmul (16x16 threads, 4x4 per thread) ----
__device__ __forceinline__ void mm_16x16(const float (*Ws)[64], const float (*Xs)[64],
                                         float acc[4][4], int ty4, int tx4) {
#pragma unroll 16
    for (int c = 0; c < 64; ++c) {
        const float4 a = *(const float4*)(&Ws[c][ty4]);
        const float4 b = *(const float4*)(&Xs[c][tx4]);
        acc[0][0] += a.x*b.x; acc[0][1] += a.x*b.y; acc[0][2] += a.x*b.z; acc[0][3] += a.x*b.w;
        acc[1][0] += a.y*b.x; acc[1][1] += a.y*b.y; acc[1][2] += a.y*b.z; acc[1][3] += a.y*b.w;
        acc[2][0] += a.z*b.x; acc[2][1] += a.z*b.y; acc[2][2] += a.z*b.z; acc[2][3] += a.z*b.w;
        acc[3][0] += a.w*b.x; acc[3][1] += a.w*b.y; acc[3][2] += a.w*b.z; acc[3][3] += a.w*b.w;
    }
}

__global__ void pack_small_kernel(const float* __restrict__ convw, const float* __restrict__ qw,
                                  const float* __restrict__ kw,   const float* __restrict__ vw,
                                  const float* __restrict__ f1w,  const float* __restrict__ f2w) {
    int idx = blockIdx.x * 256 + threadIdx.x;       // grid covers NL_*5*4096
    if (idx < NL_*5*64*64) {
        int d = idx & 63, c = (idx >> 6) & 63, r = idx >> 12, j = r % 5, i = r / 5;
        g_convT[idx] = convw[((i*64 + d)*64 + c)*5 + j];
    }
    if (idx < NL_*64*64) {
        int d = idx & 63, c = (idx >> 6) & 63, i = idx >> 12;
        g_qT [idx] = qw [(i*64 + d)*2112 + c];
        g_kT [idx] = kw [(i*64 + d)*2112 + c];
        g_vT [idx] = vw [(i*64 + d)*64 + c];
        g_f1T[idx] = f1w[(i*64 + d)*64 + c];
        g_f2T[idx] = f2w[(i*64 + d)*64 + c];
    }
}

// ---------------- timestep embedding MLP ----------------
__global__ void temb_kernel(const int* __restrict__ t,
                            const float* __restrict__ w1, const float* __restrict__ b1,
                            const float* __restrict__ w2, const float* __restrict__ b2,
                            const float* __restrict__ wp, const float* __restrict__ bp) {
    __shared__ float se[TE_], st[TE_];
    const int n = blockIdx.x, tid = threadIdx.x;
    const float tv = (float)t[n];
    if (tid < 256) {
        float f = expf((float)tid * (-logf(10000.0f) / 255.0f));
        float a = tv * f;
        se[tid] = sinf(a);
        se[tid + 256] = cosf(a);
    }
    __syncthreads();
    {
        float s = b1[tid];
        const float* w = w1 + tid * TE_;
        for (int c = 0; c < TE_; ++c) s += se[c] * w[c];
        st[tid] = s / (1.f + expf(-s));            // swish
    }
    __syncthreads();
    {
        float s = b2[tid];
        const float* w = w2 + tid * TE_;
        for (int c = 0; c < TE_; ++c) s += st[c] * w[c];
        se[tid] = s / (1.f + expf(-s));            // swish(temb)
    }
    __syncthreads();
    if (tid < D_) {
        float s = bp[tid];
        const float* w = wp + tid * TE_;
        for (int c = 0; c < TE_; ++c) s += se[c] * w[c];
        g_tproj[n * D_ + tid] = s;
    }
}

// ---------------- conv_in (1x1, 48->64) + time projection add ----------------
__global__ void __launch_bounds__(256) conv_in_kernel(const float* __restrict__ event,
                                                      const float* __restrict__ w,
                                                      const float* __restrict__ b) {
    __shared__ float Et[NC_][64];
    __shared__ float Wt[NC_][64];
    const int n = blockIdx.y, l0 = blockIdx.x * 64;
    const int tid = threadIdx.x, ty4 = (tid >> 4) << 2, tx4 = (tid & 15) << 2;
    for (int e = tid; e < NC_*64; e += 256) {
        int c = e >> 6, tt = e & 63;
        Et[c][tt] = event[(n*NC_ + c)*L_ + l0 + tt];
        Wt[c][tt] = w[tt*NC_ + c];
    }
    __syncthreads();
    float acc[4][4] = {};
#pragma unroll
    for (int c = 0; c < NC_; ++c) {
        const float4 a = *(const float4*)(&Wt[c][ty4]);
        const float4 x4 = *(const float4*)(&Et[c][tx4]);
        acc[0][0]+=a.x*x4.x; acc[0][1]+=a.x*x4.y; acc[0][2]+=a.x*x4.z; acc[0][3]+=a.x*x4.w;
        acc[1][0]+=a.y*x4.x; acc[1][1]+=a.y*x4.y; acc[1][2]+=a.y*x4.z; acc[1][3]+=a.y*x4.w;
        acc[2][0]+=a.z*x4.x; acc[2][1]+=a.z*x4.y; acc[2][2]+=a.z*x4.z; acc[2][3]+=a.z*x4.w;
        acc[3][0]+=a.w*x4.x; acc[3][1]+=a.w*x4.y; acc[3][2]+=a.w*x4.z; acc[3][3]+=a.w*x4.w;
    }
#pragma unroll
    for (int i = 0; i < 4; ++i)
#pragma unroll
        for (int j = 0; j < 4; ++j) {
            int d = ty4 + i, l = l0 + tx4 + j;
            g_fra[(n*D_ + d)*L_ + l] = acc[i][j] + b[d] + g_tproj[n*D_ + d];
        }
}

// ---------------- per-layer: dilated conv (5 shifted matmuls) + q/k/v projections ---
__global__ void __launch_bounds__(256) layer_a_kernel(const float* __restrict__ convb,
                                                      const float* __restrict__ qb,
                                                      const float* __restrict__ kb,
                                                      const float* __restrict__ vb,
                                                      int layer, int dil) {
    __shared__ float Xs[64][64];
    __shared__ float Ws[64][64];
    const int n = blockIdx.y, l0 = blockIdx.x * 64;
    const int tid = threadIdx.x, ty4 = (tid >> 4) << 2, tx4 = (tid & 15) << 2;
    const float* fb = g_fra + (size_t)n * D_ * L_;

    float acc[4][4] = {};
    for (int j = 0; j < 5; ++j) {
        int shift = (j - 2) * dil;
        const float* wsrc = g_convT + (size_t)(layer*5 + j) * 4096;
        for (int e = tid; e < 4096; e += 256) {
            int c = e >> 6, tt = e & 63, p = l0 + tt + shift;
            Xs[c][tt] = ((unsigned)p < (unsigned)L_) ? fb[c*L_ + p] : 0.f;
            ((float*)Ws)[e] = wsrc[e];
        }
        __syncthreads();
        mm_16x16(Ws, Xs, acc, ty4, tx4);
        __syncthreads();
    }
#pragma unroll
    for (int i = 0; i < 4; ++i)
#pragma unroll
        for (int j = 0; j < 4; ++j) {
            int d = ty4 + i, l = l0 + tx4 + j;
            g_out1[(n*D_ + d)*L_ + l] = acc[i][j] + convb[layer*64 + d];
        }

    for (int e = tid; e < 4096; e += 256) {
        int c = e >> 6, tt = e & 63;
        Xs[c][tt] = fb[c*L_ + l0 + tt];
    }
    // q
    {
        const float* wsrc = g_qT + (size_t)layer * 4096;
        for (int e = tid; e < 4096; e += 256) ((float*)Ws)[e] = wsrc[e];
        __syncthreads();
        float a2[4][4] = {};
        mm_16x16(Ws, Xs, a2, ty4, tx4);
        __syncthreads();
#pragma unroll
        for (int i = 0; i < 4; ++i)
#pragma unroll
            for (int j = 0; j < 4; ++j) {
                int d = ty4 + i, l = l0 + tx4 + j;
                g_xq[(n*D_ + d)*L_ + l] = a2[i][j] + qb[layer*64 + d]
                    + g_QKC[(size_t)((layer*2)*64 + d)*NCOL_ + n*L_ + l];
            }
    }
    // k
    {
        const float* wsrc = g_kT + (size_t)layer * 4096;
        for (int e = tid; e < 4096; e += 256) ((float*)Ws)[e] = wsrc[e];
        __syncthreads();
        float a2[4][4] = {};
        mm_16x16(Ws, Xs, a2, ty4, tx4);
        __syncthreads();
#pragma unroll
        for (int i = 0; i < 4; ++i)
#pragma unroll
            for (int j = 0; j < 4; ++j) {
                int d = ty4 + i, l = l0 + tx4 + j;
                g_xk[(n*D_ + d)*L_ + l] = a2[i][j] + kb[layer*64 + d]
                    + g_QKC[(size_t)((layer*2 + 1)*64 + d)*NCOL_ + n*L_ + l];
            }
    }
    // v
    {
        const float* wsrc = g_vT + (size_t)layer * 4096;
        for (int e = tid; e < 4096; e += 256) ((float*)Ws)[e] = wsrc[e];
        __syncthreads();
        float a2[4][4] = {};
        mm_16x16(Ws, Xs, a2, ty4, tx4);
#pragma unroll
        for (int i = 0; i < 4; ++i)
#pragma unroll
            for (int j = 0; j < 4; ++j) {
                int d = ty4 + i, l = l0 + tx4 + j;
                g_xv[(n*D_ + d)*L_ + l] = a2[i][j] + vb[layer*64 + d];
            }
    }
}

// ---------------- attention scores (window K=5, softmax with padding mask) ----------
__global__ void attn_score_kernel(int dil) {
    const int n = blockIdx.y;
    const int l = blockIdx.x * 256 + threadIdx.x;
    const float* qb_ = g_xq + (size_t)n * D_ * L_ + l;
    const float* kb_ = g_xk + (size_t)n * D_ * L_;
    int p[5]; bool v[5];
#pragma unroll
    for (int j = 0; j < 5; ++j) { p[j] = l + (j - 2) * dil; v[j] = ((unsigned)p[j] < (unsigned)L_); }
    float dot[5] = {};
#pragma unroll 8
    for (int c = 0; c < 64; ++c) {
        float qv = qb_[c * L_];
#pragma unroll
        for (int j = 0; j < 5; ++j) if (v[j]) dot[j] += qv * kb_[c*L_ + p[j]];
    }
    const float LVALID = logf(1.0f + 1e-6f);
    const float LINV   = logf(1e-6f);
    float lg[5];
#pragma unroll
    for (int j = 0; j < 5; ++j) lg[j] = v[j] ? dot[j]*0.125f + LVALID : LINV;
    float mx = lg[0];
#pragma unroll
    for (int j = 1; j < 5; ++j) mx = fmaxf(mx, lg[j]);
    float e[5], s = 0.f;
#pragma unroll
    for (int j = 0; j < 5; ++j) { e[j] = expf(lg[j] - mx); s += e[j]; }
    float inv = 1.f / s;
#pragma unroll
    for (int j = 0; j < 5; ++j)
        g_att[(size_t)n*5*L_ + j*L_ + l] = v[j] ? e[j]*inv : 0.f;
}

// ---------------- apply attention, y = out1 + r, partial instance-norm stats --------
__global__ void attn_apply_kernel(int dil) {
    const int n = blockIdx.z, c = blockIdx.y;
    const int tid = threadIdx.x;
    const int l = blockIdx.x * 256 + tid;
    const float* vb_ = g_xv + (size_t)(n*D_ + c) * L_;
    const float* ab_ = g_att + (size_t)n * 5 * L_ + l;
    float r = 0.f;
#pragma unroll
    for (int j = 0; j < 5; ++j) {
        int pp = l + (j - 2) * dil;
        if ((unsigned)pp < (unsigned)L_) r += ab_[j * L_] * vb_[pp];
    }
    size_t o = (size_t)(n*D_ + c) * L_ + l;
    float yv = g_out1[o] + r;
    g_y[o] = yv;
    __shared__ float s1[256], s2[256];
    s1[tid] = yv; s2[tid] = yv * yv;
    __syncthreads();
    for (int st = 128; st > 0; st >>= 1) {
        if (tid < st) { s1[tid] += s1[tid + st]; s2[tid] += s2[tid + st]; }
        __syncthreads();
    }
    if (tid == 0) {
        g_part[((n*D_ + c)*32 + blockIdx.x)*2 + 0] = s1[0];
        g_part[((n*D_ + c)*32 + blockIdx.x)*2 + 1] = s2[0];
    }
}

__global__ void norm_stats_kernel() {
    int t = threadIdx.x;                       // 128 = B_*D_
    float s = 0.f, s2 = 0.f;
    for (int bq = 0; bq < 32; ++bq) {
        s  += g_part[(t*32 + bq)*2 + 0];
        s2 += g_part[(t*32 + bq)*2 + 1];
    }
    float mean = s / (float)L_;
    float var = s2 / (float)L_ - mean*mean;
    g_norm[t*2 + 0] = mean;
    g_norm[t*2 + 1] = rsqrtf(var + 1e-5f);
}

// ---------------- instance-norm + FFN + residual into fra ----------------
__global__ void __launch_bounds__(256) ffn_kernel(const float* __restrict__ f1b,
                                                  const float* __restrict__ f2b,
                                                  int layer) {
    __shared__ float Xs[64][64];
    __shared__ float Ws[64][64];
    const int n = blockIdx.y, l0 = blockIdx.x * 64;
    const int tid = threadIdx.x, ty4 = (tid >> 4) << 2, tx4 = (tid & 15) << 2;
    {
        const float* wsrc = g_f1T + (size_t)layer * 4096;
        for (int e = tid; e < 4096; e += 256) {
            int c = e >> 6, tt = e & 63;
            float mean = g_norm[(n*D_ + c)*2 + 0];
            float rstd = g_norm[(n*D_ + c)*2 + 1];
            Xs[c][tt] = (g_y[(size_t)(n*D_ + c)*L_ + l0 + tt] - mean) * rstd;
            ((float*)Ws)[e] = wsrc[e];
        }
    }
    __syncthreads();
    float acc[4][4] = {};
    mm_16x16(Ws, Xs, acc, ty4, tx4);
    __syncthreads();
#pragma unroll
    for (int i = 0; i < 4; ++i)
#pragma unroll
        for (int j = 0; j < 4; ++j)
            Xs[ty4 + i][tx4 + j] = fmaxf(acc[i][j] + f1b[layer*64 + ty4 + i], 0.f);
    {
        const float* wsrc = g_f2T + (size_t)layer * 4096;
        for (int e = tid; e < 4096; e += 256) ((float*)Ws)[e] = wsrc[e];
    }
    __syncthreads();
    float a2[4][4] = {};
    mm_16x16(Ws, Xs, a2, ty4, tx4);
#pragma unroll
    for (int i = 0; i < 4; ++i)
#pragma unroll
        for (int j = 0; j < 4; ++j) {
            int d = ty4 + i, l = l0 + tx4 + j;
            size_t o = (size_t)(n*D_ + d)*L_ + l;
            g_fra[o] += a2[i][j] + f2b[layer*64 + d];
        }
}

// ---------------- conv_out (1x1, 64->48) ----------------
__global__ void __launch_bounds__(256) conv_out_kernel(const float* __restrict__ w,
                                                       const float* __restrict__ b,
                                                       float* __restrict__ out) {
    __shared__ float Xs[64][64];
    __shared__ float Wt[64][NC_];
    const int n = blockIdx.y, l0 = blockIdx.x * 64;
    const int tid = threadIdx.x, ty = tid >> 4, tx = tid & 15;
    for (int e = tid; e < 4096; e += 256) {
        int c = e >> 6, tt = e & 63;
        Xs[c][tt] = g_fra[(size_t)(n*D_ + c)*L_ + l0 + tt];
    }
    for (int e = tid; e < 64*NC_; e += 256) {
        int c = e / NC_, o = e % NC_;
        Wt[c][o] = w[o*64 + c];
    }
    __syncthreads();
    if (ty < 12) {
        const int ty4 = ty*4, tx4 = tx*4;
        float acc[4][4] = {};
#pragma unroll 16
        for (int c = 0; c < 64; ++c) {
            const float4 a = *(const float4*)(&Wt[c][ty4]);
            const float4 x4 = *(const float4*)(&Xs[c][tx4]);
            acc[0][0]+=a.x*x4.x; acc[0][1]+=a.x*x4.y; acc[0][2]+=a.x*x4.z; acc[0][3]+=a.x*x4.w;
            acc[1][0]+=a.y*x4.x; acc[1][1]+=a.y*x4.y; acc[1][2]+=a.y*x4.z; acc[1][3]+=a.y*x4.w;
            acc[2][0]+=a.z*x4.x; acc[2][1]+=a.z*x4.y; acc[2][2]+=a.z*x4.z; acc[2][3]+=a.z*x4.w;
            acc[3][0]+=a.w*x4.x; acc[3][1]+=a.w*x4.y; acc[3][2]+=a.w*x4.z; acc[3][3]+=a.w*x4.w;
        }
#pragma unroll
        for (int i = 0; i < 4; ++i)
#pragma unroll
            for (int j = 0; j < 4; ++j) {
                int o = ty4 + i, l = l0 + tx4 + j;
                out[(size_t)(n*NC_ + o)*L_ + l] = acc[i][j] + b[o];
            }
    }
}

// ---------------- host side ----------------
extern "C" void kernel_launch(void* const* d_in, const int* in_sizes, int n_in,
                              void* d_out, int out_size) {
    (void)in_sizes; (void)n_in; (void)out_size;
    const float* x     = (const float*)d_in[0];
    const int*   t     = (const int*)  d_in[1];
    const float* event = (const float*)d_in[2];
    const float* tw1   = (const float*)d_in[3];
    const float* tb1   = (const float*)d_in[4];
    const float* tw2   = (const float*)d_in[5];
    const float* tb2   = (const float*)d_in[6];
    const float* tpw   = (const float*)d_in[7];
    const float* tpb   = (const float*)d_in[8];
    const float* ciw   = (const float*)d_in[9];
    const float* cib   = (const float*)d_in[10];
    const float* cow   = (const float*)d_in[11];
    const float* cob   = (const float*)d_in[12];
    const float* lcw   = (const float*)d_in[13];
    const float* lcb   = (const float*)d_in[14];
    const float* qw    = (const float*)d_in[15];
    const float* qb    = (const float*)d_in[16];
    const float* kw    = (const float*)d_in[17];
    const float* kb    = (const float*)d_in[18];
    const float* vw    = (const float*)d_in[19];
    const float* vb    = (const float*)d_in[20];
    const float* f1w   = (const float*)d_in[21];
    const float* f1b   = (const float*)d_in[22];
    const float* f2w   = (const float*)d_in[23];
    const float* f2b   = (const float*)d_in[24];

    pack_wp_kernel<<<(M_*CR_)/256, 256>>>(qw, kw);
    pack_small_kernel<<<(NL_*5*64*64)/256, 256>>>(lcw, qw, kw, vw, f1w, f2w);
    xt_kernel<<<dim3(L_/32, CR_/32, B_), 256>>>(x);
    temb_kernel<<<B_, TE_>>>(t, tw1, tb1, tw2, tb2, tpw, tpb);
    conv_in_kernel<<<dim3(L_/64, B_), 256>>>(event, ciw, cib);
    gemm_bf16_kernel<<<dim3(M_/GM_BM, NCOL_/GM_BN), 256>>>();

    for (int i = 0; i < NL_; ++i) {
        int dil = 1 << i;
        layer_a_kernel<<<dim3(L_/64, B_), 256>>>(lcb, qb, kb, vb, i, dil);
        attn_score_kernel<<<dim3(L_/256, B_), 256>>>(dil);
        attn_apply_kernel<<<dim3(L_/256, D_, B_), 256>>>(dil);
        norm_stats_kernel<<<1, 128>>>();
        ffn_kernel<<<dim3(L_/64, B_), 256>>>(f1b, f2b, i);
    }
    conv_out_kernel<<<dim3(L_/64, B_), 256>>>(cow, cob, (float*)d_out);
}

// round 4
// speedup vs baseline: 2.3783x; 1.3582x over previous
#include <cuda_runtime.h>
#include <cuda_bf16.h>
#include <cuda_fp16.h>
#include <math.h>
#include <stdint.h>

#define B_  2
#define L_  8192
#define D_  64
#define CR_ 2048
#define NC_ 48
#define TE_ 512
#define NL_ 8
#define M_  1024        // NL*2*D rows of the batched cross GEMM
#define NCOL_ (B_*L_)   // 16384 columns
#define K6_ (3*CR_)     // 6144 augmented K (hi/hi/lo packing)

// ---------------- scratch (device globals; no allocation allowed) ----------------
__device__ __nv_bfloat16 g_Wp[(size_t)M_*K6_];        // A' = [Whi | Whi | Wlo], K-major
__device__ __nv_bfloat16 g_Xp[(size_t)NCOL_*K6_];     // B' = [Xhi ; Xlo ; Xhi], K-major per col
__device__ float g_QKC [(size_t)M_*NCOL_];            // cross-projection results [m][n*L+l]
__device__ __half g_AW[NL_*8*2*64*64];   // layer weights [i][slot][hi/lo][m][k]; slots: taps{0,1,3,4,2},q,k,v
__device__ __half g_fh[B_*D_*L_];        // fra fp16 hi
__device__ __half g_fl[B_*D_*L_];        // fra fp16 lo
__device__ float g_f1T [NL_*64*64];
__device__ float g_f2T [NL_*64*64];
__device__ float g_fra [B_*D_*L_];
__device__ float g_xq  [B_*D_*L_];
__device__ float g_xk  [B_*D_*L_];
__device__ float g_xv  [B_*D_*L_];
__device__ float g_out1[B_*D_*L_];
__device__ float g_y   [B_*D_*L_];
__device__ float g_att [B_*5*L_];
__device__ float g_part[B_*D_*32*2];
__device__ float g_tproj[B_*D_];
__device__ float g_t1[B_*TE_];
__device__ float g_t2[B_*TE_];

__device__ __forceinline__ uint32_t smem_u32(const void* p) {
    return (uint32_t)__cvta_generic_to_shared(p);
}
__device__ __forceinline__ void ldsm_x4(uint32_t* r, uint32_t addr) {
    asm volatile("ldmatrix.sync.aligned.m8n8.x4.shared.b16 {%0,%1,%2,%3}, [%4];"
                 : "=r"(r[0]), "=r"(r[1]), "=r"(r[2]), "=r"(r[3]) : "r"(addr));
}
__device__ __forceinline__ void ldsm_x4t(uint32_t* r, uint32_t addr) {
    asm volatile("ldmatrix.sync.aligned.m8n8.x4.trans.shared.b16 {%0,%1,%2,%3}, [%4];"
                 : "=r"(r[0]), "=r"(r[1]), "=r"(r[2]), "=r"(r[3]) : "r"(addr));
}
__device__ __forceinline__ void mma_bf16(float c[4], uint32_t a0, uint32_t a1, uint32_t a2,
                                         uint32_t a3, uint32_t b0, uint32_t b1) {
    asm volatile("mma.sync.aligned.m16n8k16.row.col.f32.bf16.bf16.f32 "
                 "{%0,%1,%2,%3}, {%4,%5,%6,%7}, {%8,%9}, {%0,%1,%2,%3};"
                 : "+f"(c[0]), "+f"(c[1]), "+f"(c[2]), "+f"(c[3])
                 : "r"(a0), "r"(a1), "r"(a2), "r"(a3), "r"(b0), "r"(b1));
}
__device__ __forceinline__ void mma_fp16(float c[4], uint32_t a0, uint32_t a1, uint32_t a2,
                                         uint32_t a3, uint32_t b0, uint32_t b1) {
    asm volatile("mma.sync.aligned.m16n8k16.row.col.f32.f16.f16.f32 "
                 "{%0,%1,%2,%3}, {%4,%5,%6,%7}, {%8,%9}, {%0,%1,%2,%3};"
                 : "+f"(c[0]), "+f"(c[1]), "+f"(c[2]), "+f"(c[3])
                 : "r"(a0), "r"(a1), "r"(a2), "r"(a3), "r"(b0), "r"(b1));
}
__device__ __forceinline__ void cp16(uint32_t saddr, const void* gptr) {
    asm volatile("cp.async.cg.shared.global [%0], [%1], 16;" :: "r"(saddr), "l"(gptr));
}
#define CP_COMMIT() asm volatile("cp.async.commit_group;")
#define CP_WAIT1() asm volatile("cp.async.wait_group 1;")
#define CP_WAIT0() asm volatile("cp.async.wait_group 0;")

// ================== bf16 HMMA cross GEMM (unchanged structure) ==================
#define GM_BM 128
#define GM_BN 128
#define GM_BK 32
#define GM_NT (K6_/GM_BK)
#define APAD 40

__global__ void __launch_bounds__(256) gemm_bf16_kernel() {
    __shared__ __nv_bfloat16 As[2][GM_BM * APAD];
    __shared__ __nv_bfloat16 Bs[2][GM_BN * APAD];
    const int tid = threadIdx.x, lane = tid & 31, wid = tid >> 5;
    const int wm = wid >> 2, wn = wid & 3;
    const int m0 = blockIdx.x * GM_BM;
    const int col0 = blockIdx.y * GM_BN;
    const int ldr = tid >> 1, ldc = (tid & 1) * 2;

    float acc[4][4][4];
#pragma unroll
    for (int i = 0; i < 4; ++i)
#pragma unroll
        for (int j = 0; j < 4; ++j)
#pragma unroll
            for (int q = 0; q < 4; ++q) acc[i][j][q] = 0.f;

    const int lrow = lane & 15, lhalf = lane >> 4;

    auto load_tile = [&](int kt, int buf) {
        const size_t gk = (size_t)kt * GM_BK;
#pragma unroll
        for (int s = 0; s < 2; ++s) {
            int c = ldc + s;
            cp16(smem_u32(&As[buf][ldr * APAD + c * 8]),
                 g_Wp + (size_t)(m0 + ldr) * K6_ + gk + c * 8);
            cp16(smem_u32(&Bs[buf][ldr * APAD + c * 8]),
                 g_Xp + (size_t)(col0 + ldr) * K6_ + gk + c * 8);
        }
        CP_COMMIT();
    };

    load_tile(0, 0);
    for (int kt = 0; kt < GM_NT; ++kt) {
        const int cur = kt & 1;
        if (kt + 1 < GM_NT) { load_tile(kt + 1, cur ^ 1); CP_WAIT1(); }
        else CP_WAIT0();
        __syncthreads();
#pragma unroll
        for (int kk2 = 0; kk2 < 2; ++kk2) {
            uint32_t a[4][4];
#pragma unroll
            for (int mt = 0; mt < 4; ++mt)
                ldsm_x4(a[mt], smem_u32(&As[cur][(wm*64 + mt*16 + lrow) * APAD + kk2*16 + lhalf*8]));
            uint32_t b[4][2];
#pragma unroll
            for (int nb2 = 0; nb2 < 2; ++nb2) {
                uint32_t r[4];
                ldsm_x4(r, smem_u32(&Bs[cur][(wn*32 + nb2*16 + lrow) * APAD + kk2*16 + lhalf*8]));
                b[nb2*2 + 0][0] = r[0]; b[nb2*2 + 0][1] = r[2];
                b[nb2*2 + 1][0] = r[1]; b[nb2*2 + 1][1] = r[3];
            }
#pragma unroll
            for (int mt = 0; mt < 4; ++mt)
#pragma unroll
                for (int nt = 0; nt < 4; ++nt)
                    mma_bf16(acc[mt][nt], a[mt][0], a[mt][1], a[mt][2], a[mt][3],
                             b[nt][0], b[nt][1]);
        }
        __syncthreads();
    }
    const int grp = lane >> 2, qd = (lane & 3) * 2;
#pragma unroll
    for (int mt = 0; mt < 4; ++mt)
#pragma unroll
        for (int nt = 0; nt < 4; ++nt) {
            int m = m0 + wm*64 + mt*16 + grp;
            int n = col0 + wn*32 + nt*8 + qd;
            *(float2*)(g_QKC + (size_t)m * NCOL_ + n)       = make_float2(acc[mt][nt][0], acc[mt][nt][1]);
            *(float2*)(g_QKC + (size_t)(m + 8) * NCOL_ + n) = make_float2(acc[mt][nt][2], acc[mt][nt][3]);
        }
}

// ---------------- packing kernels ----------------
__global__ void pack_wp_kernel(const float* __restrict__ qw, const float* __restrict__ kw) {
    int idx = blockIdx.x * 256 + threadIdx.x;
    int m = idx >> 11, c = idx & 2047;
    int i = m >> 7, r = m & 127, s = r >> 6, d = r & 63;
    const float* src = s ? kw : qw;
    float v = src[(i*64 + d)*2112 + 64 + c];
    __nv_bfloat16 h = __float2bfloat16(v);
    __nv_bfloat16 lo = __float2bfloat16(v - __bfloat162float(h));
    size_t base = (size_t)m * K6_ + c;
    g_Wp[base] = h; g_Wp[base + CR_] = h; g_Wp[base + 2*CR_] = lo;
}

__global__ void __launch_bounds__(256) xt_kernel(const float* __restrict__ x) {
    __shared__ float ts[32][33];
    const int lb = blockIdx.x * 32, kb = blockIdx.y * 32, n = blockIdx.z;
    const int tx = threadIdx.x & 31, ty = threadIdx.x >> 5;
#pragma unroll
    for (int r = ty; r < 32; r += 8)
        ts[r][tx] = x[((size_t)n * CR_ + kb + r) * L_ + lb + tx];
    __syncthreads();
#pragma unroll
    for (int r = ty; r < 32; r += 8) {
        float v = ts[tx][r];
        __nv_bfloat16 h = __float2bfloat16(v);
        __nv_bfloat16 lo = __float2bfloat16(v - __bfloat162float(h));
        size_t base = (size_t)(n * L_ + lb + r) * K6_ + kb + tx;
        g_Xp[base] = h; g_Xp[base + CR_] = lo; g_Xp[base + 2*CR_] = h;
    }
}

// pack per-layer weights into fp16 hi/lo A-layout [m][k]
__global__ void pack_aw_kernel(const float* __restrict__ convw, const float* __restrict__ qw,
                               const float* __restrict__ kw,   const float* __restrict__ vw,
                               const float* __restrict__ f1w,  const float* __restrict__ f2w) {
    int idx = blockIdx.x * 256 + threadIdx.x;     // NL_*8*4096
    if (idx < NL_*8*64*64) {
        int c = idx & 63, m = (idx >> 6) & 63, s = (idx >> 12) & 7, i = idx >> 15;
        const int tapmap[5] = {0, 1, 3, 4, 2};
        float v;
        if (s < 5)      v = convw[((i*64 + m)*64 + c)*5 + tapmap[s]];
        else if (s == 5) v = qw[(i*64 + m)*2112 + c];
        else if (s == 6) v = kw[(i*64 + m)*2112 + c];
        else             v = vw[(i*64 + m)*64 + c];
        __half h = __float2half(v);
        __half lo = __float2half(v - __half2float(h));
        size_t base = ((size_t)(i*8 + s)*2) * 4096 + m*64 + c;
        g_AW[base] = h;
        g_AW[base + 4096] = lo;
    }
    if (idx < NL_*64*64) {
        int d = idx & 63, c = (idx >> 6) & 63, i = idx >> 12;
        g_f1T[idx] = f1w[(i*64 + d)*64 + c];
        g_f2T[idx] = f2w[(i*64 + d)*64 + c];
    }
}

// ---------------- timestep embedding (coalesced, 3 stages) ----------------
__global__ void temb1_kernel(const int* __restrict__ t, const float* __restrict__ w1,
                             const float* __restrict__ b1) {
    __shared__ float se[TE_];
    const int n = blockIdx.y, tid = threadIdx.x;
    const float tv = (float)t[n];
    if (tid < 256) {
        float f = expf((float)tid * (-logf(10000.0f) / 255.0f));
        se[tid] = sinf(tv * f);
        se[tid + 256] = cosf(tv * f);
    }
    __syncthreads();
    const int w = tid >> 5, lane = tid & 31;
    const int o = blockIdx.x * 8 + w;
    const float* wr = w1 + (size_t)o * TE_;
    float s = 0.f;
    for (int c = lane; c < TE_; c += 32) s += se[c] * wr[c];
#pragma unroll
    for (int off = 16; off; off >>= 1) s += __shfl_xor_sync(0xffffffffu, s, off);
    if (!lane) { s += b1[o]; g_t1[n*TE_ + o] = s / (1.f + expf(-s)); }
}
__global__ void temb2_kernel(const float* __restrict__ w2, const float* __restrict__ b2) {
    __shared__ float se[TE_];
    const int n = blockIdx.y, tid = threadIdx.x;
    se[tid] = g_t1[n*TE_ + tid];
    se[tid + 256] = g_t1[n*TE_ + tid + 256];
    __syncthreads();
    const int w = tid >> 5, lane = tid & 31;
    const int o = blockIdx.x * 8 + w;
    const float* wr = w2 + (size_t)o * TE_;
    float s = 0.f;
    for (int c = lane; c < TE_; c += 32) s += se[c] * wr[c];
#pragma unroll
    for (int off = 16; off; off >>= 1) s += __shfl_xor_sync(0xffffffffu, s, off);
    if (!lane) g_t2[n*TE_ + o] = s + b2[o];
}
__global__ void tembp_kernel(const float* __restrict__ wp, const float* __restrict__ bp) {
    __shared__ float se[TE_];
    const int n = blockIdx.y, tid = threadIdx.x;
    {
        float v0 = g_t2[n*TE_ + tid], v1 = g_t2[n*TE_ + tid + 256];
        se[tid]       = v0 / (1.f + expf(-v0));
        se[tid + 256] = v1 / (1.f + expf(-v1));
    }
    __syncthreads();
    const int w = tid >> 5, lane = tid & 31;
    const int o = blockIdx.x * 8 + w;
    const float* wr = wp + (size_t)o * TE_;
    float s = 0.f;
    for (int c = lane; c < TE_; c += 32) s += se[c] * wr[c];
#pragma unroll
    for (int off = 16; off; off >>= 1) s += __shfl_xor_sync(0xffffffffu, s, off);
    if (!lane) g_tproj[n*D_ + o] = s + bp[o];
}

// ---------------- conv_in (1x1, 48->64) + time proj; writes fp32 + fp16 hi/lo ------
__global__ void __launch_bounds__(256) conv_in_kernel(const float* __restrict__ event,
                                                      const float* __restrict__ w,
                                                      const float* __restrict__ b) {
    __shared__ float Et[NC_][64];
    __shared__ float Wt[NC_][64];
    const int n = blockIdx.y, l0 = blockIdx.x * 64;
    const int tid = threadIdx.x, ty4 = (tid >> 4) << 2, tx4 = (tid & 15) << 2;
    for (int e = tid; e < NC_*64; e += 256) {
        int c = e >> 6, tt = e & 63;
        Et[c][tt] = event[(n*NC_ + c)*L_ + l0 + tt];
        Wt[c][tt] = w[tt*NC_ + c];
    }
    __syncthreads();
    float acc[4][4] = {};
#pragma unroll
    for (int c = 0; c < NC_; ++c) {
        const float4 a = *(const float4*)(&Wt[c][ty4]);
        const float4 x4 = *(const float4*)(&Et[c][tx4]);
        acc[0][0]+=a.x*x4.x; acc[0][1]+=a.x*x4.y; acc[0][2]+=a.x*x4.z; acc[0][3]+=a.x*x4.w;
        acc[1][0]+=a.y*x4.x; acc[1][1]+=a.y*x4.y; acc[1][2]+=a.y*x4.z; acc[1][3]+=a.y*x4.w;
        acc[2][0]+=a.z*x4.x; acc[2][1]+=a.z*x4.y; acc[2][2]+=a.z*x4.z; acc[2][3]+=a.z*x4.w;
        acc[3][0]+=a.w*x4.x; acc[3][1]+=a.w*x4.y; acc[3][2]+=a.w*x4.z; acc[3][3]+=a.w*x4.w;
    }
#pragma unroll
    for (int i = 0; i < 4; ++i)
#pragma unroll
        for (int j = 0; j < 4; ++j) {
            int d = ty4 + i, l = l0 + tx4 + j;
            size_t o = (size_t)(n*D_ + d)*L_ + l;
            float v = acc[i][j] + b[d] + g_tproj[n*D_ + d];
            g_fra[o] = v;
            __half h = __float2half(v);
            g_fh[o] = h;
            g_fl[o] = __float2half(v - __half2float(h));
        }
}

// ================== per-layer HMMA: conv(5 taps) + q/k/v ==================
// block: 256 threads (8 warps, 2m x 4n), tile M=64 x N=128 l-positions
// smem: A weights 2 bufs x (hi+lo 8KB each)=32KB ; B acts 2 bufs x (hi+lo 16KB)=64KB
#define LA_SMEM (32768 + 65536)

__device__ __forceinline__ void mm64(float acc[2][4][4], uint32_t Ah, uint32_t Al,
                                     uint32_t Bh, uint32_t Bl, int wm, int wn, int lane) {
    const int lrow = lane & 15, lhalf = lane >> 4;
    const int bk = (lane & 7) + (((lane >> 3) & 1) << 3);
    const int bn8 = (lane >> 4) << 3;
#pragma unroll
    for (int pass = 0; pass < 3; ++pass) {
        uint32_t Ab = (pass == 2) ? Al : Ah;
        uint32_t Bb = (pass == 1) ? Bl : Bh;
#pragma unroll
        for (int k0 = 0; k0 < 4; ++k0) {
            uint32_t a[2][4];
#pragma unroll
            for (int mt = 0; mt < 2; ++mt) {
                int m = wm*32 + mt*16 + lrow;
                int ch = (k0*2 + lhalf) ^ (m & 7);
                ldsm_x4(a[mt], Ab + m*128 + ch*16);
            }
            uint32_t b[4][2];
#pragma unroll
            for (int ng = 0; ng < 2; ++ng) {
                int k = k0*16 + bk;
                int n = wn*32 + ng*16 + bn8;
                int ch = (n >> 3) ^ (k & 7);
                uint32_t r[4];
                ldsm_x4t(r, Bb + k*256 + ch*16);
                b[ng*2 + 0][0] = r[0]; b[ng*2 + 0][1] = r[1];
                b[ng*2 + 1][0] = r[2]; b[ng*2 + 1][1] = r[3];
            }
#pragma unroll
            for (int mt = 0; mt < 2; ++mt)
#pragma unroll
                for (int nt = 0; nt < 4; ++nt)
                    mma_fp16(acc[mt][nt], a[mt][0], a[mt][1], a[mt][2], a[mt][3],
                             b[nt][0], b[nt][1]);
        }
    }
}

__global__ void __launch_bounds__(256) layer_mm_kernel(const float* __restrict__ convb,
                                                       const float* __restrict__ qb,
                                                       const float* __restrict__ kb,
                                                       const float* __restrict__ vb,
                                                       int layer, int dil) {
    extern __shared__ char dsm[];
    char* smA = dsm;            // 2 x 16KB (hi 8KB + lo 8KB)
    char* smB = dsm + 32768;    // 2 x 32KB (hi 16KB + lo 16KB)
    const int tid = threadIdx.x, lane = tid & 31, wid = tid >> 5;
    const int wm = wid >> 2, wn = wid & 3;
    const int l0 = blockIdx.x * 128, nb = blockIdx.y;
    const __half* fh = g_fh + (size_t)nb * D_ * L_;
    const __half* fl = g_fl + (size_t)nb * D_ * L_;

    auto loadA = [&](int slot, int buf) {
        const __half* src = g_AW + ((size_t)(layer*8 + slot)*2) * 4096;
        char* dh = smA + buf * 16384;
        char* dl = dh + 8192;
#pragma unroll
        for (int e = tid; e < 512; e += 256) {
            int m = e >> 3, c = e & 7;
            int off = m*128 + ((c ^ (m & 7)) << 4);
            cp16(smem_u32(dh + off), src + m*64 + c*8);
            cp16(smem_u32(dl + off), src + 4096 + m*64 + c*8);
        }
    };
    auto loadB = [&](int shift, int buf) {
        char* dh = smB + buf * 32768;
        char* dl = dh + 16384;
        const bool aligned = ((shift & 7) == 0);
#pragma unroll
        for (int e = tid; e < 1024; e += 256) {
            int k = e >> 4, c = e & 15;
            int gl = l0 + c*8 + shift;
            int off = k*256 + ((c ^ (k & 7)) << 4);
            if (aligned && gl >= 0 && gl + 8 <= L_) {
                cp16(smem_u32(dh + off), fh + (size_t)k * L_ + gl);
                cp16(smem_u32(dl + off), fl + (size_t)k * L_ + gl);
            } else {
                __half* ph = (__half*)(dh + off);
                __half* pl = (__half*)(dl + off);
#pragma unroll
                for (int u = 0; u < 8; ++u) {
                    int l = gl + u;
                    bool ok = ((unsigned)l < (unsigned)L_);
                    ph[u] = ok ? fh[(size_t)k * L_ + l] : __half(0.f);
                    pl[u] = ok ? fl[(size_t)k * L_ + l] : __half(0.f);
                }
            }
        }
    };

    const int tapshift[5] = {-2*dil, -dil, dil, 2*dil, 0};   // order: taps 0,1,3,4,2

    float acc[2][4][4];
#pragma unroll
    for (int i = 0; i < 2; ++i)
#pragma unroll
        for (int j = 0; j < 4; ++j)
#pragma unroll
            for (int q = 0; q < 4; ++q) acc[i][j][q] = 0.f;

    loadB(tapshift[0], 0);
    loadA(0, 0);
    CP_COMMIT();

    const int grp = lane >> 2, qd = (lane & 3) * 2;
    auto epilogue = [&](float* dst, const float* bias, const float* qkc) {
#pragma unroll
        for (int mt = 0; mt < 2; ++mt)
#pragma unroll
            for (int nt = 0; nt < 4; ++nt) {
                int m = wm*32 + mt*16 + grp;
                int n = wn*32 + nt*8 + qd;
                float v0 = acc[mt][nt][0] + bias[m];
                float v1 = acc[mt][nt][1] + bias[m];
                float v2 = acc[mt][nt][2] + bias[m + 8];
                float v3 = acc[mt][nt][3] + bias[m + 8];
                if (qkc) {
                    float2 e0 = *(const float2*)(qkc + (size_t)m * NCOL_ + n);
                    float2 e1 = *(const float2*)(qkc + (size_t)(m + 8) * NCOL_ + n);
                    v0 += e0.x; v1 += e0.y; v2 += e1.x; v3 += e1.y;
                }
                *(float2*)(dst + (size_t)(nb*D_ + m) * L_ + l0 + n)     = make_float2(v0, v1);
                *(float2*)(dst + (size_t)(nb*D_ + m + 8) * L_ + l0 + n) = make_float2(v2, v3);
                acc[mt][nt][0] = acc[mt][nt][1] = acc[mt][nt][2] = acc[mt][nt][3] = 0.f;
            }
    };

    for (int it = 0; it < 8; ++it) {
        __syncthreads();                       // prior compute done; safe to overwrite alt bufs
        if (it < 7) {
            if (it < 4) loadB(tapshift[it + 1], (it + 1) & 1);
            loadA(it + 1, (it + 1) & 1);
            CP_COMMIT();
            CP_WAIT1();
        } else {
            CP_WAIT0();
        }
        __syncthreads();
        const int abuf = it & 1;
        const int bbuf = (it < 5) ? (it & 1) : 0;
        uint32_t Ah = smem_u32(smA + abuf * 16384);
        uint32_t Al = Ah + 8192;
        uint32_t Bh = smem_u32(smB + bbuf * 32768);
        uint32_t Bl = Bh + 16384;
        mm64(acc, Ah, Al, Bh, Bl, wm, wn, lane);
        if (it == 4) {
            epilogue(g_out1, convb + layer*64, nullptr);
        } else if (it == 5) {
            epilogue(g_xq, qb + layer*64, g_QKC + (size_t)(layer*2)*64*NCOL_ + nb*L_ + l0);
        } else if (it == 6) {
            epilogue(g_xk, kb + layer*64, g_QKC + (size_t)(layer*2 + 1)*64*NCOL_ + nb*L_ + l0);
        } else if (it == 7) {
            epilogue(g_xv, vb + layer*64, nullptr);
        }
    }
}

// ---------------- attention scores ----------------
__global__ void attn_score_kernel(int dil) {
    const int n = blockIdx.y;
    const int l = blockIdx.x * 256 + threadIdx.x;
    const float* qb_ = g_xq + (size_t)n * D_ * L_ + l;
    const float* kb_ = g_xk + (size_t)n * D_ * L_;
    int p[5]; bool v[5]; int pc[5];
#pragma unroll
    for (int j = 0; j < 5; ++j) {
        p[j] = l + (j - 2) * dil;
        v[j] = ((unsigned)p[j] < (unsigned)L_);
        pc[j] = v[j] ? p[j] : l;
    }
    float dot[5] = {};
#pragma unroll 8
    for (int c = 0; c < 64; ++c) {
        float qv = qb_[c * L_];
#pragma unroll
        for (int j = 0; j < 5; ++j) dot[j] += qv * kb_[c*L_ + pc[j]];
    }
    const float LVALID = logf(1.0f + 1e-6f);
    const float LINV   = logf(1e-6f);
    float lg[5];
#pragma unroll
    for (int j = 0; j < 5; ++j) lg[j] = v[j] ? dot[j]*0.125f + LVALID : LINV;
    float mx = lg[0];
#pragma unroll
    for (int j = 1; j < 5; ++j) mx = fmaxf(mx, lg[j]);
    float e[5], s = 0.f;
#pragma unroll
    for (int j = 0; j < 5; ++j) { e[j] = expf(lg[j] - mx); s += e[j]; }
    float inv = 1.f / s;
#pragma unroll
    for (int j = 0; j < 5; ++j)
        g_att[(size_t)n*5*L_ + j*L_ + l] = v[j] ? e[j]*inv : 0.f;
}

// ---------------- apply attention, y = out1 + r, partial IN stats ----------------
__global__ void attn_apply_kernel(int dil) {
    const int n = blockIdx.z, c = blockIdx.y;
    const int tid = threadIdx.x;
    const int l = blockIdx.x * 256 + tid;
    const float* vb_ = g_xv + (size_t)(n*D_ + c) * L_;
    const float* ab_ = g_att + (size_t)n * 5 * L_ + l;
    float r = 0.f;
#pragma unroll
    for (int j = 0; j < 5; ++j) {
        int pp = l + (j - 2) * dil;
        if ((unsigned)pp < (unsigned)L_) r += ab_[j * L_] * vb_[pp];
    }
    size_t o = (size_t)(n*D_ + c) * L_ + l;
    float yv = g_out1[o] + r;
    g_y[o] = yv;
    __shared__ float s1[256], s2[256];
    s1[tid] = yv; s2[tid] = yv * yv;
    __syncthreads();
    for (int st = 128; st > 0; st >>= 1) {
        if (tid < st) { s1[tid] += s1[tid + st]; s2[tid] += s2[tid + st]; }
        __syncthreads();
    }
    if (tid == 0) {
        g_part[((n*D_ + c)*32 + blockIdx.x)*2 + 0] = s1[0];
        g_part[((n*D_ + c)*32 + blockIdx.x)*2 + 1] = s2[0];
    }
}

// ---------------- shared-mem 64x64 micro-matmul (SIMT, for FFN) ----------------
__device__ __forceinline__ void mm_16x16(const float (*Ws)[64], const float (*Xs)[64],
                                         float acc[4][4], int ty4, int tx4) {
#pragma unroll 16
    for (int c = 0; c < 64; ++c) {
        const float4 a = *(const float4*)(&Ws[c][ty4]);
        const float4 b = *(const float4*)(&Xs[c][tx4]);
        acc[0][0] += a.x*b.x; acc[0][1] += a.x*b.y; acc[0][2] += a.x*b.z; acc[0][3] += a.x*b.w;
        acc[1][0] += a.y*b.x; acc[1][1] += a.y*b.y; acc[1][2] += a.y*b.z; acc[1][3] += a.y*b.w;
        acc[2][0] += a.z*b.x; acc[2][1] += a.z*b.y; acc[2][2] += a.z*b.z; acc[2][3] += a.z*b.w;
        acc[3][0] += a.w*b.x; acc[3][1] += a.w*b.y; acc[3][2] += a.w*b.z; acc[3][3] += a.w*b.w;
    }
}

// ---------------- instance-norm stats + FFN + residual; writes fp32 + fp16 ---------
__global__ void __launch_bounds__(256) ffn_kernel(const float* __restrict__ f1b,
                                                  const float* __restrict__ f2b,
                                                  int layer) {
    __shared__ float Xs[64][64];
    __shared__ float Ws[64][64];
    __shared__ float sms[64], srs[64];
    const int n = blockIdx.y, l0 = blockIdx.x * 64;
    const int tid = threadIdx.x, ty4 = (tid >> 4) << 2, tx4 = (tid & 15) << 2;
    if (tid < 64) {
        float s = 0.f, s2 = 0.f;
#pragma unroll
        for (int bq = 0; bq < 32; ++bq) {
            s  += g_part[((n*D_ + tid)*32 + bq)*2 + 0];
            s2 += g_part[((n*D_ + tid)*32 + bq)*2 + 1];
        }
        float mean = s / (float)L_;
        float var = s2 / (float)L_ - mean*mean;
        sms[tid] = mean;
        srs[tid] = rsqrtf(var + 1e-5f);
    }
    __syncthreads();
    {
        const float* wsrc = g_f1T + (size_t)layer * 4096;
        for (int e = tid; e < 4096; e += 256) {
            int c = e >> 6, tt = e & 63;
            Xs[c][tt] = (g_y[(size_t)(n*D_ + c)*L_ + l0 + tt] - sms[c]) * srs[c];
            ((float*)Ws)[e] = wsrc[e];
        }
    }
    __syncthreads();
    float acc[4][4] = {};
    mm_16x16(Ws, Xs, acc, ty4, tx4);
    __syncthreads();
#pragma unroll
    for (int i = 0; i < 4; ++i)
#pragma unroll
        for (int j = 0; j < 4; ++j)
            Xs[ty4 + i][tx4 + j] = fmaxf(acc[i][j] + f1b[layer*64 + ty4 + i], 0.f);
    {
        const float* wsrc = g_f2T + (size_t)layer * 4096;
        for (int e = tid; e < 4096; e += 256) ((float*)Ws)[e] = wsrc[e];
    }
    __syncthreads();
    float a2[4][4] = {};
    mm_16x16(Ws, Xs, a2, ty4, tx4);
#pragma unroll
    for (int i = 0; i < 4; ++i)
#pragma unroll
        for (int j = 0; j < 4; ++j) {
            int d = ty4 + i, l = l0 + tx4 + j;
            size_t o = (size_t)(n*D_ + d)*L_ + l;
            float nv = g_fra[o] + a2[i][j] + f2b[layer*64 + d];
            g_fra[o] = nv;
            __half h = __float2half(nv);
            g_fh[o] = h;
            g_fl[o] = __float2half(nv - __half2float(h));
        }
}

// ---------------- conv_out (1x1, 64->48) ----------------
__global__ void __launch_bounds__(256) conv_out_kernel(const float* __restrict__ w,
                                                       const float* __restrict__ b,
                                                       float* __restrict__ out) {
    __shared__ float Xs[64][64];
    __shared__ float Wt[64][NC_];
    const int n = blockIdx.y, l0 = blockIdx.x * 64;
    const int tid = threadIdx.x, ty = tid >> 4, tx = tid & 15;
    for (int e = tid; e < 4096; e += 256) {
        int c = e >> 6, tt = e & 63;
        Xs[c][tt] = g_fra[(size_t)(n*D_ + c)*L_ + l0 + tt];
    }
    for (int e = tid; e < 64*NC_; e += 256) {
        int c = e / NC_, o = e % NC_;
        Wt[c][o] = w[o*64 + c];
    }
    __syncthreads();
    if (ty < 12) {
        const int ty4 = ty*4, tx4 = tx*4;
        float acc[4][4] = {};
#pragma unroll 16
        for (int c = 0; c < 64; ++c) {
            const float4 a = *(const float4*)(&Wt[c][ty4]);
            const float4 x4 = *(const float4*)(&Xs[c][tx4]);
            acc[0][0]+=a.x*x4.x; acc[0][1]+=a.x*x4.y; acc[0][2]+=a.x*x4.z; acc[0][3]+=a.x*x4.w;
            acc[1][0]+=a.y*x4.x; acc[1][1]+=a.y*x4.y; acc[1][2]+=a.y*x4.z; acc[1][3]+=a.y*x4.w;
            acc[2][0]+=a.z*x4.x; acc[2][1]+=a.z*x4.y; acc[2][2]+=a.z*x4.z; acc[2][3]+=a.z*x4.w;
            acc[3][0]+=a.w*x4.x; acc[3][1]+=a.w*x4.y; acc[3][2]+=a.w*x4.z; acc[3][3]+=a.w*x4.w;
        }
#pragma unroll
        for (int i = 0; i < 4; ++i)
#pragma unroll
            for (int j = 0; j < 4; ++j) {
                int o = ty4 + i, l = l0 + tx4 + j;
                out[(size_t)(n*NC_ + o)*L_ + l] = acc[i][j] + b[o];
            }
    }
}

// ---------------- host side ----------------
extern "C" void kernel_launch(void* const* d_in, const int* in_sizes, int n_in,
                              void* d_out, int out_size) {
    (void)in_sizes; (void)n_in; (void)out_size;
    const float* x     = (const float*)d_in[0];
    const int*   t     = (const int*)  d_in[1];
    const float* event = (const float*)d_in[2];
    const float* tw1   = (const float*)d_in[3];
    const float* tb1   = (const float*)d_in[4];
    const float* tw2   = (const float*)d_in[5];
    const float* tb2   = (const float*)d_in[6];
    const float* tpw   = (const float*)d_in[7];
    const float* tpb   = (const float*)d_in[8];
    const float* ciw   = (const float*)d_in[9];
    const float* cib   = (const float*)d_in[10];
    const float* cow   = (const float*)d_in[11];
    const float* cob   = (const float*)d_in[12];
    const float* lcw   = (const float*)d_in[13];
    const float* lcb   = (const float*)d_in[14];
    const float* qw    = (const float*)d_in[15];
    const float* qb    = (const float*)d_in[16];
    const float* kw    = (const float*)d_in[17];
    const float* kb    = (const float*)d_in[18];
    const float* vw    = (const float*)d_in[19];
    const float* vb    = (const float*)d_in[20];
    const float* f1w   = (const float*)d_in[21];
    const float* f1b   = (const float*)d_in[22];
    const float* f2w   = (const float*)d_in[23];
    const float* f2b   = (const float*)d_in[24];

    cudaFuncSetAttribute(layer_mm_kernel, cudaFuncAttributeMaxDynamicSharedMemorySize, LA_SMEM);

    pack_wp_kernel<<<(M_*CR_)/256, 256>>>(qw, kw);
    xt_kernel<<<dim3(L_/32, CR_/32, B_), 256>>>(x);
    pack_aw_kernel<<<(NL_*8*64*64)/256, 256>>>(lcw, qw, kw, vw, f1w, f2w);
    temb1_kernel<<<dim3(64, B_), 256>>>(t, tw1, tb1);
    temb2_kernel<<<dim3(64, B_), 256>>>(tw2, tb2);
    gemm_bf16_kernel<<<dim3(M_/GM_BM, NCOL_/GM_BN), 256>>>();
    tembp_kernel<<<dim3(8, B_), 256>>>(tpw, tpb);
    conv_in_kernel<<<dim3(L_/64, B_), 256>>>(event, ciw, cib);

    for (int i = 0; i < NL_; ++i) {
        int dil = 1 << i;
        layer_mm_kernel<<<dim3(L_/128, B_), 256, LA_SMEM>>>(lcb, qb, kb, vb, i, dil);
        attn_score_kernel<<<dim3(L_/256, B_), 256>>>(dil);
        attn_apply_kernel<<<dim3(L_/256, D_, B_), 256>>>(dil);
        ffn_kernel<<<dim3(L_/64, B_), 256>>>(f1b, f2b, i);
    }
    conv_out_kernel<<<dim3(L_/64, B_), 256>>>(cow, cob, (float*)d_out);
}

// round 5
// speedup vs baseline: 3.0809x; 1.2954x over previous
#include <cuda_runtime.h>
#include <cuda_bf16.h>
#include <cuda_fp16.h>
#include <math.h>
#include <stdint.h>

#define B_  2
#define L_  8192
#define D_  64
#define CR_ 2048
#define NC_ 48
#define TE_ 512
#define NL_ 8
#define M_  1024        // NL*2*D rows of the batched cross GEMM
#define NCOL_ (B_*L_)   // 16384 columns
#define K4_ (2*CR_)     // 4096 augmented K: [W|W] x [xh;xl]

// ---------------- scratch (device globals; no allocation allowed) ----------------
__device__ __half g_Wp[(size_t)M_*K4_];        // A' = [W | W] fp16, K-major
__device__ __half g_Xp[(size_t)NCOL_*K4_];     // B' = [xh ; xl] fp16, K-major per col
__device__ float g_QKC [(size_t)M_*NCOL_];     // cross-projection results [m][n*L+l]
__device__ __half g_AW[NL_*8*2*64*64];   // layer weights [i][slot][hi/lo][m][k]; slots: taps{0,1,3,4,2},q,k,v
__device__ __half g_fh[B_*D_*L_];        // fra fp16 hi
__device__ __half g_fl[B_*D_*L_];        // fra fp16 lo
__device__ float g_f1T [NL_*64*64];
__device__ float g_f2T [NL_*64*64];
__device__ float g_fra [B_*D_*L_];
__device__ float g_xq  [B_*D_*L_];
__device__ float g_xk  [B_*D_*L_];
__device__ float g_xv  [B_*D_*L_];
__device__ float g_out1[B_*D_*L_];
__device__ float g_y   [B_*D_*L_];
__device__ float g_part[B_*D_*128*2];
__device__ float g_tproj[B_*D_];
__device__ float g_t1[B_*TE_];
__device__ float g_t2[B_*TE_];

__device__ __forceinline__ uint32_t smem_u32(const void* p) {
    return (uint32_t)__cvta_generic_to_shared(p);
}
__device__ __forceinline__ void ldsm_x4(uint32_t* r, uint32_t addr) {
    asm volatile("ldmatrix.sync.aligned.m8n8.x4.shared.b16 {%0,%1,%2,%3}, [%4];"
                 : "=r"(r[0]), "=r"(r[1]), "=r"(r[2]), "=r"(r[3]) : "r"(addr));
}
__device__ __forceinline__ void ldsm_x4t(uint32_t* r, uint32_t addr) {
    asm volatile("ldmatrix.sync.aligned.m8n8.x4.trans.shared.b16 {%0,%1,%2,%3}, [%4];"
                 : "=r"(r[0]), "=r"(r[1]), "=r"(r[2]), "=r"(r[3]) : "r"(addr));
}
__device__ __forceinline__ void mma_fp16(float c[4], uint32_t a0, uint32_t a1, uint32_t a2,
                                         uint32_t a3, uint32_t b0, uint32_t b1) {
    asm volatile("mma.sync.aligned.m16n8k16.row.col.f32.f16.f16.f32 "
                 "{%0,%1,%2,%3}, {%4,%5,%6,%7}, {%8,%9}, {%0,%1,%2,%3};"
                 : "+f"(c[0]), "+f"(c[1]), "+f"(c[2]), "+f"(c[3])
                 : "r"(a0), "r"(a1), "r"(a2), "r"(a3), "r"(b0), "r"(b1));
}
__device__ __forceinline__ void cp16(uint32_t saddr, const void* gptr) {
    asm volatile("cp.async.cg.shared.global [%0], [%1], 16;" :: "r"(saddr), "l"(gptr));
}
#define CP_COMMIT() asm volatile("cp.async.commit_group;")
#define CP_WAIT1() asm volatile("cp.async.wait_group 1;")
#define CP_WAIT0() asm volatile("cp.async.wait_group 0;")

// ================== fp16 HMMA cross GEMM ==================
#define GM_BM 128
#define GM_BN 128
#define GM_BK 32
#define GM_NT (K4_/GM_BK)   // 128
#define APAD 40

__global__ void __launch_bounds__(256) gemm_fp16_kernel() {
    __shared__ __half As[2][GM_BM * APAD];
    __shared__ __half Bs[2][GM_BN * APAD];
    const int tid = threadIdx.x, lane = tid & 31, wid = tid >> 5;
    const int wm = wid >> 2, wn = wid & 3;
    const int m0 = blockIdx.x * GM_BM;
    const int col0 = blockIdx.y * GM_BN;
    const int ldr = tid >> 1, ldc = (tid & 1) * 2;

    float acc[4][4][4];
#pragma unroll
    for (int i = 0; i < 4; ++i)
#pragma unroll
        for (int j = 0; j < 4; ++j)
#pragma unroll
            for (int q = 0; q < 4; ++q) acc[i][j][q] = 0.f;

    const int lrow = lane & 15, lhalf = lane >> 4;

    auto load_tile = [&](int kt, int buf) {
        const size_t gk = (size_t)kt * GM_BK;
#pragma unroll
        for (int s = 0; s < 2; ++s) {
            int c = ldc + s;
            cp16(smem_u32(&As[buf][ldr * APAD + c * 8]),
                 g_Wp + (size_t)(m0 + ldr) * K4_ + gk + c * 8);
            cp16(smem_u32(&Bs[buf][ldr * APAD + c * 8]),
                 g_Xp + (size_t)(col0 + ldr) * K4_ + gk + c * 8);
        }
        CP_COMMIT();
    };

    load_tile(0, 0);
    for (int kt = 0; kt < GM_NT; ++kt) {
        const int cur = kt & 1;
        if (kt + 1 < GM_NT) { load_tile(kt + 1, cur ^ 1); CP_WAIT1(); }
        else CP_WAIT0();
        __syncthreads();
#pragma unroll
        for (int kk2 = 0; kk2 < 2; ++kk2) {
            uint32_t a[4][4];
#pragma unroll
            for (int mt = 0; mt < 4; ++mt)
                ldsm_x4(a[mt], smem_u32(&As[cur][(wm*64 + mt*16 + lrow) * APAD + kk2*16 + lhalf*8]));
            uint32_t b[4][2];
#pragma unroll
            for (int nb2 = 0; nb2 < 2; ++nb2) {
                uint32_t r[4];
                ldsm_x4(r, smem_u32(&Bs[cur][(wn*32 + nb2*16 + lrow) * APAD + kk2*16 + lhalf*8]));
                b[nb2*2 + 0][0] = r[0]; b[nb2*2 + 0][1] = r[2];
                b[nb2*2 + 1][0] = r[1]; b[nb2*2 + 1][1] = r[3];
            }
#pragma unroll
            for (int mt = 0; mt < 4; ++mt)
#pragma unroll
                for (int nt = 0; nt < 4; ++nt)
                    mma_fp16(acc[mt][nt], a[mt][0], a[mt][1], a[mt][2], a[mt][3],
                             b[nt][0], b[nt][1]);
        }
        __syncthreads();
    }
    const int grp = lane >> 2, qd = (lane & 3) * 2;
#pragma unroll
    for (int mt = 0; mt < 4; ++mt)
#pragma unroll
        for (int nt = 0; nt < 4; ++nt) {
            int m = m0 + wm*64 + mt*16 + grp;
            int n = col0 + wn*32 + nt*8 + qd;
            *(float2*)(g_QKC + (size_t)m * NCOL_ + n)       = make_float2(acc[mt][nt][0], acc[mt][nt][1]);
            *(float2*)(g_QKC + (size_t)(m + 8) * NCOL_ + n) = make_float2(acc[mt][nt][2], acc[mt][nt][3]);
        }
}

// ---------------- packing kernels ----------------
__global__ void pack_wp_kernel(const float* __restrict__ qw, const float* __restrict__ kw) {
    int idx = blockIdx.x * 256 + threadIdx.x;
    int m = idx >> 11, c = idx & 2047;
    int i = m >> 7, r = m & 127, s = r >> 6, d = r & 63;
    const float* src = s ? kw : qw;
    float v = src[(i*64 + d)*2112 + 64 + c];
    __half h = __float2half(v);
    size_t base = (size_t)m * K4_ + c;
    g_Wp[base] = h; g_Wp[base + CR_] = h;
}

__global__ void __launch_bounds__(256) xt_kernel(const float* __restrict__ x) {
    __shared__ float ts[32][33];
    const int lb = blockIdx.x * 32, kb = blockIdx.y * 32, n = blockIdx.z;
    const int tx = threadIdx.x & 31, ty = threadIdx.x >> 5;
#pragma unroll
    for (int r = ty; r < 32; r += 8)
        ts[r][tx] = x[((size_t)n * CR_ + kb + r) * L_ + lb + tx];
    __syncthreads();
#pragma unroll
    for (int r = ty; r < 32; r += 8) {
        float v = ts[tx][r];
        __half h = __float2half(v);
        __half lo = __float2half(v - __half2float(h));
        size_t base = (size_t)(n * L_ + lb + r) * K4_ + kb + tx;
        g_Xp[base] = h; g_Xp[base + CR_] = lo;
    }
}

// pack per-layer weights into fp16 hi/lo A-layout [m][k]
__global__ void pack_aw_kernel(const float* __restrict__ convw, const float* __restrict__ qw,
                               const float* __restrict__ kw,   const float* __restrict__ vw,
                               const float* __restrict__ f1w,  const float* __restrict__ f2w) {
    int idx = blockIdx.x * 256 + threadIdx.x;     // NL_*8*4096
    if (idx < NL_*8*64*64) {
        int c = idx & 63, m = (idx >> 6) & 63, s = (idx >> 12) & 7, i = idx >> 15;
        const int tapmap[5] = {0, 1, 3, 4, 2};
        float v;
        if (s < 5)      v = convw[((i*64 + m)*64 + c)*5 + tapmap[s]];
        else if (s == 5) v = qw[(i*64 + m)*2112 + c];
        else if (s == 6) v = kw[(i*64 + m)*2112 + c];
        else             v = vw[(i*64 + m)*64 + c];
        __half h = __float2half(v);
        __half lo = __float2half(v - __half2float(h));
        size_t base = ((size_t)(i*8 + s)*2) * 4096 + m*64 + c;
        g_AW[base] = h;
        g_AW[base + 4096] = lo;
    }
    if (idx < NL_*64*64) {
        int d = idx & 63, c = (idx >> 6) & 63, i = idx >> 12;
        g_f1T[idx] = f1w[(i*64 + d)*64 + c];
        g_f2T[idx] = f2w[(i*64 + d)*64 + c];
    }
}

// ---------------- timestep embedding (coalesced, 3 stages) ----------------
__global__ void temb1_kernel(const int* __restrict__ t, const float* __restrict__ w1,
                             const float* __restrict__ b1) {
    __shared__ float se[TE_];
    const int n = blockIdx.y, tid = threadIdx.x;
    const float tv = (float)t[n];
    if (tid < 256) {
        float f = expf((float)tid * (-logf(10000.0f) / 255.0f));
        se[tid] = sinf(tv * f);
        se[tid + 256] = cosf(tv * f);
    }
    __syncthreads();
    const int w = tid >> 5, lane = tid & 31;
    const int o = blockIdx.x * 8 + w;
    const float* wr = w1 + (size_t)o * TE_;
    float s = 0.f;
    for (int c = lane; c < TE_; c += 32) s += se[c] * wr[c];
#pragma unroll
    for (int off = 16; off; off >>= 1) s += __shfl_xor_sync(0xffffffffu, s, off);
    if (!lane) { s += b1[o]; g_t1[n*TE_ + o] = s / (1.f + expf(-s)); }
}
__global__ void temb2_kernel(const float* __restrict__ w2, const float* __restrict__ b2) {
    __shared__ float se[TE_];
    const int n = blockIdx.y, tid = threadIdx.x;
    se[tid] = g_t1[n*TE_ + tid];
    se[tid + 256] = g_t1[n*TE_ + tid + 256];
    __syncthreads();
    const int w = tid >> 5, lane = tid & 31;
    const int o = blockIdx.x * 8 + w;
    const float* wr = w2 + (size_t)o * TE_;
    float s = 0.f;
    for (int c = lane; c < TE_; c += 32) s += se[c] * wr[c];
#pragma unroll
    for (int off = 16; off; off >>= 1) s += __shfl_xor_sync(0xffffffffu, s, off);
    if (!lane) g_t2[n*TE_ + o] = s + b2[o];
}
__global__ void tembp_kernel(const float* __restrict__ wp, const float* __restrict__ bp) {
    __shared__ float se[TE_];
    const int n = blockIdx.y, tid = threadIdx.x;
    {
        float v0 = g_t2[n*TE_ + tid], v1 = g_t2[n*TE_ + tid + 256];
        se[tid]       = v0 / (1.f + expf(-v0));
        se[tid + 256] = v1 / (1.f + expf(-v1));
    }
    __syncthreads();
    const int w = tid >> 5, lane = tid & 31;
    const int o = blockIdx.x * 8 + w;
    const float* wr = wp + (size_t)o * TE_;
    float s = 0.f;
    for (int c = lane; c < TE_; c += 32) s += se[c] * wr[c];
#pragma unroll
    for (int off = 16; off; off >>= 1) s += __shfl_xor_sync(0xffffffffu, s, off);
    if (!lane) g_tproj[n*D_ + o] = s + bp[o];
}

// ---------------- conv_in (1x1, 48->64) + time proj; writes fp32 + fp16 hi/lo ------
__global__ void __launch_bounds__(256) conv_in_kernel(const float* __restrict__ event,
                                                      const float* __restrict__ w,
                                                      const float* __restrict__ b) {
    __shared__ float Et[NC_][64];
    __shared__ float Wt[NC_][64];
    const int n = blockIdx.y, l0 = blockIdx.x * 64;
    const int tid = threadIdx.x, ty4 = (tid >> 4) << 2, tx4 = (tid & 15) << 2;
    for (int e = tid; e < NC_*64; e += 256) {
        int c = e >> 6, tt = e & 63;
        Et[c][tt] = event[(n*NC_ + c)*L_ + l0 + tt];
        Wt[c][tt] = w[tt*NC_ + c];
    }
    __syncthreads();
    float acc[4][4] = {};
#pragma unroll
    for (int c = 0; c < NC_; ++c) {
        const float4 a = *(const float4*)(&Wt[c][ty4]);
        const float4 x4 = *(const float4*)(&Et[c][tx4]);
        acc[0][0]+=a.x*x4.x; acc[0][1]+=a.x*x4.y; acc[0][2]+=a.x*x4.z; acc[0][3]+=a.x*x4.w;
        acc[1][0]+=a.y*x4.x; acc[1][1]+=a.y*x4.y; acc[1][2]+=a.y*x4.z; acc[1][3]+=a.y*x4.w;
        acc[2][0]+=a.z*x4.x; acc[2][1]+=a.z*x4.y; acc[2][2]+=a.z*x4.z; acc[2][3]+=a.z*x4.w;
        acc[3][0]+=a.w*x4.x; acc[3][1]+=a.w*x4.y; acc[3][2]+=a.w*x4.z; acc[3][3]+=a.w*x4.w;
    }
#pragma unroll
    for (int i = 0; i < 4; ++i)
#pragma unroll
        for (int j = 0; j < 4; ++j) {
            int d = ty4 + i, l = l0 + tx4 + j;
            size_t o = (size_t)(n*D_ + d)*L_ + l;
            float v = acc[i][j] + b[d] + g_tproj[n*D_ + d];
            g_fra[o] = v;
            __half h = __float2half(v);
            g_fh[o] = h;
            g_fl[o] = __float2half(v - __half2float(h));
        }
}

// ================== per-layer HMMA: conv(5 taps) + q/k/v ==================
#define LA_SMEM (32768 + 65536)

__device__ __forceinline__ void mm64(float acc[2][4][4], uint32_t Ah, uint32_t Al,
                                     uint32_t Bh, uint32_t Bl, int wm, int wn, int lane) {
    const int lrow = lane & 15, lhalf = lane >> 4;
    const int bk = (lane & 7) + (((lane >> 3) & 1) << 3);
    const int bn8 = (lane >> 4) << 3;
#pragma unroll
    for (int pass = 0; pass < 3; ++pass) {
        uint32_t Ab = (pass == 2) ? Al : Ah;
        uint32_t Bb = (pass == 1) ? Bl : Bh;
#pragma unroll
        for (int k0 = 0; k0 < 4; ++k0) {
            uint32_t a[2][4];
#pragma unroll
            for (int mt = 0; mt < 2; ++mt) {
                int m = wm*32 + mt*16 + lrow;
                int ch = (k0*2 + lhalf) ^ (m & 7);
                ldsm_x4(a[mt], Ab + m*128 + ch*16);
            }
            uint32_t b[4][2];
#pragma unroll
            for (int ng = 0; ng < 2; ++ng) {
                int k = k0*16 + bk;
                int n = wn*32 + ng*16 + bn8;
                int ch = (n >> 3) ^ (k & 7);
                uint32_t r[4];
                ldsm_x4t(r, Bb + k*256 + ch*16);
                b[ng*2 + 0][0] = r[0]; b[ng*2 + 0][1] = r[1];
                b[ng*2 + 1][0] = r[2]; b[ng*2 + 1][1] = r[3];
            }
#pragma unroll
            for (int mt = 0; mt < 2; ++mt)
#pragma unroll
                for (int nt = 0; nt < 4; ++nt)
                    mma_fp16(acc[mt][nt], a[mt][0], a[mt][1], a[mt][2], a[mt][3],
                             b[nt][0], b[nt][1]);
        }
    }
}

__global__ void __launch_bounds__(256) layer_mm_kernel(const float* __restrict__ convb,
                                                       const float* __restrict__ qb,
                                                       const float* __restrict__ kb,
                                                       const float* __restrict__ vb,
                                                       int layer, int dil) {
    extern __shared__ char dsm[];
    char* smA = dsm;            // 2 x 16KB (hi 8KB + lo 8KB)
    char* smB = dsm + 32768;    // 2 x 32KB (hi 16KB + lo 16KB)
    const int tid = threadIdx.x, lane = tid & 31, wid = tid >> 5;
    const int wm = wid >> 2, wn = wid & 3;
    const int l0 = blockIdx.x * 128, nb = blockIdx.y;
    const __half* fh = g_fh + (size_t)nb * D_ * L_;
    const __half* fl = g_fl + (size_t)nb * D_ * L_;

    auto loadA = [&](int slot, int buf) {
        const __half* src = g_AW + ((size_t)(layer*8 + slot)*2) * 4096;
        char* dh = smA + buf * 16384;
        char* dl = dh + 8192;
#pragma unroll
        for (int e = tid; e < 512; e += 256) {
            int m = e >> 3, c = e & 7;
            int off = m*128 + ((c ^ (m & 7)) << 4);
            cp16(smem_u32(dh + off), src + m*64 + c*8);
            cp16(smem_u32(dl + off), src + 4096 + m*64 + c*8);
        }
    };
    auto loadB = [&](int shift, int buf) {
        char* dh = smB + buf * 32768;
        char* dl = dh + 16384;
        const bool aligned = ((shift & 7) == 0);
#pragma unroll
        for (int e = tid; e < 1024; e += 256) {
            int k = e >> 4, c = e & 15;
            int gl = l0 + c*8 + shift;
            int off = k*256 + ((c ^ (k & 7)) << 4);
            if (aligned && gl >= 0 && gl + 8 <= L_) {
                cp16(smem_u32(dh + off), fh + (size_t)k * L_ + gl);
                cp16(smem_u32(dl + off), fl + (size_t)k * L_ + gl);
            } else {
                __half* ph = (__half*)(dh + off);
                __half* pl = (__half*)(dl + off);
#pragma unroll
                for (int u = 0; u < 8; ++u) {
                    int l = gl + u;
                    bool ok = ((unsigned)l < (unsigned)L_);
                    ph[u] = ok ? fh[(size_t)k * L_ + l] : __half(0.f);
                    pl[u] = ok ? fl[(size_t)k * L_ + l] : __half(0.f);
                }
            }
        }
    };

    const int tapshift[5] = {-2*dil, -dil, dil, 2*dil, 0};

    float acc[2][4][4];
#pragma unroll
    for (int i = 0; i < 2; ++i)
#pragma unroll
        for (int j = 0; j < 4; ++j)
#pragma unroll
            for (int q = 0; q < 4; ++q) acc[i][j][q] = 0.f;

    loadB(tapshift[0], 0);
    loadA(0, 0);
    CP_COMMIT();

    const int grp = lane >> 2, qd = (lane & 3) * 2;
    auto epilogue = [&](float* dst, const float* bias, const float* qkc) {
#pragma unroll
        for (int mt = 0; mt < 2; ++mt)
#pragma unroll
            for (int nt = 0; nt < 4; ++nt) {
                int m = wm*32 + mt*16 + grp;
                int n = wn*32 + nt*8 + qd;
                float v0 = acc[mt][nt][0] + bias[m];
                float v1 = acc[mt][nt][1] + bias[m];
                float v2 = acc[mt][nt][2] + bias[m + 8];
                float v3 = acc[mt][nt][3] + bias[m + 8];
                if (qkc) {
                    float2 e0 = *(const float2*)(qkc + (size_t)m * NCOL_ + n);
                    float2 e1 = *(const float2*)(qkc + (size_t)(m + 8) * NCOL_ + n);
                    v0 += e0.x; v1 += e0.y; v2 += e1.x; v3 += e1.y;
                }
                *(float2*)(dst + (size_t)(nb*D_ + m) * L_ + l0 + n)     = make_float2(v0, v1);
                *(float2*)(dst + (size_t)(nb*D_ + m + 8) * L_ + l0 + n) = make_float2(v2, v3);
                acc[mt][nt][0] = acc[mt][nt][1] = acc[mt][nt][2] = acc[mt][nt][3] = 0.f;
            }
    };

    for (int it = 0; it < 8; ++it) {
        __syncthreads();
        if (it < 7) {
            if (it < 4) loadB(tapshift[it + 1], (it + 1) & 1);
            loadA(it + 1, (it + 1) & 1);
            CP_COMMIT();
            CP_WAIT1();
        } else {
            CP_WAIT0();
        }
        __syncthreads();
        const int abuf = it & 1;
        const int bbuf = (it < 5) ? (it & 1) : 0;
        uint32_t Ah = smem_u32(smA + abuf * 16384);
        uint32_t Al = Ah + 8192;
        uint32_t Bh = smem_u32(smB + bbuf * 32768);
        uint32_t Bl = Bh + 16384;
        mm64(acc, Ah, Al, Bh, Bl, wm, wn, lane);
        if (it == 4) {
            epilogue(g_out1, convb + layer*64, nullptr);
        } else if (it == 5) {
            epilogue(g_xq, qb + layer*64, g_QKC + (size_t)(layer*2)*64*NCOL_ + nb*L_ + l0);
        } else if (it == 6) {
            epilogue(g_xk, kb + layer*64, g_QKC + (size_t)(layer*2 + 1)*64*NCOL_ + nb*L_ + l0);
        } else if (it == 7) {
            epilogue(g_xv, vb + layer*64, nullptr);
        }
    }
}

// ---------------- fused attention: scores + softmax + apply + IN partials ----------
__global__ void __launch_bounds__(256) attn_fused_kernel(int dil) {
    __shared__ float satt[5][64];
    const int n = blockIdx.y, l0 = blockIdx.x * 64;
    const int tid = threadIdx.x;

    // ---- stage A: scores + softmax (4 lanes per l) ----
    {
        const int g = tid & 3, l = tid >> 2;          // l 0..63
        const int lg = l0 + l;
        const float* qp = g_xq + (size_t)n * D_ * L_ + lg;
        const float* kp = g_xk + (size_t)n * D_ * L_;
        bool v[5]; int pc[5];
#pragma unroll
        for (int j = 0; j < 5; ++j) {
            int p = lg + (j - 2) * dil;
            v[j] = ((unsigned)p < (unsigned)L_);
            pc[j] = v[j] ? p : lg;
        }
        float dot[5] = {};
#pragma unroll 4
        for (int c = g; c < 64; c += 4) {
            float qv = qp[c * L_];
#pragma unroll
            for (int j = 0; j < 5; ++j) dot[j] += qv * kp[c*L_ + pc[j]];
        }
#pragma unroll
        for (int j = 0; j < 5; ++j) {
            dot[j] += __shfl_xor_sync(0xffffffffu, dot[j], 1);
            dot[j] += __shfl_xor_sync(0xffffffffu, dot[j], 2);
        }
        const float LVALID = logf(1.0f + 1e-6f);
        const float LINV   = logf(1e-6f);
        float lg5[5];
#pragma unroll
        for (int j = 0; j < 5; ++j) lg5[j] = v[j] ? dot[j]*0.125f + LVALID : LINV;
        float mx = lg5[0];
#pragma unroll
        for (int j = 1; j < 5; ++j) mx = fmaxf(mx, lg5[j]);
        float e[5], s = 0.f;
#pragma unroll
        for (int j = 0; j < 5; ++j) { e[j] = expf(lg5[j] - mx); s += e[j]; }
        float inv = 1.f / s;
        if (g == 0) {
#pragma unroll
            for (int j = 0; j < 5; ++j) satt[j][l] = v[j] ? e[j]*inv : 0.f;
        }
    }
    __syncthreads();

    // ---- stage B: r = att @ v_win, y = out1 + r, per-channel partial stats ----
    const int tx = tid & 15, ty = tid >> 4;
    const int c0 = ty * 4, lx = tx * 4;
    float s1[4] = {}, s2[4] = {};
#pragma unroll
    for (int ci = 0; ci < 4; ++ci) {
        int c = c0 + ci;
        const float* vp = g_xv + (size_t)(n*D_ + c) * L_;
        const float* op = g_out1 + (size_t)(n*D_ + c) * L_ + l0;
        float* yp = g_y + (size_t)(n*D_ + c) * L_ + l0;
        float yv4[4];
#pragma unroll
        for (int lj = 0; lj < 4; ++lj) {
            int l = lx + lj, lgl = l0 + l;
            float r = 0.f;
#pragma unroll
            for (int j = 0; j < 5; ++j) {
                int pp = lgl + (j - 2) * dil;
                if ((unsigned)pp < (unsigned)L_) r += satt[j][l] * vp[pp];
            }
            float yv = op[l] + r;
            yv4[lj] = yv;
            s1[ci] += yv; s2[ci] += yv * yv;
        }
        *(float4*)(yp + lx) = make_float4(yv4[0], yv4[1], yv4[2], yv4[3]);
    }
#pragma unroll
    for (int off = 8; off; off >>= 1)
#pragma unroll
        for (int ci = 0; ci < 4; ++ci) {
            s1[ci] += __shfl_xor_sync(0xffffffffu, s1[ci], off);
            s2[ci] += __shfl_xor_sync(0xffffffffu, s2[ci], off);
        }
    if (tx == 0) {
#pragma unroll
        for (int ci = 0; ci < 4; ++ci) {
            g_part[((n*D_ + c0 + ci)*128 + blockIdx.x)*2 + 0] = s1[ci];
            g_part[((n*D_ + c0 + ci)*128 + blockIdx.x)*2 + 1] = s2[ci];
        }
    }
}

// ---------------- shared-mem 64x64 micro-matmul (SIMT, for FFN) ----------------
__device__ __forceinline__ void mm_16x16(const float (*Ws)[64], const float (*Xs)[64],
                                         float acc[4][4], int ty4, int tx4) {
#pragma unroll 16
    for (int c = 0; c < 64; ++c) {
        const float4 a = *(const float4*)(&Ws[c][ty4]);
        const float4 b = *(const float4*)(&Xs[c][tx4]);
        acc[0][0] += a.x*b.x; acc[0][1] += a.x*b.y; acc[0][2] += a.x*b.z; acc[0][3] += a.x*b.w;
        acc[1][0] += a.y*b.x; acc[1][1] += a.y*b.y; acc[1][2] += a.y*b.z; acc[1][3] += a.y*b.w;
        acc[2][0] += a.z*b.x; acc[2][1] += a.z*b.y; acc[2][2] += a.z*b.z; acc[2][3] += a.z*b.w;
        acc[3][0] += a.w*b.x; acc[3][1] += a.w*b.y; acc[3][2] += a.w*b.z; acc[3][3] += a.w*b.w;
    }
}

// ---------------- instance-norm stats + FFN + residual; writes fp32 + fp16 ---------
__global__ void __launch_bounds__(256) ffn_kernel(const float* __restrict__ f1b,
                                                  const float* __restrict__ f2b,
                                                  int layer) {
    __shared__ float Xs[64][64];
    __shared__ float Ws[64][64];
    __shared__ float sms[64], srs[64];
    const int n = blockIdx.y, l0 = blockIdx.x * 64;
    const int tid = threadIdx.x, ty4 = (tid >> 4) << 2, tx4 = (tid & 15) << 2;
    if (tid < 64) {
        float s = 0.f, s2 = 0.f;
        for (int bq = 0; bq < 128; ++bq) {
            s  += g_part[((n*D_ + tid)*128 + bq)*2 + 0];
            s2 += g_part[((n*D_ + tid)*128 + bq)*2 + 1];
        }
        float mean = s / (float)L_;
        float var = s2 / (float)L_ - mean*mean;
        sms[tid] = mean;
        srs[tid] = rsqrtf(var + 1e-5f);
    }
    __syncthreads();
    {
        const float* wsrc = g_f1T + (size_t)layer * 4096;
        for (int e = tid; e < 4096; e += 256) {
            int c = e >> 6, tt = e & 63;
            Xs[c][tt] = (g_y[(size_t)(n*D_ + c)*L_ + l0 + tt] - sms[c]) * srs[c];
            ((float*)Ws)[e] = wsrc[e];
        }
    }
    __syncthreads();
    float acc[4][4] = {};
    mm_16x16(Ws, Xs, acc, ty4, tx4);
    __syncthreads();
#pragma unroll
    for (int i = 0; i < 4; ++i)
#pragma unroll
        for (int j = 0; j < 4; ++j)
            Xs[ty4 + i][tx4 + j] = fmaxf(acc[i][j] + f1b[layer*64 + ty4 + i], 0.f);
    {
        const float* wsrc = g_f2T + (size_t)layer * 4096;
        for (int e = tid; e < 4096; e += 256) ((float*)Ws)[e] = wsrc[e];
    }
    __syncthreads();
    float a2[4][4] = {};
    mm_16x16(Ws, Xs, a2, ty4, tx4);
#pragma unroll
    for (int i = 0; i < 4; ++i)
#pragma unroll
        for (int j = 0; j < 4; ++j) {
            int d = ty4 + i, l = l0 + tx4 + j;
            size_t o = (size_t)(n*D_ + d)*L_ + l;
            float nv = g_fra[o] + a2[i][j] + f2b[layer*64 + d];
            g_fra[o] = nv;
            __half h = __float2half(nv);
            g_fh[o] = h;
            g_fl[o] = __float2half(nv - __half2float(h));
        }
}

// ---------------- conv_out (1x1, 64->48) ----------------
__global__ void __launch_bounds__(256) conv_out_kernel(const float* __restrict__ w,
                                                       const float* __restrict__ b,
                                                       float* __restrict__ out) {
    __shared__ float Xs[64][64];
    __shared__ float Wt[64][NC_];
    const int n = blockIdx.y, l0 = blockIdx.x * 64;
    const int tid = threadIdx.x, ty = tid >> 4, tx = tid & 15;
    for (int e = tid; e < 4096; e += 256) {
        int c = e >> 6, tt = e & 63;
        Xs[c][tt] = g_fra[(size_t)(n*D_ + c)*L_ + l0 + tt];
    }
    for (int e = tid; e < 64*NC_; e += 256) {
        int c = e / NC_, o = e % NC_;
        Wt[c][o] = w[o*64 + c];
    }
    __syncthreads();
    if (ty < 12) {
        const int ty4 = ty*4, tx4 = tx*4;
        float acc[4][4] = {};
#pragma unroll 16
        for (int c = 0; c < 64; ++c) {
            const float4 a = *(const float4*)(&Wt[c][ty4]);
            const float4 x4 = *(const float4*)(&Xs[c][tx4]);
            acc[0][0]+=a.x*x4.x; acc[0][1]+=a.x*x4.y; acc[0][2]+=a.x*x4.z; acc[0][3]+=a.x*x4.w;
            acc[1][0]+=a.y*x4.x; acc[1][1]+=a.y*x4.y; acc[1][2]+=a.y*x4.z; acc[1][3]+=a.y*x4.w;
            acc[2][0]+=a.z*x4.x; acc[2][1]+=a.z*x4.y; acc[2][2]+=a.z*x4.z; acc[2][3]+=a.z*x4.w;
            acc[3][0]+=a.w*x4.x; acc[3][1]+=a.w*x4.y; acc[3][2]+=a.w*x4.z; acc[3][3]+=a.w*x4.w;
        }
#pragma unroll
        for (int i = 0; i < 4; ++i)
#pragma unroll
            for (int j = 0; j < 4; ++j) {
                int o = ty4 + i, l = l0 + tx4 + j;
                out[(size_t)(n*NC_ + o)*L_ + l] = acc[i][j] + b[o];
            }
    }
}

// ---------------- host side ----------------
extern "C" void kernel_launch(void* const* d_in, const int* in_sizes, int n_in,
                              void* d_out, int out_size) {
    (void)in_sizes; (void)n_in; (void)out_size;
    const float* x     = (const float*)d_in[0];
    const int*   t     = (const int*)  d_in[1];
    const float* event = (const float*)d_in[2];
    const float* tw1   = (const float*)d_in[3];
    const float* tb1   = (const float*)d_in[4];
    const float* tw2   = (const float*)d_in[5];
    const float* tb2   = (const float*)d_in[6];
    const float* tpw   = (const float*)d_in[7];
    const float* tpb   = (const float*)d_in[8];
    const float* ciw   = (const float*)d_in[9];
    const float* cib   = (const float*)d_in[10];
    const float* cow   = (const float*)d_in[11];
    const float* cob   = (const float*)d_in[12];
    const float* lcw   = (const float*)d_in[13];
    const float* lcb   = (const float*)d_in[14];
    const float* qw    = (const float*)d_in[15];
    const float* qb    = (const float*)d_in[16];
    const float* kw    = (const float*)d_in[17];
    const float* kb    = (const float*)d_in[18];
    const float* vw    = (const float*)d_in[19];
    const float* vb    = (const float*)d_in[20];
    const float* f1w   = (const float*)d_in[21];
    const float* f1b   = (const float*)d_in[22];
    const float* f2w   = (const float*)d_in[23];
    const float* f2b   = (const float*)d_in[24];

    cudaFuncSetAttribute(layer_mm_kernel, cudaFuncAttributeMaxDynamicSharedMemorySize, LA_SMEM);

    pack_wp_kernel<<<(M_*CR_)/256, 256>>>(qw, kw);
    xt_kernel<<<dim3(L_/32, CR_/32, B_), 256>>>(x);
    pack_aw_kernel<<<(NL_*8*64*64)/256, 256>>>(lcw, qw, kw, vw, f1w, f2w);
    temb1_kernel<<<dim3(64, B_), 256>>>(t, tw1, tb1);
    temb2_kernel<<<dim3(64, B_), 256>>>(tw2, tb2);
    gemm_fp16_kernel<<<dim3(M_/GM_BM, NCOL_/GM_BN), 256>>>();
    tembp_kernel<<<dim3(8, B_), 256>>>(tpw, tpb);
    conv_in_kernel<<<dim3(L_/64, B_), 256>>>(event, ciw, cib);

    for (int i = 0; i < NL_; ++i) {
        int dil = 1 << i;
        layer_mm_kernel<<<dim3(L_/128, B_), 256, LA_SMEM>>>(lcb, qb, kb, vb, i, dil);
        attn_fused_kernel<<<dim3(L_/64, B_), 256>>>(dil);
        ffn_kernel<<<dim3(L_/64, B_), 256>>>(f1b, f2b, i);
    }
    conv_out_kernel<<<dim3(L_/64, B_), 256>>>(cow, cob, (float*)d_out);
}

// round 6
// speedup vs baseline: 4.0638x; 1.3190x over previous
#include <cuda_runtime.h>
#include <cuda_bf16.h>
#include <cuda_fp16.h>
#include <math.h>
#include <stdint.h>

#define B_  2
#define L_  8192
#define D_  64
#define CR_ 2048
#define NC_ 48
#define TE_ 512
#define NL_ 8
#define M_  1024        // NL*2*D rows of the batched cross GEMM
#define NCOL_ (B_*L_)   // 16384 columns

// ---------------- scratch (device globals; no allocation allowed) ----------------
__device__ __half g_Wp[(size_t)M_*CR_];        // A = W fp16, K-major
__device__ __half g_Xp[(size_t)NCOL_*CR_];     // B = x fp16, K-major per col
__device__ float g_QKC [(size_t)M_*NCOL_];     // cross-projection results [m][n*L+l]
__device__ __half g_AW[NL_*8*2*64*64];   // layer weights [i][slot][hi/lo][m][k]; slots: taps{0,1,3,4,2},q,k,v
__device__ __half g_fh[B_*D_*L_];        // fra fp16 hi
__device__ __half g_fl[B_*D_*L_];        // fra fp16 lo
__device__ float g_f1T [NL_*64*64];
__device__ float g_f2T [NL_*64*64];
__device__ float g_fra [B_*D_*L_];
__device__ float g_xq  [B_*D_*L_];
__device__ float g_xk  [B_*D_*L_];
__device__ float g_xv  [B_*D_*L_];
__device__ float g_out1[B_*D_*L_];
__device__ float g_y   [B_*D_*L_];
__device__ float g_part[B_*D_*128*2];
__device__ float g_tproj[B_*D_];
__device__ float g_t1[B_*TE_];
__device__ float g_t2[B_*TE_];

__device__ __forceinline__ uint32_t smem_u32(const void* p) {
    return (uint32_t)__cvta_generic_to_shared(p);
}
__device__ __forceinline__ void ldsm_x4(uint32_t* r, uint32_t addr) {
    asm volatile("ldmatrix.sync.aligned.m8n8.x4.shared.b16 {%0,%1,%2,%3}, [%4];"
                 : "=r"(r[0]), "=r"(r[1]), "=r"(r[2]), "=r"(r[3]) : "r"(addr));
}
__device__ __forceinline__ void ldsm_x4t(uint32_t* r, uint32_t addr) {
    asm volatile("ldmatrix.sync.aligned.m8n8.x4.trans.shared.b16 {%0,%1,%2,%3}, [%4];"
                 : "=r"(r[0]), "=r"(r[1]), "=r"(r[2]), "=r"(r[3]) : "r"(addr));
}
__device__ __forceinline__ void mma_fp16(float c[4], uint32_t a0, uint32_t a1, uint32_t a2,
                                         uint32_t a3, uint32_t b0, uint32_t b1) {
    asm volatile("mma.sync.aligned.m16n8k16.row.col.f32.f16.f16.f32 "
                 "{%0,%1,%2,%3}, {%4,%5,%6,%7}, {%8,%9}, {%0,%1,%2,%3};"
                 : "+f"(c[0]), "+f"(c[1]), "+f"(c[2]), "+f"(c[3])
                 : "r"(a0), "r"(a1), "r"(a2), "r"(a3), "r"(b0), "r"(b1));
}
__device__ __forceinline__ void cp16(uint32_t saddr, const void* gptr) {
    asm volatile("cp.async.cg.shared.global [%0], [%1], 16;" :: "r"(saddr), "l"(gptr));
}
#define CP_COMMIT() asm volatile("cp.async.commit_group;")
#define CP_WAIT1() asm volatile("cp.async.wait_group 1;")
#define CP_WAIT0() asm volatile("cp.async.wait_group 0;")

// ================== fp16 HMMA cross GEMM (single-precision-split-free) ==================
#define GM_BM 128
#define GM_BN 128
#define GM_BK 32
#define GM_NT (CR_/GM_BK)   // 64
#define APAD 40

__global__ void __launch_bounds__(256) gemm_fp16_kernel() {
    __shared__ __half As[2][GM_BM * APAD];
    __shared__ __half Bs[2][GM_BN * APAD];
    const int tid = threadIdx.x, lane = tid & 31, wid = tid >> 5;
    const int wm = wid >> 2, wn = wid & 3;
    const int m0 = blockIdx.x * GM_BM;
    const int col0 = blockIdx.y * GM_BN;
    const int ldr = tid >> 1, ldc = (tid & 1) * 2;

    float acc[4][4][4];
#pragma unroll
    for (int i = 0; i < 4; ++i)
#pragma unroll
        for (int j = 0; j < 4; ++j)
#pragma unroll
            for (int q = 0; q < 4; ++q) acc[i][j][q] = 0.f;

    const int lrow = lane & 15, lhalf = lane >> 4;

    auto load_tile = [&](int kt, int buf) {
        const size_t gk = (size_t)kt * GM_BK;
#pragma unroll
        for (int s = 0; s < 2; ++s) {
            int c = ldc + s;
            cp16(smem_u32(&As[buf][ldr * APAD + c * 8]),
                 g_Wp + (size_t)(m0 + ldr) * CR_ + gk + c * 8);
            cp16(smem_u32(&Bs[buf][ldr * APAD + c * 8]),
                 g_Xp + (size_t)(col0 + ldr) * CR_ + gk + c * 8);
        }
        CP_COMMIT();
    };

    load_tile(0, 0);
    for (int kt = 0; kt < GM_NT; ++kt) {
        const int cur = kt & 1;
        if (kt + 1 < GM_NT) { load_tile(kt + 1, cur ^ 1); CP_WAIT1(); }
        else CP_WAIT0();
        __syncthreads();
#pragma unroll
        for (int kk2 = 0; kk2 < 2; ++kk2) {
            uint32_t a[4][4];
#pragma unroll
            for (int mt = 0; mt < 4; ++mt)
                ldsm_x4(a[mt], smem_u32(&As[cur][(wm*64 + mt*16 + lrow) * APAD + kk2*16 + lhalf*8]));
            uint32_t b[4][2];
#pragma unroll
            for (int nb2 = 0; nb2 < 2; ++nb2) {
                uint32_t r[4];
                ldsm_x4(r, smem_u32(&Bs[cur][(wn*32 + nb2*16 + lrow) * APAD + kk2*16 + lhalf*8]));
                b[nb2*2 + 0][0] = r[0]; b[nb2*2 + 0][1] = r[2];
                b[nb2*2 + 1][0] = r[1]; b[nb2*2 + 1][1] = r[3];
            }
#pragma unroll
            for (int mt = 0; mt < 4; ++mt)
#pragma unroll
                for (int nt = 0; nt < 4; ++nt)
                    mma_fp16(acc[mt][nt], a[mt][0], a[mt][1], a[mt][2], a[mt][3],
                             b[nt][0], b[nt][1]);
        }
        __syncthreads();
    }
    const int grp = lane >> 2, qd = (lane & 3) * 2;
#pragma unroll
    for (int mt = 0; mt < 4; ++mt)
#pragma unroll
        for (int nt = 0; nt < 4; ++nt) {
            int m = m0 + wm*64 + mt*16 + grp;
            int n = col0 + wn*32 + nt*8 + qd;
            *(float2*)(g_QKC + (size_t)m * NCOL_ + n)       = make_float2(acc[mt][nt][0], acc[mt][nt][1]);
            *(float2*)(g_QKC + (size_t)(m + 8) * NCOL_ + n) = make_float2(acc[mt][nt][2], acc[mt][nt][3]);
        }
}

// ---------------- packing kernels ----------------
__global__ void pack_wp_kernel(const float* __restrict__ qw, const float* __restrict__ kw) {
    int idx = blockIdx.x * 256 + threadIdx.x;
    int m = idx >> 11, c = idx & 2047;
    int i = m >> 7, r = m & 127, s = r >> 6, d = r & 63;
    const float* src = s ? kw : qw;
    g_Wp[(size_t)m * CR_ + c] = __float2half(src[(i*64 + d)*2112 + 64 + c]);
}

__global__ void __launch_bounds__(256) xt_kernel(const float* __restrict__ x) {
    __shared__ float ts[32][33];
    const int lb = blockIdx.x * 32, kb = blockIdx.y * 32, n = blockIdx.z;
    const int tx = threadIdx.x & 31, ty = threadIdx.x >> 5;
#pragma unroll
    for (int r = ty; r < 32; r += 8)
        ts[r][tx] = x[((size_t)n * CR_ + kb + r) * L_ + lb + tx];
    __syncthreads();
#pragma unroll
    for (int r = ty; r < 32; r += 8)
        g_Xp[(size_t)(n * L_ + lb + r) * CR_ + kb + tx] = __float2half(ts[tx][r]);
}

// pack per-layer weights into fp16 hi/lo A-layout [m][k]
__global__ void pack_aw_kernel(const float* __restrict__ convw, const float* __restrict__ qw,
                               const float* __restrict__ kw,   const float* __restrict__ vw,
                               const float* __restrict__ f1w,  const float* __restrict__ f2w) {
    int idx = blockIdx.x * 256 + threadIdx.x;     // NL_*8*4096
    if (idx < NL_*8*64*64) {
        int c = idx & 63, m = (idx >> 6) & 63, s = (idx >> 12) & 7, i = idx >> 15;
        const int tapmap[5] = {0, 1, 3, 4, 2};
        float v;
        if (s < 5)      v = convw[((i*64 + m)*64 + c)*5 + tapmap[s]];
        else if (s == 5) v = qw[(i*64 + m)*2112 + c];
        else if (s == 6) v = kw[(i*64 + m)*2112 + c];
        else             v = vw[(i*64 + m)*64 + c];
        __half h = __float2half(v);
        __half lo = __float2half(v - __half2float(h));
        size_t base = ((size_t)(i*8 + s)*2) * 4096 + m*64 + c;
        g_AW[base] = h;
        g_AW[base + 4096] = lo;
    }
    if (idx < NL_*64*64) {
        int d = idx & 63, c = (idx >> 6) & 63, i = idx >> 12;
        g_f1T[idx] = f1w[(i*64 + d)*64 + c];
        g_f2T[idx] = f2w[(i*64 + d)*64 + c];
    }
}

// ---------------- timestep embedding (coalesced, 3 stages) ----------------
__global__ void temb1_kernel(const int* __restrict__ t, const float* __restrict__ w1,
                             const float* __restrict__ b1) {
    __shared__ float se[TE_];
    const int n = blockIdx.y, tid = threadIdx.x;
    const float tv = (float)t[n];
    if (tid < 256) {
        float f = expf((float)tid * (-logf(10000.0f) / 255.0f));
        se[tid] = sinf(tv * f);
        se[tid + 256] = cosf(tv * f);
    }
    __syncthreads();
    const int w = tid >> 5, lane = tid & 31;
    const int o = blockIdx.x * 8 + w;
    const float* wr = w1 + (size_t)o * TE_;
    float s = 0.f;
    for (int c = lane; c < TE_; c += 32) s += se[c] * wr[c];
#pragma unroll
    for (int off = 16; off; off >>= 1) s += __shfl_xor_sync(0xffffffffu, s, off);
    if (!lane) { s += b1[o]; g_t1[n*TE_ + o] = s / (1.f + expf(-s)); }
}
__global__ void temb2_kernel(const float* __restrict__ w2, const float* __restrict__ b2) {
    __shared__ float se[TE_];
    const int n = blockIdx.y, tid = threadIdx.x;
    se[tid] = g_t1[n*TE_ + tid];
    se[tid + 256] = g_t1[n*TE_ + tid + 256];
    __syncthreads();
    const int w = tid >> 5, lane = tid & 31;
    const int o = blockIdx.x * 8 + w;
    const float* wr = w2 + (size_t)o * TE_;
    float s = 0.f;
    for (int c = lane; c < TE_; c += 32) s += se[c] * wr[c];
#pragma unroll
    for (int off = 16; off; off >>= 1) s += __shfl_xor_sync(0xffffffffu, s, off);
    if (!lane) g_t2[n*TE_ + o] = s + b2[o];
}
__global__ void tembp_kernel(const float* __restrict__ wp, const float* __restrict__ bp) {
    __shared__ float se[TE_];
    const int n = blockIdx.y, tid = threadIdx.x;
    {
        float v0 = g_t2[n*TE_ + tid], v1 = g_t2[n*TE_ + tid + 256];
        se[tid]       = v0 / (1.f + expf(-v0));
        se[tid + 256] = v1 / (1.f + expf(-v1));
    }
    __syncthreads();
    const int w = tid >> 5, lane = tid & 31;
    const int o = blockIdx.x * 8 + w;
    const float* wr = wp + (size_t)o * TE_;
    float s = 0.f;
    for (int c = lane; c < TE_; c += 32) s += se[c] * wr[c];
#pragma unroll
    for (int off = 16; off; off >>= 1) s += __shfl_xor_sync(0xffffffffu, s, off);
    if (!lane) g_tproj[n*D_ + o] = s + bp[o];
}

// ---------------- conv_in (1x1, 48->64) + time proj; writes fp32 + fp16 hi/lo ------
__global__ void __launch_bounds__(256) conv_in_kernel(const float* __restrict__ event,
                                                      const float* __restrict__ w,
                                                      const float* __restrict__ b) {
    __shared__ float Et[NC_][64];
    __shared__ float Wt[NC_][64];
    const int n = blockIdx.y, l0 = blockIdx.x * 64;
    const int tid = threadIdx.x, ty4 = (tid >> 4) << 2, tx4 = (tid & 15) << 2;
    for (int e = tid; e < NC_*64; e += 256) {
        int c = e >> 6, tt = e & 63;
        Et[c][tt] = event[(n*NC_ + c)*L_ + l0 + tt];
        Wt[c][tt] = w[tt*NC_ + c];
    }
    __syncthreads();
    float acc[4][4] = {};
#pragma unroll
    for (int c = 0; c < NC_; ++c) {
        const float4 a = *(const float4*)(&Wt[c][ty4]);
        const float4 x4 = *(const float4*)(&Et[c][tx4]);
        acc[0][0]+=a.x*x4.x; acc[0][1]+=a.x*x4.y; acc[0][2]+=a.x*x4.z; acc[0][3]+=a.x*x4.w;
        acc[1][0]+=a.y*x4.x; acc[1][1]+=a.y*x4.y; acc[1][2]+=a.y*x4.z; acc[1][3]+=a.y*x4.w;
        acc[2][0]+=a.z*x4.x; acc[2][1]+=a.z*x4.y; acc[2][2]+=a.z*x4.z; acc[2][3]+=a.z*x4.w;
        acc[3][0]+=a.w*x4.x; acc[3][1]+=a.w*x4.y; acc[3][2]+=a.w*x4.z; acc[3][3]+=a.w*x4.w;
    }
#pragma unroll
    for (int i = 0; i < 4; ++i)
#pragma unroll
        for (int j = 0; j < 4; ++j) {
            int d = ty4 + i, l = l0 + tx4 + j;
            size_t o = (size_t)(n*D_ + d)*L_ + l;
            float v = acc[i][j] + b[d] + g_tproj[n*D_ + d];
            g_fra[o] = v;
            __half h = __float2half(v);
            g_fh[o] = h;
            g_fl[o] = __float2half(v - __half2float(h));
        }
}

// ================== per-layer HMMA: conv(5 taps) + q/k/v ==================
#define LA_SMEM (32768 + 65536)

__device__ __forceinline__ void mm64(float acc[2][4][4], uint32_t Ah, uint32_t Al,
                                     uint32_t Bh, uint32_t Bl, int wm, int wn, int lane) {
    const int lrow = lane & 15, lhalf = lane >> 4;
    const int bk = (lane & 7) + (((lane >> 3) & 1) << 3);
    const int bn8 = (lane >> 4) << 3;
#pragma unroll
    for (int pass = 0; pass < 3; ++pass) {
        uint32_t Ab = (pass == 2) ? Al : Ah;
        uint32_t Bb = (pass == 1) ? Bl : Bh;
#pragma unroll
        for (int k0 = 0; k0 < 4; ++k0) {
            uint32_t a[2][4];
#pragma unroll
            for (int mt = 0; mt < 2; ++mt) {
                int m = wm*32 + mt*16 + lrow;
                int ch = (k0*2 + lhalf) ^ (m & 7);
                ldsm_x4(a[mt], Ab + m*128 + ch*16);
            }
            uint32_t b[4][2];
#pragma unroll
            for (int ng = 0; ng < 2; ++ng) {
                int k = k0*16 + bk;
                int n = wn*32 + ng*16 + bn8;
                int ch = (n >> 3) ^ (k & 7);
                uint32_t r[4];
                ldsm_x4t(r, Bb + k*256 + ch*16);
                b[ng*2 + 0][0] = r[0]; b[ng*2 + 0][1] = r[1];
                b[ng*2 + 1][0] = r[2]; b[ng*2 + 1][1] = r[3];
            }
#pragma unroll
            for (int mt = 0; mt < 2; ++mt)
#pragma unroll
                for (int nt = 0; nt < 4; ++nt)
                    mma_fp16(acc[mt][nt], a[mt][0], a[mt][1], a[mt][2], a[mt][3],
                             b[nt][0], b[nt][1]);
        }
    }
}

__global__ void __launch_bounds__(256) layer_mm_kernel(const float* __restrict__ convb,
                                                       const float* __restrict__ qb,
                                                       const float* __restrict__ kb,
                                                       const float* __restrict__ vb,
                                                       int layer, int dil) {
    extern __shared__ char dsm[];
    char* smA = dsm;            // 2 x 16KB (hi 8KB + lo 8KB)
    char* smB = dsm + 32768;    // 2 x 32KB (hi 16KB + lo 16KB)
    const int tid = threadIdx.x, lane = tid & 31, wid = tid >> 5;
    const int wm = wid >> 2, wn = wid & 3;
    const int l0 = blockIdx.x * 128, nb = blockIdx.y;
    const __half* fh = g_fh + (size_t)nb * D_ * L_;
    const __half* fl = g_fl + (size_t)nb * D_ * L_;
    const float* fb = g_fra + (size_t)nb * D_ * L_;

    auto loadA = [&](int slot, int buf) {
        const __half* src = g_AW + ((size_t)(layer*8 + slot)*2) * 4096;
        char* dh = smA + buf * 16384;
        char* dl = dh + 8192;
#pragma unroll
        for (int e = tid; e < 512; e += 256) {
            int m = e >> 3, c = e & 7;
            int off = m*128 + ((c ^ (m & 7)) << 4);
            cp16(smem_u32(dh + off), src + m*64 + c*8);
            cp16(smem_u32(dl + off), src + 4096 + m*64 + c*8);
        }
    };
    auto loadB = [&](int shift, int buf) {
        char* dh = smB + buf * 32768;
        char* dl = dh + 16384;
        if ((shift & 7) == 0) {
#pragma unroll
            for (int e = tid; e < 1024; e += 256) {
                int k = e >> 4, c = e & 15;
                int gl = l0 + c*8 + shift;
                int off = k*256 + ((c ^ (k & 7)) << 4);
                if (gl >= 0 && gl + 8 <= L_) {
                    cp16(smem_u32(dh + off), fh + (size_t)k * L_ + gl);
                    cp16(smem_u32(dl + off), fl + (size_t)k * L_ + gl);
                } else {
                    __half* ph = (__half*)(dh + off);
                    __half* pl = (__half*)(dl + off);
#pragma unroll
                    for (int u = 0; u < 8; ++u) {
                        int l = gl + u;
                        bool ok = ((unsigned)l < (unsigned)L_);
                        ph[u] = ok ? fh[(size_t)k * L_ + l] : __half(0.f);
                        pl[u] = ok ? fl[(size_t)k * L_ + l] : __half(0.f);
                    }
                }
            }
        } else {
            // unaligned shift: read fp32 fra once, split in-register
#pragma unroll
            for (int e = tid; e < 1024; e += 256) {
                int k = e >> 4, c = e & 15;
                int gl = l0 + c*8 + shift;
                int off = k*256 + ((c ^ (k & 7)) << 4);
                const float* src = fb + (size_t)k * L_;
                __half hb[8], lb[8];
#pragma unroll
                for (int u = 0; u < 8; ++u) {
                    int l = gl + u;
                    float v = ((unsigned)l < (unsigned)L_) ? __ldg(src + l) : 0.f;
                    __half h = __float2half(v);
                    hb[u] = h;
                    lb[u] = __float2half(v - __half2float(h));
                }
                *(uint4*)(dh + off) = *(uint4*)hb;
                *(uint4*)(dl + off) = *(uint4*)lb;
            }
        }
    };

    const int tapshift[5] = {-2*dil, -dil, dil, 2*dil, 0};

    float acc[2][4][4];
#pragma unroll
    for (int i = 0; i < 2; ++i)
#pragma unroll
        for (int j = 0; j < 4; ++j)
#pragma unroll
            for (int q = 0; q < 4; ++q) acc[i][j][q] = 0.f;

    loadB(tapshift[0], 0);
    loadA(0, 0);
    CP_COMMIT();

    const int grp = lane >> 2, qd = (lane & 3) * 2;
    auto epilogue = [&](float* dst, const float* bias, const float* qkc) {
#pragma unroll
        for (int mt = 0; mt < 2; ++mt)
#pragma unroll
            for (int nt = 0; nt < 4; ++nt) {
                int m = wm*32 + mt*16 + grp;
                int n = wn*32 + nt*8 + qd;
                float v0 = acc[mt][nt][0] + bias[m];
                float v1 = acc[mt][nt][1] + bias[m];
                float v2 = acc[mt][nt][2] + bias[m + 8];
                float v3 = acc[mt][nt][3] + bias[m + 8];
                if (qkc) {
                    float2 e0 = *(const float2*)(qkc + (size_t)m * NCOL_ + n);
                    float2 e1 = *(const float2*)(qkc + (size_t)(m + 8) * NCOL_ + n);
                    v0 += e0.x; v1 += e0.y; v2 += e1.x; v3 += e1.y;
                }
                *(float2*)(dst + (size_t)(nb*D_ + m) * L_ + l0 + n)     = make_float2(v0, v1);
                *(float2*)(dst + (size_t)(nb*D_ + m + 8) * L_ + l0 + n) = make_float2(v2, v3);
                acc[mt][nt][0] = acc[mt][nt][1] = acc[mt][nt][2] = acc[mt][nt][3] = 0.f;
            }
    };

    for (int it = 0; it < 8; ++it) {
        __syncthreads();
        if (it < 7) {
            if (it < 4) loadB(tapshift[it + 1], (it + 1) & 1);
            loadA(it + 1, (it + 1) & 1);
            CP_COMMIT();
            CP_WAIT1();
        } else {
            CP_WAIT0();
        }
        __syncthreads();
        const int abuf = it & 1;
        const int bbuf = (it < 5) ? (it & 1) : 0;
        uint32_t Ah = smem_u32(smA + abuf * 16384);
        uint32_t Al = Ah + 8192;
        uint32_t Bh = smem_u32(smB + bbuf * 32768);
        uint32_t Bl = Bh + 16384;
        mm64(acc, Ah, Al, Bh, Bl, wm, wn, lane);
        if (it == 4) {
            epilogue(g_out1, convb + layer*64, nullptr);
        } else if (it == 5) {
            epilogue(g_xq, qb + layer*64, g_QKC + (size_t)(layer*2)*64*NCOL_ + nb*L_ + l0);
        } else if (it == 6) {
            epilogue(g_xk, kb + layer*64, g_QKC + (size_t)(layer*2 + 1)*64*NCOL_ + nb*L_ + l0);
        } else if (it == 7) {
            epilogue(g_xv, vb + layer*64, nullptr);
        }
    }
}

// ---------------- fused attention: scores + softmax + apply + IN partials ----------
__global__ void __launch_bounds__(256) attn_fused_kernel(int dil) {
    __shared__ float satt[5][64];
    const int n = blockIdx.y, l0 = blockIdx.x * 64;
    const int tid = threadIdx.x;

    // ---- stage A: scores + softmax (4 lanes per l) ----
    {
        const int g = tid & 3, l = tid >> 2;          // l 0..63
        const int lg = l0 + l;
        const float* qp = g_xq + (size_t)n * D_ * L_ + lg;
        const float* kp = g_xk + (size_t)n * D_ * L_;
        bool v[5]; int pc[5];
#pragma unroll
        for (int j = 0; j < 5; ++j) {
            int p = lg + (j - 2) * dil;
            v[j] = ((unsigned)p < (unsigned)L_);
            pc[j] = v[j] ? p : lg;
        }
        float dot[5] = {};
#pragma unroll 4
        for (int c = g; c < 64; c += 4) {
            float qv = qp[c * L_];
#pragma unroll
            for (int j = 0; j < 5; ++j) dot[j] += qv * kp[c*L_ + pc[j]];
        }
#pragma unroll
        for (int j = 0; j < 5; ++j) {
            dot[j] += __shfl_xor_sync(0xffffffffu, dot[j], 1);
            dot[j] += __shfl_xor_sync(0xffffffffu, dot[j], 2);
        }
        const float LVALID = logf(1.0f + 1e-6f);
        const float LINV   = logf(1e-6f);
        float lg5[5];
#pragma unroll
        for (int j = 0; j < 5; ++j) lg5[j] = v[j] ? dot[j]*0.125f + LVALID : LINV;
        float mx = lg5[0];
#pragma unroll
        for (int j = 1; j < 5; ++j) mx = fmaxf(mx, lg5[j]);
        float e[5], s = 0.f;
#pragma unroll
        for (int j = 0; j < 5; ++j) { e[j] = expf(lg5[j] - mx); s += e[j]; }
        float inv = 1.f / s;
        if (g == 0) {
#pragma unroll
            for (int j = 0; j < 5; ++j) satt[j][l] = v[j] ? e[j]*inv : 0.f;
        }
    }
    __syncthreads();

    // ---- stage B: r = att @ v_win, y = out1 + r, per-channel partial stats ----
    const int tx = tid & 15, ty = tid >> 4;
    const int c0 = ty * 4, lx = tx * 4;
    float s1[4] = {}, s2[4] = {};
#pragma unroll
    for (int ci = 0; ci < 4; ++ci) {
        int c = c0 + ci;
        const float* vp = g_xv + (size_t)(n*D_ + c) * L_;
        const float* op = g_out1 + (size_t)(n*D_ + c) * L_ + l0;
        float* yp = g_y + (size_t)(n*D_ + c) * L_ + l0;
        float yv4[4];
#pragma unroll
        for (int lj = 0; lj < 4; ++lj) {
            int l = lx + lj, lgl = l0 + l;
            float r = 0.f;
#pragma unroll
            for (int j = 0; j < 5; ++j) {
                int pp = lgl + (j - 2) * dil;
                if ((unsigned)pp < (unsigned)L_) r += satt[j][l] * vp[pp];
            }
            float yv = op[l] + r;
            yv4[lj] = yv;
            s1[ci] += yv; s2[ci] += yv * yv;
        }
        *(float4*)(yp + lx) = make_float4(yv4[0], yv4[1], yv4[2], yv4[3]);
    }
#pragma unroll
    for (int off = 8; off; off >>= 1)
#pragma unroll
        for (int ci = 0; ci < 4; ++ci) {
            s1[ci] += __shfl_xor_sync(0xffffffffu, s1[ci], off);
            s2[ci] += __shfl_xor_sync(0xffffffffu, s2[ci], off);
        }
    if (tx == 0) {
#pragma unroll
        for (int ci = 0; ci < 4; ++ci) {
            g_part[((n*D_ + c0 + ci)*128 + blockIdx.x)*2 + 0] = s1[ci];
            g_part[((n*D_ + c0 + ci)*128 + blockIdx.x)*2 + 1] = s2[ci];
        }
    }
}

// ---------------- shared-mem 64x64 micro-matmul (SIMT, for FFN) ----------------
__device__ __forceinline__ void mm_16x16(const float (*Ws)[64], const float (*Xs)[64],
                                         float acc[4][4], int ty4, int tx4) {
#pragma unroll 16
    for (int c = 0; c < 64; ++c) {
        const float4 a = *(const float4*)(&Ws[c][ty4]);
        const float4 b = *(const float4*)(&Xs[c][tx4]);
        acc[0][0] += a.x*b.x; acc[0][1] += a.x*b.y; acc[0][2] += a.x*b.z; acc[0][3] += a.x*b.w;
        acc[1][0] += a.y*b.x; acc[1][1] += a.y*b.y; acc[1][2] += a.y*b.z; acc[1][3] += a.y*b.w;
        acc[2][0] += a.z*b.x; acc[2][1] += a.z*b.y; acc[2][2] += a.z*b.z; acc[2][3] += a.z*b.w;
        acc[3][0] += a.w*b.x; acc[3][1] += a.w*b.y; acc[3][2] += a.w*b.z; acc[3][3] += a.w*b.w;
    }
}

// ---------------- instance-norm stats + FFN + residual; writes fp32 + fp16 ---------
__global__ void __launch_bounds__(256) ffn_kernel(const float* __restrict__ f1b,
                                                  const float* __restrict__ f2b,
                                                  int layer) {
    __shared__ float Xs[64][64];
    __shared__ float Ws[64][64];
    __shared__ float sms[64], srs[64];
    const int n = blockIdx.y, l0 = blockIdx.x * 64;
    const int tid = threadIdx.x, ty4 = (tid >> 4) << 2, tx4 = (tid & 15) << 2;
    if (tid < 64) {
        float s = 0.f, s2 = 0.f;
        for (int bq = 0; bq < 128; ++bq) {
            s  += g_part[((n*D_ + tid)*128 + bq)*2 + 0];
            s2 += g_part[((n*D_ + tid)*128 + bq)*2 + 1];
        }
        float mean = s / (float)L_;
        float var = s2 / (float)L_ - mean*mean;
        sms[tid] = mean;
        srs[tid] = rsqrtf(var + 1e-5f);
    }
    __syncthreads();
    {
        const float* wsrc = g_f1T + (size_t)layer * 4096;
        for (int e = tid; e < 4096; e += 256) {
            int c = e >> 6, tt = e & 63;
            Xs[c][tt] = (g_y[(size_t)(n*D_ + c)*L_ + l0 + tt] - sms[c]) * srs[c];
            ((float*)Ws)[e] = wsrc[e];
        }
    }
    __syncthreads();
    float acc[4][4] = {};
    mm_16x16(Ws, Xs, acc, ty4, tx4);
    __syncthreads();
#pragma unroll
    for (int i = 0; i < 4; ++i)
#pragma unroll
        for (int j = 0; j < 4; ++j)
            Xs[ty4 + i][tx4 + j] = fmaxf(acc[i][j] + f1b[layer*64 + ty4 + i], 0.f);
    {
        const float* wsrc = g_f2T + (size_t)layer * 4096;
        for (int e = tid; e < 4096; e += 256) ((float*)Ws)[e] = wsrc[e];
    }
    __syncthreads();
    float a2[4][4] = {};
    mm_16x16(Ws, Xs, a2, ty4, tx4);
#pragma unroll
    for (int i = 0; i < 4; ++i)
#pragma unroll
        for (int j = 0; j < 4; ++j) {
            int d = ty4 + i, l = l0 + tx4 + j;
            size_t o = (size_t)(n*D_ + d)*L_ + l;
            float nv = g_fra[o] + a2[i][j] + f2b[layer*64 + d];
            g_fra[o] = nv;
            __half h = __float2half(nv);
            g_fh[o] = h;
            g_fl[o] = __float2half(nv - __half2float(h));
        }
}

// ---------------- conv_out (1x1, 64->48) ----------------
__global__ void __launch_bounds__(256) conv_out_kernel(const float* __restrict__ w,
                                                       const float* __restrict__ b,
                                                       float* __restrict__ out) {
    __shared__ float Xs[64][64];
    __shared__ float Wt[64][NC_];
    const int n = blockIdx.y, l0 = blockIdx.x * 64;
    const int tid = threadIdx.x, ty = tid >> 4, tx = tid & 15;
    for (int e = tid; e < 4096; e += 256) {
        int c = e >> 6, tt = e & 63;
        Xs[c][tt] = g_fra[(size_t)(n*D_ + c)*L_ + l0 + tt];
    }
    for (int e = tid; e < 64*NC_; e += 256) {
        int c = e / NC_, o = e % NC_;
        Wt[c][o] = w[o*64 + c];
    }
    __syncthreads();
    if (ty < 12) {
        const int ty4 = ty*4, tx4 = tx*4;
        float acc[4][4] = {};
#pragma unroll 16
        for (int c = 0; c < 64; ++c) {
            const float4 a = *(const float4*)(&Wt[c][ty4]);
            const float4 x4 = *(const float4*)(&Xs[c][tx4]);
            acc[0][0]+=a.x*x4.x; acc[0][1]+=a.x*x4.y; acc[0][2]+=a.x*x4.z; acc[0][3]+=a.x*x4.w;
            acc[1][0]+=a.y*x4.x; acc[1][1]+=a.y*x4.y; acc[1][2]+=a.y*x4.z; acc[1][3]+=a.y*x4.w;
            acc[2][0]+=a.z*x4.x; acc[2][1]+=a.z*x4.y; acc[2][2]+=a.z*x4.z; acc[2][3]+=a.z*x4.w;
            acc[3][0]+=a.w*x4.x; acc[3][1]+=a.w*x4.y; acc[3][2]+=a.w*x4.z; acc[3][3]+=a.w*x4.w;
        }
#pragma unroll
        for (int i = 0; i < 4; ++i)
#pragma unroll
            for (int j = 0; j < 4; ++j) {
                int o = ty4 + i, l = l0 + tx4 + j;
                out[(size_t)(n*NC_ + o)*L_ + l] = acc[i][j] + b[o];
            }
    }
}

// ---------------- host side ----------------
extern "C" void kernel_launch(void* const* d_in, const int* in_sizes, int n_in,
                              void* d_out, int out_size) {
    (void)in_sizes; (void)n_in; (void)out_size;
    const float* x     = (const float*)d_in[0];
    const int*   t     = (const int*)  d_in[1];
    const float* event = (const float*)d_in[2];
    const float* tw1   = (const float*)d_in[3];
    const float* tb1   = (const float*)d_in[4];
    const float* tw2   = (const float*)d_in[5];
    const float* tb2   = (const float*)d_in[6];
    const float* tpw   = (const float*)d_in[7];
    const float* tpb   = (const float*)d_in[8];
    const float* ciw   = (const float*)d_in[9];
    const float* cib   = (const float*)d_in[10];
    const float* cow   = (const float*)d_in[11];
    const float* cob   = (const float*)d_in[12];
    const float* lcw   = (const float*)d_in[13];
    const float* lcb   = (const float*)d_in[14];
    const float* qw    = (const float*)d_in[15];
    const float* qb    = (const float*)d_in[16];
    const float* kw    = (const float*)d_in[17];
    const float* kb    = (const float*)d_in[18];
    const float* vw    = (const float*)d_in[19];
    const float* vb    = (const float*)d_in[20];
    const float* f1w   = (const float*)d_in[21];
    const float* f1b   = (const float*)d_in[22];
    const float* f2w   = (const float*)d_in[23];
    const float* f2b   = (const float*)d_in[24];

    cudaFuncSetAttribute(layer_mm_kernel, cudaFuncAttributeMaxDynamicSharedMemorySize, LA_SMEM);

    pack_wp_kernel<<<(M_*CR_)/256, 256>>>(qw, kw);
    xt_kernel<<<dim3(L_/32, CR_/32, B_), 256>>>(x);
    pack_aw_kernel<<<(NL_*8*64*64)/256, 256>>>(lcw, qw, kw, vw, f1w, f2w);
    temb1_kernel<<<dim3(64, B_), 256>>>(t, tw1, tb1);
    temb2_kernel<<<dim3(64, B_), 256>>>(tw2, tb2);
    gemm_fp16_kernel<<<dim3(M_/GM_BM, NCOL_/GM_BN), 256>>>();
    tembp_kernel<<<dim3(8, B_), 256>>>(tpw, tpb);
    conv_in_kernel<<<dim3(L_/64, B_), 256>>>(event, ciw, cib);

    for (int i = 0; i < NL_; ++i) {
        int dil = 1 << i;
        layer_mm_kernel<<<dim3(L_/128, B_), 256, LA_SMEM>>>(lcb, qb, kb, vb, i, dil);
        attn_fused_kernel<<<dim3(L_/64, B_), 256>>>(dil);
        ffn_kernel<<<dim3(L_/64, B_), 256>>>(f1b, f2b, i);
    }
    conv_out_kernel<<<dim3(L_/64, B_), 256>>>(cow, cob, (float*)d_out);
}

// round 7
// speedup vs baseline: 4.1834x; 1.0294x over previous
#include <cuda_runtime.h>
#include <cuda_bf16.h>
#include <cuda_fp16.h>
#include <math.h>
#include <stdint.h>

#define B_  2
#define L_  8192
#define D_  64
#define CR_ 2048
#define NC_ 48
#define TE_ 512
#define NL_ 8
#define M_  1024        // NL*2*D rows of the batched cross GEMM
#define NCOL_ (B_*L_)   // 16384 columns

// ---------------- scratch (device globals; no allocation allowed) ----------------
__device__ __half g_Wp[(size_t)M_*CR_];        // A = W fp16, K-major
__device__ __half g_Xp[(size_t)NCOL_*CR_];     // B = x fp16, K-major per col
__device__ float g_QKC [(size_t)M_*NCOL_];     // cross-projection results [m][n*L+l]
__device__ __half g_AW[NL_*8*64*64];     // layer weights fp16 hi [i][slot][m][k]; slots: taps{0,1,3,4,2},q,k,v
__device__ __half g_fh[B_*D_*L_];        // fra fp16 hi
__device__ __half g_fl[B_*D_*L_];        // fra fp16 lo
__device__ float g_f1T [NL_*64*64];
__device__ float g_f2T [NL_*64*64];
__device__ float g_fra [B_*D_*L_];
__device__ __half g_xq  [B_*D_*L_];
__device__ __half g_xk  [B_*D_*L_];
__device__ __half g_xv  [B_*D_*L_];
__device__ __half g_out1[B_*D_*L_];
__device__ float g_y   [B_*D_*L_];
__device__ float g_part[B_*D_*128*2];
__device__ float g_tproj[B_*D_];
__device__ float g_t1[B_*TE_];
__device__ float g_t2[B_*TE_];

__device__ __forceinline__ uint32_t smem_u32(const void* p) {
    return (uint32_t)__cvta_generic_to_shared(p);
}
__device__ __forceinline__ void ldsm_x4(uint32_t* r, uint32_t addr) {
    asm volatile("ldmatrix.sync.aligned.m8n8.x4.shared.b16 {%0,%1,%2,%3}, [%4];"
                 : "=r"(r[0]), "=r"(r[1]), "=r"(r[2]), "=r"(r[3]) : "r"(addr));
}
__device__ __forceinline__ void ldsm_x4t(uint32_t* r, uint32_t addr) {
    asm volatile("ldmatrix.sync.aligned.m8n8.x4.trans.shared.b16 {%0,%1,%2,%3}, [%4];"
                 : "=r"(r[0]), "=r"(r[1]), "=r"(r[2]), "=r"(r[3]) : "r"(addr));
}
__device__ __forceinline__ void mma_fp16(float c[4], uint32_t a0, uint32_t a1, uint32_t a2,
                                         uint32_t a3, uint32_t b0, uint32_t b1) {
    asm volatile("mma.sync.aligned.m16n8k16.row.col.f32.f16.f16.f32 "
                 "{%0,%1,%2,%3}, {%4,%5,%6,%7}, {%8,%9}, {%0,%1,%2,%3};"
                 : "+f"(c[0]), "+f"(c[1]), "+f"(c[2]), "+f"(c[3])
                 : "r"(a0), "r"(a1), "r"(a2), "r"(a3), "r"(b0), "r"(b1));
}
__device__ __forceinline__ void cp16(uint32_t saddr, const void* gptr) {
    asm volatile("cp.async.cg.shared.global [%0], [%1], 16;" :: "r"(saddr), "l"(gptr));
}
#define CP_COMMIT() asm volatile("cp.async.commit_group;")
#define CP_WAIT1() asm volatile("cp.async.wait_group 1;")
#define CP_WAIT0() asm volatile("cp.async.wait_group 0;")

// ================== fp16 HMMA cross GEMM ==================
#define GM_BM 128
#define GM_BN 128
#define GM_BK 32
#define GM_NT (CR_/GM_BK)   // 64
#define APAD 40

__global__ void __launch_bounds__(256) gemm_fp16_kernel() {
    __shared__ __half As[2][GM_BM * APAD];
    __shared__ __half Bs[2][GM_BN * APAD];
    const int tid = threadIdx.x, lane = tid & 31, wid = tid >> 5;
    const int wm = wid >> 2, wn = wid & 3;
    const int m0 = blockIdx.x * GM_BM;
    const int col0 = blockIdx.y * GM_BN;
    const int ldr = tid >> 1, ldc = (tid & 1) * 2;

    float acc[4][4][4];
#pragma unroll
    for (int i = 0; i < 4; ++i)
#pragma unroll
        for (int j = 0; j < 4; ++j)
#pragma unroll
            for (int q = 0; q < 4; ++q) acc[i][j][q] = 0.f;

    const int lrow = lane & 15, lhalf = lane >> 4;

    auto load_tile = [&](int kt, int buf) {
        const size_t gk = (size_t)kt * GM_BK;
#pragma unroll
        for (int s = 0; s < 2; ++s) {
            int c = ldc + s;
            cp16(smem_u32(&As[buf][ldr * APAD + c * 8]),
                 g_Wp + (size_t)(m0 + ldr) * CR_ + gk + c * 8);
            cp16(smem_u32(&Bs[buf][ldr * APAD + c * 8]),
                 g_Xp + (size_t)(col0 + ldr) * CR_ + gk + c * 8);
        }
        CP_COMMIT();
    };

    load_tile(0, 0);
    for (int kt = 0; kt < GM_NT; ++kt) {
        const int cur = kt & 1;
        if (kt + 1 < GM_NT) { load_tile(kt + 1, cur ^ 1); CP_WAIT1(); }
        else CP_WAIT0();
        __syncthreads();
#pragma unroll
        for (int kk2 = 0; kk2 < 2; ++kk2) {
            uint32_t a[4][4];
#pragma unroll
            for (int mt = 0; mt < 4; ++mt)
                ldsm_x4(a[mt], smem_u32(&As[cur][(wm*64 + mt*16 + lrow) * APAD + kk2*16 + lhalf*8]));
            uint32_t b[4][2];
#pragma unroll
            for (int nb2 = 0; nb2 < 2; ++nb2) {
                uint32_t r[4];
                ldsm_x4(r, smem_u32(&Bs[cur][(wn*32 + nb2*16 + lrow) * APAD + kk2*16 + lhalf*8]));
                b[nb2*2 + 0][0] = r[0]; b[nb2*2 + 0][1] = r[2];
                b[nb2*2 + 1][0] = r[1]; b[nb2*2 + 1][1] = r[3];
            }
#pragma unroll
            for (int mt = 0; mt < 4; ++mt)
#pragma unroll
                for (int nt = 0; nt < 4; ++nt)
                    mma_fp16(acc[mt][nt], a[mt][0], a[mt][1], a[mt][2], a[mt][3],
                             b[nt][0], b[nt][1]);
        }
        __syncthreads();
    }
    const int grp = lane >> 2, qd = (lane & 3) * 2;
#pragma unroll
    for (int mt = 0; mt < 4; ++mt)
#pragma unroll
        for (int nt = 0; nt < 4; ++nt) {
            int m = m0 + wm*64 + mt*16 + grp;
            int n = col0 + wn*32 + nt*8 + qd;
            *(float2*)(g_QKC + (size_t)m * NCOL_ + n)       = make_float2(acc[mt][nt][0], acc[mt][nt][1]);
            *(float2*)(g_QKC + (size_t)(m + 8) * NCOL_ + n) = make_float2(acc[mt][nt][2], acc[mt][nt][3]);
        }
}

// ---------------- packing kernels ----------------
__global__ void pack_wp_kernel(const float* __restrict__ qw, const float* __restrict__ kw) {
    int idx = blockIdx.x * 256 + threadIdx.x;
    int m = idx >> 11, c = idx & 2047;
    int i = m >> 7, r = m & 127, s = r >> 6, d = r & 63;
    const float* src = s ? kw : qw;
    g_Wp[(size_t)m * CR_ + c] = __float2half(src[(i*64 + d)*2112 + 64 + c]);
}

__global__ void __launch_bounds__(256) xt_kernel(const float* __restrict__ x) {
    __shared__ float ts[32][33];
    const int lb = blockIdx.x * 32, kb = blockIdx.y * 32, n = blockIdx.z;
    const int tx = threadIdx.x & 31, ty = threadIdx.x >> 5;
#pragma unroll
    for (int r = ty; r < 32; r += 8)
        ts[r][tx] = x[((size_t)n * CR_ + kb + r) * L_ + lb + tx];
    __syncthreads();
#pragma unroll
    for (int r = ty; r < 32; r += 8)
        g_Xp[(size_t)(n * L_ + lb + r) * CR_ + kb + tx] = __float2half(ts[tx][r]);
}

// pack per-layer weights into fp16 (hi only) A-layout [m][k]
__global__ void pack_aw_kernel(const float* __restrict__ convw, const float* __restrict__ qw,
                               const float* __restrict__ kw,   const float* __restrict__ vw,
                               const float* __restrict__ f1w,  const float* __restrict__ f2w) {
    int idx = blockIdx.x * 256 + threadIdx.x;     // NL_*8*4096
    if (idx < NL_*8*64*64) {
        int c = idx & 63, m = (idx >> 6) & 63, s = (idx >> 12) & 7, i = idx >> 15;
        const int tapmap[5] = {0, 1, 3, 4, 2};
        float v;
        if (s < 5)      v = convw[((i*64 + m)*64 + c)*5 + tapmap[s]];
        else if (s == 5) v = qw[(i*64 + m)*2112 + c];
        else if (s == 6) v = kw[(i*64 + m)*2112 + c];
        else             v = vw[(i*64 + m)*64 + c];
        g_AW[(size_t)(i*8 + s) * 4096 + m*64 + c] = __float2half(v);
    }
    if (idx < NL_*64*64) {
        int d = idx & 63, c = (idx >> 6) & 63, i = idx >> 12;
        g_f1T[idx] = f1w[(i*64 + d)*64 + c];
        g_f2T[idx] = f2w[(i*64 + d)*64 + c];
    }
}

// ---------------- timestep embedding (coalesced, 3 stages) ----------------
__global__ void temb1_kernel(const int* __restrict__ t, const float* __restrict__ w1,
                             const float* __restrict__ b1) {
    __shared__ float se[TE_];
    const int n = blockIdx.y, tid = threadIdx.x;
    const float tv = (float)t[n];
    if (tid < 256) {
        float f = expf((float)tid * (-logf(10000.0f) / 255.0f));
        se[tid] = sinf(tv * f);
        se[tid + 256] = cosf(tv * f);
    }
    __syncthreads();
    const int w = tid >> 5, lane = tid & 31;
    const int o = blockIdx.x * 8 + w;
    const float* wr = w1 + (size_t)o * TE_;
    float s = 0.f;
    for (int c = lane; c < TE_; c += 32) s += se[c] * wr[c];
#pragma unroll
    for (int off = 16; off; off >>= 1) s += __shfl_xor_sync(0xffffffffu, s, off);
    if (!lane) { s += b1[o]; g_t1[n*TE_ + o] = s / (1.f + expf(-s)); }
}
__global__ void temb2_kernel(const float* __restrict__ w2, const float* __restrict__ b2) {
    __shared__ float se[TE_];
    const int n = blockIdx.y, tid = threadIdx.x;
    se[tid] = g_t1[n*TE_ + tid];
    se[tid + 256] = g_t1[n*TE_ + tid + 256];
    __syncthreads();
    const int w = tid >> 5, lane = tid & 31;
    const int o = blockIdx.x * 8 + w;
    const float* wr = w2 + (size_t)o * TE_;
    float s = 0.f;
    for (int c = lane; c < TE_; c += 32) s += se[c] * wr[c];
#pragma unroll
    for (int off = 16; off; off >>= 1) s += __shfl_xor_sync(0xffffffffu, s, off);
    if (!lane) g_t2[n*TE_ + o] = s + b2[o];
}
__global__ void tembp_kernel(const float* __restrict__ wp, const float* __restrict__ bp) {
    __shared__ float se[TE_];
    const int n = blockIdx.y, tid = threadIdx.x;
    {
        float v0 = g_t2[n*TE_ + tid], v1 = g_t2[n*TE_ + tid + 256];
        se[tid]       = v0 / (1.f + expf(-v0));
        se[tid + 256] = v1 / (1.f + expf(-v1));
    }
    __syncthreads();
    const int w = tid >> 5, lane = tid & 31;
    const int o = blockIdx.x * 8 + w;
    const float* wr = wp + (size_t)o * TE_;
    float s = 0.f;
    for (int c = lane; c < TE_; c += 32) s += se[c] * wr[c];
#pragma unroll
    for (int off = 16; off; off >>= 1) s += __shfl_xor_sync(0xffffffffu, s, off);
    if (!lane) g_tproj[n*D_ + o] = s + bp[o];
}

// ---------------- conv_in (1x1, 48->64) + time proj; writes fp32 + fp16 hi/lo ------
__global__ void __launch_bounds__(256) conv_in_kernel(const float* __restrict__ event,
                                                      const float* __restrict__ w,
                                                      const float* __restrict__ b) {
    __shared__ float Et[NC_][64];
    __shared__ float Wt[NC_][64];
    const int n = blockIdx.y, l0 = blockIdx.x * 64;
    const int tid = threadIdx.x, ty4 = (tid >> 4) << 2, tx4 = (tid & 15) << 2;
    for (int e = tid; e < NC_*64; e += 256) {
        int c = e >> 6, tt = e & 63;
        Et[c][tt] = event[(n*NC_ + c)*L_ + l0 + tt];
        Wt[c][tt] = w[tt*NC_ + c];
    }
    __syncthreads();
    float acc[4][4] = {};
#pragma unroll
    for (int c = 0; c < NC_; ++c) {
        const float4 a = *(const float4*)(&Wt[c][ty4]);
        const float4 x4 = *(const float4*)(&Et[c][tx4]);
        acc[0][0]+=a.x*x4.x; acc[0][1]+=a.x*x4.y; acc[0][2]+=a.x*x4.z; acc[0][3]+=a.x*x4.w;
        acc[1][0]+=a.y*x4.x; acc[1][1]+=a.y*x4.y; acc[1][2]+=a.y*x4.z; acc[1][3]+=a.y*x4.w;
        acc[2][0]+=a.z*x4.x; acc[2][1]+=a.z*x4.y; acc[2][2]+=a.z*x4.z; acc[2][3]+=a.z*x4.w;
        acc[3][0]+=a.w*x4.x; acc[3][1]+=a.w*x4.y; acc[3][2]+=a.w*x4.z; acc[3][3]+=a.w*x4.w;
    }
#pragma unroll
    for (int i = 0; i < 4; ++i)
#pragma unroll
        for (int j = 0; j < 4; ++j) {
            int d = ty4 + i, l = l0 + tx4 + j;
            size_t o = (size_t)(n*D_ + d)*L_ + l;
            float v = acc[i][j] + b[d] + g_tproj[n*D_ + d];
            g_fra[o] = v;
            __half h = __float2half(v);
            g_fh[o] = h;
            g_fl[o] = __float2half(v - __half2float(h));
        }
}

// ================== per-layer HMMA: conv(5 taps) + q/k/v (2-pass: Ah*Bh + Ah*Bl) ====
#define LA_SMEM (16384 + 65536)

__device__ __forceinline__ void mm64(float acc[2][4][4], uint32_t Ah,
                                     uint32_t Bh, uint32_t Bl, int wm, int wn, int lane) {
    const int lrow = lane & 15, lhalf = lane >> 4;
    const int bk = (lane & 7) + (((lane >> 3) & 1) << 3);
    const int bn8 = (lane >> 4) << 3;
#pragma unroll
    for (int pass = 0; pass < 2; ++pass) {
        uint32_t Bb = pass ? Bl : Bh;
#pragma unroll
        for (int k0 = 0; k0 < 4; ++k0) {
            uint32_t a[2][4];
#pragma unroll
            for (int mt = 0; mt < 2; ++mt) {
                int m = wm*32 + mt*16 + lrow;
                int ch = (k0*2 + lhalf) ^ (m & 7);
                ldsm_x4(a[mt], Ah + m*128 + ch*16);
            }
            uint32_t b[4][2];
#pragma unroll
            for (int ng = 0; ng < 2; ++ng) {
                int k = k0*16 + bk;
                int n = wn*32 + ng*16 + bn8;
                int ch = (n >> 3) ^ (k & 7);
                uint32_t r[4];
                ldsm_x4t(r, Bb + k*256 + ch*16);
                b[ng*2 + 0][0] = r[0]; b[ng*2 + 0][1] = r[1];
                b[ng*2 + 1][0] = r[2]; b[ng*2 + 1][1] = r[3];
            }
#pragma unroll
            for (int mt = 0; mt < 2; ++mt)
#pragma unroll
                for (int nt = 0; nt < 4; ++nt)
                    mma_fp16(acc[mt][nt], a[mt][0], a[mt][1], a[mt][2], a[mt][3],
                             b[nt][0], b[nt][1]);
        }
    }
}

__global__ void __launch_bounds__(256) layer_mm_kernel(const float* __restrict__ convb,
                                                       const float* __restrict__ qb,
                                                       const float* __restrict__ kb,
                                                       const float* __restrict__ vb,
                                                       int layer, int dil) {
    extern __shared__ char dsm[];
    char* smA = dsm;            // 2 x 8KB (hi only)
    char* smB = dsm + 16384;    // 2 x 32KB (hi 16KB + lo 16KB)
    const int tid = threadIdx.x, lane = tid & 31, wid = tid >> 5;
    const int wm = wid >> 2, wn = wid & 3;
    const int l0 = blockIdx.x * 128, nb = blockIdx.y;
    const __half* fh = g_fh + (size_t)nb * D_ * L_;
    const __half* fl = g_fl + (size_t)nb * D_ * L_;
    const float* fb = g_fra + (size_t)nb * D_ * L_;

    auto loadA = [&](int slot, int buf) {
        const __half* src = g_AW + (size_t)(layer*8 + slot) * 4096;
        char* dh = smA + buf * 8192;
#pragma unroll
        for (int e = tid; e < 512; e += 256) {
            int m = e >> 3, c = e & 7;
            int off = m*128 + ((c ^ (m & 7)) << 4);
            cp16(smem_u32(dh + off), src + m*64 + c*8);
        }
    };
    auto loadB = [&](int shift, int buf) {
        char* dh = smB + buf * 32768;
        char* dl = dh + 16384;
        if ((shift & 7) == 0) {
#pragma unroll
            for (int e = tid; e < 1024; e += 256) {
                int k = e >> 4, c = e & 15;
                int gl = l0 + c*8 + shift;
                int off = k*256 + ((c ^ (k & 7)) << 4);
                if (gl >= 0 && gl + 8 <= L_) {
                    cp16(smem_u32(dh + off), fh + (size_t)k * L_ + gl);
                    cp16(smem_u32(dl + off), fl + (size_t)k * L_ + gl);
                } else {
                    __half* ph = (__half*)(dh + off);
                    __half* pl = (__half*)(dl + off);
#pragma unroll
                    for (int u = 0; u < 8; ++u) {
                        int l = gl + u;
                        bool ok = ((unsigned)l < (unsigned)L_);
                        ph[u] = ok ? fh[(size_t)k * L_ + l] : __half(0.f);
                        pl[u] = ok ? fl[(size_t)k * L_ + l] : __half(0.f);
                    }
                }
            }
        } else {
            // unaligned shift: read fp32 fra once, split in-register
#pragma unroll
            for (int e = tid; e < 1024; e += 256) {
                int k = e >> 4, c = e & 15;
                int gl = l0 + c*8 + shift;
                int off = k*256 + ((c ^ (k & 7)) << 4);
                const float* src = fb + (size_t)k * L_;
                __half hb[8], lb[8];
#pragma unroll
                for (int u = 0; u < 8; ++u) {
                    int l = gl + u;
                    float v = ((unsigned)l < (unsigned)L_) ? __ldg(src + l) : 0.f;
                    __half h = __float2half(v);
                    hb[u] = h;
                    lb[u] = __float2half(v - __half2float(h));
                }
                *(uint4*)(dh + off) = *(uint4*)hb;
                *(uint4*)(dl + off) = *(uint4*)lb;
            }
        }
    };

    const int tapshift[5] = {-2*dil, -dil, dil, 2*dil, 0};

    float acc[2][4][4];
#pragma unroll
    for (int i = 0; i < 2; ++i)
#pragma unroll
        for (int j = 0; j < 4; ++j)
#pragma unroll
            for (int q = 0; q < 4; ++q) acc[i][j][q] = 0.f;

    loadB(tapshift[0], 0);
    loadA(0, 0);
    CP_COMMIT();

    const int grp = lane >> 2, qd = (lane & 3) * 2;
    auto epilogue = [&](__half* dst, const float* bias, const float* qkc) {
#pragma unroll
        for (int mt = 0; mt < 2; ++mt)
#pragma unroll
            for (int nt = 0; nt < 4; ++nt) {
                int m = wm*32 + mt*16 + grp;
                int n = wn*32 + nt*8 + qd;
                float v0 = acc[mt][nt][0] + bias[m];
                float v1 = acc[mt][nt][1] + bias[m];
                float v2 = acc[mt][nt][2] + bias[m + 8];
                float v3 = acc[mt][nt][3] + bias[m + 8];
                if (qkc) {
                    float2 e0 = *(const float2*)(qkc + (size_t)m * NCOL_ + n);
                    float2 e1 = *(const float2*)(qkc + (size_t)(m + 8) * NCOL_ + n);
                    v0 += e0.x; v1 += e0.y; v2 += e1.x; v3 += e1.y;
                }
                *(__half2*)(dst + (size_t)(nb*D_ + m) * L_ + l0 + n)     = __floats2half2_rn(v0, v1);
                *(__half2*)(dst + (size_t)(nb*D_ + m + 8) * L_ + l0 + n) = __floats2half2_rn(v2, v3);
                acc[mt][nt][0] = acc[mt][nt][1] = acc[mt][nt][2] = acc[mt][nt][3] = 0.f;
            }
    };

    for (int it = 0; it < 8; ++it) {
        __syncthreads();
        if (it < 7) {
            if (it < 4) loadB(tapshift[it + 1], (it + 1) & 1);
            loadA(it + 1, (it + 1) & 1);
            CP_COMMIT();
            CP_WAIT1();
        } else {
            CP_WAIT0();
        }
        __syncthreads();
        const int abuf = it & 1;
        const int bbuf = (it < 5) ? (it & 1) : 0;
        uint32_t Ah = smem_u32(smA + abuf * 8192);
        uint32_t Bh = smem_u32(smB + bbuf * 32768);
        uint32_t Bl = Bh + 16384;
        mm64(acc, Ah, Bh, Bl, wm, wn, lane);
        if (it == 4) {
            epilogue(g_out1, convb + layer*64, nullptr);
        } else if (it == 5) {
            epilogue(g_xq, qb + layer*64, g_QKC + (size_t)(layer*2)*64*NCOL_ + nb*L_ + l0);
        } else if (it == 6) {
            epilogue(g_xk, kb + layer*64, g_QKC + (size_t)(layer*2 + 1)*64*NCOL_ + nb*L_ + l0);
        } else if (it == 7) {
            epilogue(g_xv, vb + layer*64, nullptr);
        }
    }
}

// ---------------- fused attention: scores + softmax + apply + IN partials ----------
__global__ void __launch_bounds__(256) attn_fused_kernel(int dil) {
    __shared__ float satt[5][64];
    const int n = blockIdx.y, l0 = blockIdx.x * 64;
    const int tid = threadIdx.x;

    // ---- stage A: scores + softmax (4 lanes per l) ----
    {
        const int g = tid & 3, l = tid >> 2;          // l 0..63
        const int lg = l0 + l;
        const __half* qp = g_xq + (size_t)n * D_ * L_ + lg;
        const __half* kp = g_xk + (size_t)n * D_ * L_;
        bool v[5]; int pc[5];
#pragma unroll
        for (int j = 0; j < 5; ++j) {
            int p = lg + (j - 2) * dil;
            v[j] = ((unsigned)p < (unsigned)L_);
            pc[j] = v[j] ? p : lg;
        }
        float dot[5] = {};
#pragma unroll 4
        for (int c = g; c < 64; c += 4) {
            float qv = __half2float(__ldg(qp + c * L_));
#pragma unroll
            for (int j = 0; j < 5; ++j)
                dot[j] += qv * __half2float(__ldg(kp + c*L_ + pc[j]));
        }
#pragma unroll
        for (int j = 0; j < 5; ++j) {
            dot[j] += __shfl_xor_sync(0xffffffffu, dot[j], 1);
            dot[j] += __shfl_xor_sync(0xffffffffu, dot[j], 2);
        }
        const float LVALID = logf(1.0f + 1e-6f);
        const float LINV   = logf(1e-6f);
        float lg5[5];
#pragma unroll
        for (int j = 0; j < 5; ++j) lg5[j] = v[j] ? dot[j]*0.125f + LVALID : LINV;
        float mx = lg5[0];
#pragma unroll
        for (int j = 1; j < 5; ++j) mx = fmaxf(mx, lg5[j]);
        float e[5], s = 0.f;
#pragma unroll
        for (int j = 0; j < 5; ++j) { e[j] = expf(lg5[j] - mx); s += e[j]; }
        float inv = 1.f / s;
        if (g == 0) {
#pragma unroll
            for (int j = 0; j < 5; ++j) satt[j][l] = v[j] ? e[j]*inv : 0.f;
        }
    }
    __syncthreads();

    // ---- stage B: r = att @ v_win, y = out1 + r, per-channel partial stats ----
    const int tx = tid & 15, ty = tid >> 4;
    const int c0 = ty * 4, lx = tx * 4;
    float s1[4] = {}, s2[4] = {};
#pragma unroll
    for (int ci = 0; ci < 4; ++ci) {
        int c = c0 + ci;
        const __half* vp = g_xv + (size_t)(n*D_ + c) * L_;
        const __half* op = g_out1 + (size_t)(n*D_ + c) * L_ + l0;
        float* yp = g_y + (size_t)(n*D_ + c) * L_ + l0;
        float yv4[4];
#pragma unroll
        for (int lj = 0; lj < 4; ++lj) {
            int l = lx + lj, lgl = l0 + l;
            float r = 0.f;
#pragma unroll
            for (int j = 0; j < 5; ++j) {
                int pp = lgl + (j - 2) * dil;
                if ((unsigned)pp < (unsigned)L_)
                    r += satt[j][l] * __half2float(__ldg(vp + pp));
            }
            float yv = __half2float(op[l]) + r;
            yv4[lj] = yv;
            s1[ci] += yv; s2[ci] += yv * yv;
        }
        *(float4*)(yp + lx) = make_float4(yv4[0], yv4[1], yv4[2], yv4[3]);
    }
#pragma unroll
    for (int off = 8; off; off >>= 1)
#pragma unroll
        for (int ci = 0; ci < 4; ++ci) {
            s1[ci] += __shfl_xor_sync(0xffffffffu, s1[ci], off);
            s2[ci] += __shfl_xor_sync(0xffffffffu, s2[ci], off);
        }
    if (tx == 0) {
#pragma unroll
        for (int ci = 0; ci < 4; ++ci) {
            g_part[((n*D_ + c0 + ci)*128 + blockIdx.x)*2 + 0] = s1[ci];
            g_part[((n*D_ + c0 + ci)*128 + blockIdx.x)*2 + 1] = s2[ci];
        }
    }
}

// ---------------- shared-mem 64x64 micro-matmul (SIMT, for FFN) ----------------
__device__ __forceinline__ void mm_16x16(const float (*Ws)[64], const float (*Xs)[64],
                                         float acc[4][4], int ty4, int tx4) {
#pragma unroll 16
    for (int c = 0; c < 64; ++c) {
        const float4 a = *(const float4*)(&Ws[c][ty4]);
        const float4 b = *(const float4*)(&Xs[c][tx4]);
        acc[0][0] += a.x*b.x; acc[0][1] += a.x*b.y; acc[0][2] += a.x*b.z; acc[0][3] += a.x*b.w;
        acc[1][0] += a.y*b.x; acc[1][1] += a.y*b.y; acc[1][2] += a.y*b.z; acc[1][3] += a.y*b.w;
        acc[2][0] += a.z*b.x; acc[2][1] += a.z*b.y; acc[2][2] += a.z*b.z; acc[2][3] += a.z*b.w;
        acc[3][0] += a.w*b.x; acc[3][1] += a.w*b.y; acc[3][2] += a.w*b.z; acc[3][3] += a.w*b.w;
    }
}

// ---------------- instance-norm stats + FFN + residual; writes fp32 + fp16 ---------
__global__ void __launch_bounds__(256) ffn_kernel(const float* __restrict__ f1b,
                                                  const float* __restrict__ f2b,
                                                  int layer) {
    __shared__ float Xs[64][64];
    __shared__ float Ws[64][64];
    __shared__ float sms[64], srs[64];
    const int n = blockIdx.y, l0 = blockIdx.x * 64;
    const int tid = threadIdx.x, ty4 = (tid >> 4) << 2, tx4 = (tid & 15) << 2;
    if (tid < 64) {
        float s = 0.f, s2 = 0.f;
        for (int bq = 0; bq < 128; ++bq) {
            s  += g_part[((n*D_ + tid)*128 + bq)*2 + 0];
            s2 += g_part[((n*D_ + tid)*128 + bq)*2 + 1];
        }
        float mean = s / (float)L_;
        float var = s2 / (float)L_ - mean*mean;
        sms[tid] = mean;
        srs[tid] = rsqrtf(var + 1e-5f);
    }
    __syncthreads();
    {
        const float* wsrc = g_f1T + (size_t)layer * 4096;
        for (int e = tid; e < 4096; e += 256) {
            int c = e >> 6, tt = e & 63;
            Xs[c][tt] = (g_y[(size_t)(n*D_ + c)*L_ + l0 + tt] - sms[c]) * srs[c];
            ((float*)Ws)[e] = wsrc[e];
        }
    }
    __syncthreads();
    float acc[4][4] = {};
    mm_16x16(Ws, Xs, acc, ty4, tx4);
    __syncthreads();
#pragma unroll
    for (int i = 0; i < 4; ++i)
#pragma unroll
        for (int j = 0; j < 4; ++j)
            Xs[ty4 + i][tx4 + j] = fmaxf(acc[i][j] + f1b[layer*64 + ty4 + i], 0.f);
    {
        const float* wsrc = g_f2T + (size_t)layer * 4096;
        for (int e = tid; e < 4096; e += 256) ((float*)Ws)[e] = wsrc[e];
    }
    __syncthreads();
    float a2[4][4] = {};
    mm_16x16(Ws, Xs, a2, ty4, tx4);
#pragma unroll
    for (int i = 0; i < 4; ++i)
#pragma unroll
        for (int j = 0; j < 4; ++j) {
            int d = ty4 + i, l = l0 + tx4 + j;
            size_t o = (size_t)(n*D_ + d)*L_ + l;
            float nv = g_fra[o] + a2[i][j] + f2b[layer*64 + d];
            g_fra[o] = nv;
            __half h = __float2half(nv);
            g_fh[o] = h;
            g_fl[o] = __float2half(nv - __half2float(h));
        }
}

// ---------------- conv_out (1x1, 64->48) ----------------
__global__ void __launch_bounds__(256) conv_out_kernel(const float* __restrict__ w,
                                                       const float* __restrict__ b,
                                                       float* __restrict__ out) {
    __shared__ float Xs[64][64];
    __shared__ float Wt[64][NC_];
    const int n = blockIdx.y, l0 = blockIdx.x * 64;
    const int tid = threadIdx.x, ty = tid >> 4, tx = tid & 15;
    for (int e = tid; e < 4096; e += 256) {
        int c = e >> 6, tt = e & 63;
        Xs[c][tt] = g_fra[(size_t)(n*D_ + c)*L_ + l0 + tt];
    }
    for (int e = tid; e < 64*NC_; e += 256) {
        int c = e / NC_, o = e % NC_;
        Wt[c][o] = w[o*64 + c];
    }
    __syncthreads();
    if (ty < 12) {
        const int ty4 = ty*4, tx4 = tx*4;
        float acc[4][4] = {};
#pragma unroll 16
        for (int c = 0; c < 64; ++c) {
            const float4 a = *(const float4*)(&Wt[c][ty4]);
            const float4 x4 = *(const float4*)(&Xs[c][tx4]);
            acc[0][0]+=a.x*x4.x; acc[0][1]+=a.x*x4.y; acc[0][2]+=a.x*x4.z; acc[0][3]+=a.x*x4.w;
            acc[1][0]+=a.y*x4.x; acc[1][1]+=a.y*x4.y; acc[1][2]+=a.y*x4.z; acc[1][3]+=a.y*x4.w;
            acc[2][0]+=a.z*x4.x; acc[2][1]+=a.z*x4.y; acc[2][2]+=a.z*x4.z; acc[2][3]+=a.z*x4.w;
            acc[3][0]+=a.w*x4.x; acc[3][1]+=a.w*x4.y; acc[3][2]+=a.w*x4.z; acc[3][3]+=a.w*x4.w;
        }
#pragma unroll
        for (int i = 0; i < 4; ++i)
#pragma unroll
            for (int j = 0; j < 4; ++j) {
                int o = ty4 + i, l = l0 + tx4 + j;
                out[(size_t)(n*NC_ + o)*L_ + l] = acc[i][j] + b[o];
            }
    }
}

// ---------------- host side ----------------
extern "C" void kernel_launch(void* const* d_in, const int* in_sizes, int n_in,
                              void* d_out, int out_size) {
    (void)in_sizes; (void)n_in; (void)out_size;
    const float* x     = (const float*)d_in[0];
    const int*   t     = (const int*)  d_in[1];
    const float* event = (const float*)d_in[2];
    const float* tw1   = (const float*)d_in[3];
    const float* tb1   = (const float*)d_in[4];
    const float* tw2   = (const float*)d_in[5];
    const float* tb2   = (const float*)d_in[6];
    const float* tpw   = (const float*)d_in[7];
    const float* tpb   = (const float*)d_in[8];
    const float* ciw   = (const float*)d_in[9];
    const float* cib   = (const float*)d_in[10];
    const float* cow   = (const float*)d_in[11];
    const float* cob   = (const float*)d_in[12];
    const float* lcw   = (const float*)d_in[13];
    const float* lcb   = (const float*)d_in[14];
    const float* qw    = (const float*)d_in[15];
    const float* qb    = (const float*)d_in[16];
    const float* kw    = (const float*)d_in[17];
    const float* kb    = (const float*)d_in[18];
    const float* vw    = (const float*)d_in[19];
    const float* vb    = (const float*)d_in[20];
    const float* f1w   = (const float*)d_in[21];
    const float* f1b   = (const float*)d_in[22];
    const float* f2w   = (const float*)d_in[23];
    const float* f2b   = (const float*)d_in[24];

    cudaFuncSetAttribute(layer_mm_kernel, cudaFuncAttributeMaxDynamicSharedMemorySize, LA_SMEM);

    pack_wp_kernel<<<(M_*CR_)/256, 256>>>(qw, kw);
    xt_kernel<<<dim3(L_/32, CR_/32, B_), 256>>>(x);
    pack_aw_kernel<<<(NL_*8*64*64)/256, 256>>>(lcw, qw, kw, vw, f1w, f2w);
    temb1_kernel<<<dim3(64, B_), 256>>>(t, tw1, tb1);
    temb2_kernel<<<dim3(64, B_), 256>>>(tw2, tb2);
    gemm_fp16_kernel<<<dim3(M_/GM_BM, NCOL_/GM_BN), 256>>>();
    tembp_kernel<<<dim3(8, B_), 256>>>(tpw, tpb);
    conv_in_kernel<<<dim3(L_/64, B_), 256>>>(event, ciw, cib);

    for (int i = 0; i < NL_; ++i) {
        int dil = 1 << i;
        layer_mm_kernel<<<dim3(L_/128, B_), 256, LA_SMEM>>>(lcb, qb, kb, vb, i, dil);
        attn_fused_kernel<<<dim3(L_/64, B_), 256>>>(dil);
        ffn_kernel<<<dim3(L_/64, B_), 256>>>(f1b, f2b, i);
    }
    conv_out_kernel<<<dim3(L_/64, B_), 256>>>(cow, cob, (float*)d_out);
}

// round 8
// speedup vs baseline: 4.4818x; 1.0713x over previous
#include <cuda_runtime.h>
#include <cuda_bf16.h>
#include <cuda_fp16.h>
#include <math.h>
#include <stdint.h>

#define B_  2
#define L_  8192
#define D_  64
#define CR_ 2048
#define NC_ 48
#define TE_ 512
#define NL_ 8
#define M_  1024        // NL*2*D rows of the batched cross GEMM
#define NCOL_ (B_*L_)   // 16384 columns

// ---------------- scratch (device globals; no allocation allowed) ----------------
__device__ __half g_Wp[(size_t)M_*CR_];        // A = W fp16, K-major
__device__ __half g_Xp[(size_t)NCOL_*CR_];     // B = x fp16, K-major per col
__device__ __half g_QKCh[(size_t)M_*NCOL_];    // cross-projection results fp16 [m][n*L+l]
__device__ __half g_AW[NL_*8*64*64];     // layer weights fp16 [i][slot][m][k]; slots: taps{0,1,3,4,2},q,k,v
__device__ __half g_fh[B_*D_*L_];        // fra fp16 hi
__device__ __half g_fl[B_*D_*L_];        // fra fp16 lo
__device__ float g_f1T [NL_*64*64];
__device__ float g_f2T [NL_*64*64];
__device__ float g_fra [B_*D_*L_];
__device__ __half g_xq  [B_*D_*L_];
__device__ __half g_xk  [B_*D_*L_];
__device__ __half g_xv  [B_*D_*L_];
__device__ __half g_out1[B_*D_*L_];
__device__ float g_y   [B_*D_*L_];
__device__ float g_part[B_*D_*128*2];
__device__ float g_tproj[B_*D_];
__device__ float g_t1[B_*TE_];
__device__ float g_t2[B_*TE_];

__device__ __forceinline__ uint32_t smem_u32(const void* p) {
    return (uint32_t)__cvta_generic_to_shared(p);
}
__device__ __forceinline__ void ldsm_x4(uint32_t* r, uint32_t addr) {
    asm volatile("ldmatrix.sync.aligned.m8n8.x4.shared.b16 {%0,%1,%2,%3}, [%4];"
                 : "=r"(r[0]), "=r"(r[1]), "=r"(r[2]), "=r"(r[3]) : "r"(addr));
}
__device__ __forceinline__ void ldsm_x4t(uint32_t* r, uint32_t addr) {
    asm volatile("ldmatrix.sync.aligned.m8n8.x4.trans.shared.b16 {%0,%1,%2,%3}, [%4];"
                 : "=r"(r[0]), "=r"(r[1]), "=r"(r[2]), "=r"(r[3]) : "r"(addr));
}
__device__ __forceinline__ void mma_fp16(float c[4], uint32_t a0, uint32_t a1, uint32_t a2,
                                         uint32_t a3, uint32_t b0, uint32_t b1) {
    asm volatile("mma.sync.aligned.m16n8k16.row.col.f32.f16.f16.f32 "
                 "{%0,%1,%2,%3}, {%4,%5,%6,%7}, {%8,%9}, {%0,%1,%2,%3};"
                 : "+f"(c[0]), "+f"(c[1]), "+f"(c[2]), "+f"(c[3])
                 : "r"(a0), "r"(a1), "r"(a2), "r"(a3), "r"(b0), "r"(b1));
}
__device__ __forceinline__ void cp16(uint32_t saddr, const void* gptr) {
    asm volatile("cp.async.cg.shared.global [%0], [%1], 16;" :: "r"(saddr), "l"(gptr));
}
#define CP_COMMIT() asm volatile("cp.async.commit_group;")
#define CP_WAIT1() asm volatile("cp.async.wait_group 1;")
#define CP_WAIT0() asm volatile("cp.async.wait_group 0;")

// ================== fp16 HMMA cross GEMM, 3-stage pipeline ==================
#define GM_BM 128
#define GM_BN 128
#define GM_BK 32
#define GM_NT (CR_/GM_BK)   // 64
#define APAD 40
#define GM_ST 3
#define GM_TILE (128*APAD)                // __half elements per operand tile
#define GM_SMEM (GM_ST*2*GM_TILE*2)       // bytes

__global__ void __launch_bounds__(256) gemm_fp16_kernel() {
    extern __shared__ __half gsm[];
    __half* As = gsm;                     // GM_ST tiles
    __half* Bs = gsm + GM_ST*GM_TILE;
    const int tid = threadIdx.x, lane = tid & 31, wid = tid >> 5;
    const int wm = wid >> 2, wn = wid & 3;
    const int m0 = blockIdx.x * GM_BM;
    const int col0 = blockIdx.y * GM_BN;
    const int ldr = tid >> 1, ldc = (tid & 1) * 2;

    float acc[4][4][4];
#pragma unroll
    for (int i = 0; i < 4; ++i)
#pragma unroll
        for (int j = 0; j < 4; ++j)
#pragma unroll
            for (int q = 0; q < 4; ++q) acc[i][j][q] = 0.f;

    const int lrow = lane & 15, lhalf = lane >> 4;

    auto load_tile = [&](int kt, int buf) {
        const size_t gk = (size_t)kt * GM_BK;
        __half* ab = As + buf * GM_TILE;
        __half* bb = Bs + buf * GM_TILE;
#pragma unroll
        for (int s = 0; s < 2; ++s) {
            int c = ldc + s;
            cp16(smem_u32(ab + ldr * APAD + c * 8),
                 g_Wp + (size_t)(m0 + ldr) * CR_ + gk + c * 8);
            cp16(smem_u32(bb + ldr * APAD + c * 8),
                 g_Xp + (size_t)(col0 + ldr) * CR_ + gk + c * 8);
        }
        CP_COMMIT();
    };

    load_tile(0, 0);
    load_tile(1, 1);
    for (int kt = 0; kt < GM_NT; ++kt) {
        const int cur = kt % GM_ST;
        CP_WAIT1();
        __syncthreads();
        if (kt + 2 < GM_NT) load_tile(kt + 2, (kt + 2) % GM_ST);
        const __half* ab = As + cur * GM_TILE;
        const __half* bb = Bs + cur * GM_TILE;
#pragma unroll
        for (int kk2 = 0; kk2 < 2; ++kk2) {
            uint32_t a[4][4];
#pragma unroll
            for (int mt = 0; mt < 4; ++mt)
                ldsm_x4(a[mt], smem_u32(ab + (wm*64 + mt*16 + lrow) * APAD + kk2*16 + lhalf*8));
            uint32_t b[4][2];
#pragma unroll
            for (int nb2 = 0; nb2 < 2; ++nb2) {
                uint32_t r[4];
                ldsm_x4(r, smem_u32(bb + (wn*32 + nb2*16 + lrow) * APAD + kk2*16 + lhalf*8));
                b[nb2*2 + 0][0] = r[0]; b[nb2*2 + 0][1] = r[2];
                b[nb2*2 + 1][0] = r[1]; b[nb2*2 + 1][1] = r[3];
            }
#pragma unroll
            for (int mt = 0; mt < 4; ++mt)
#pragma unroll
                for (int nt = 0; nt < 4; ++nt)
                    mma_fp16(acc[mt][nt], a[mt][0], a[mt][1], a[mt][2], a[mt][3],
                             b[nt][0], b[nt][1]);
        }
    }
    const int grp = lane >> 2, qd = (lane & 3) * 2;
#pragma unroll
    for (int mt = 0; mt < 4; ++mt)
#pragma unroll
        for (int nt = 0; nt < 4; ++nt) {
            int m = m0 + wm*64 + mt*16 + grp;
            int n = col0 + wn*32 + nt*8 + qd;
            *(__half2*)(g_QKCh + (size_t)m * NCOL_ + n)       = __floats2half2_rn(acc[mt][nt][0], acc[mt][nt][1]);
            *(__half2*)(g_QKCh + (size_t)(m + 8) * NCOL_ + n) = __floats2half2_rn(acc[mt][nt][2], acc[mt][nt][3]);
        }
}

// ---------------- packing kernels ----------------
__global__ void pack_wp_kernel(const float* __restrict__ qw, const float* __restrict__ kw) {
    int idx = blockIdx.x * 256 + threadIdx.x;
    int m = idx >> 11, c = idx & 2047;
    int i = m >> 7, r = m & 127, s = r >> 6, d = r & 63;
    const float* src = s ? kw : qw;
    g_Wp[(size_t)m * CR_ + c] = __float2half(src[(i*64 + d)*2112 + 64 + c]);
}

__global__ void __launch_bounds__(256) xt_kernel(const float* __restrict__ x) {
    __shared__ float ts[32][33];
    const int lb = blockIdx.x * 32, kb = blockIdx.y * 32, n = blockIdx.z;
    const int tx = threadIdx.x & 31, ty = threadIdx.x >> 5;
#pragma unroll
    for (int r = ty; r < 32; r += 8)
        ts[r][tx] = x[((size_t)n * CR_ + kb + r) * L_ + lb + tx];
    __syncthreads();
#pragma unroll
    for (int r = ty; r < 32; r += 8)
        g_Xp[(size_t)(n * L_ + lb + r) * CR_ + kb + tx] = __float2half(ts[tx][r]);
}

// pack per-layer weights into fp16 A-layout [m][k]
__global__ void pack_aw_kernel(const float* __restrict__ convw, const float* __restrict__ qw,
                               const float* __restrict__ kw,   const float* __restrict__ vw,
                               const float* __restrict__ f1w,  const float* __restrict__ f2w) {
    int idx = blockIdx.x * 256 + threadIdx.x;     // NL_*8*4096
    if (idx < NL_*8*64*64) {
        int c = idx & 63, m = (idx >> 6) & 63, s = (idx >> 12) & 7, i = idx >> 15;
        const int tapmap[5] = {0, 1, 3, 4, 2};
        float v;
        if (s < 5)      v = convw[((i*64 + m)*64 + c)*5 + tapmap[s]];
        else if (s == 5) v = qw[(i*64 + m)*2112 + c];
        else if (s == 6) v = kw[(i*64 + m)*2112 + c];
        else             v = vw[(i*64 + m)*64 + c];
        g_AW[(size_t)(i*8 + s) * 4096 + m*64 + c] = __float2half(v);
    }
    if (idx < NL_*64*64) {
        int d = idx & 63, c = (idx >> 6) & 63, i = idx >> 12;
        g_f1T[idx] = f1w[(i*64 + d)*64 + c];
        g_f2T[idx] = f2w[(i*64 + d)*64 + c];
    }
}

// ---------------- timestep embedding (coalesced, 3 stages) ----------------
__global__ void temb1_kernel(const int* __restrict__ t, const float* __restrict__ w1,
                             const float* __restrict__ b1) {
    __shared__ float se[TE_];
    const int n = blockIdx.y, tid = threadIdx.x;
    const float tv = (float)t[n];
    if (tid < 256) {
        float f = expf((float)tid * (-logf(10000.0f) / 255.0f));
        se[tid] = sinf(tv * f);
        se[tid + 256] = cosf(tv * f);
    }
    __syncthreads();
    const int w = tid >> 5, lane = tid & 31;
    const int o = blockIdx.x * 8 + w;
    const float* wr = w1 + (size_t)o * TE_;
    float s = 0.f;
    for (int c = lane; c < TE_; c += 32) s += se[c] * wr[c];
#pragma unroll
    for (int off = 16; off; off >>= 1) s += __shfl_xor_sync(0xffffffffu, s, off);
    if (!lane) { s += b1[o]; g_t1[n*TE_ + o] = s / (1.f + expf(-s)); }
}
__global__ void temb2_kernel(const float* __restrict__ w2, const float* __restrict__ b2) {
    __shared__ float se[TE_];
    const int n = blockIdx.y, tid = threadIdx.x;
    se[tid] = g_t1[n*TE_ + tid];
    se[tid + 256] = g_t1[n*TE_ + tid + 256];
    __syncthreads();
    const int w = tid >> 5, lane = tid & 31;
    const int o = blockIdx.x * 8 + w;
    const float* wr = w2 + (size_t)o * TE_;
    float s = 0.f;
    for (int c = lane; c < TE_; c += 32) s += se[c] * wr[c];
#pragma unroll
    for (int off = 16; off; off >>= 1) s += __shfl_xor_sync(0xffffffffu, s, off);
    if (!lane) g_t2[n*TE_ + o] = s + b2[o];
}
__global__ void tembp_kernel(const float* __restrict__ wp, const float* __restrict__ bp) {
    __shared__ float se[TE_];
    const int n = blockIdx.y, tid = threadIdx.x;
    {
        float v0 = g_t2[n*TE_ + tid], v1 = g_t2[n*TE_ + tid + 256];
        se[tid]       = v0 / (1.f + expf(-v0));
        se[tid + 256] = v1 / (1.f + expf(-v1));
    }
    __syncthreads();
    const int w = tid >> 5, lane = tid & 31;
    const int o = blockIdx.x * 8 + w;
    const float* wr = wp + (size_t)o * TE_;
    float s = 0.f;
    for (int c = lane; c < TE_; c += 32) s += se[c] * wr[c];
#pragma unroll
    for (int off = 16; off; off >>= 1) s += __shfl_xor_sync(0xffffffffu, s, off);
    if (!lane) g_tproj[n*D_ + o] = s + bp[o];
}

// ---------------- conv_in (1x1, 48->64) + time proj; writes fp32 + fp16 hi/lo ------
__global__ void __launch_bounds__(256) conv_in_kernel(const float* __restrict__ event,
                                                      const float* __restrict__ w,
                                                      const float* __restrict__ b) {
    __shared__ float Et[NC_][64];
    __shared__ float Wt[NC_][64];
    const int n = blockIdx.y, l0 = blockIdx.x * 64;
    const int tid = threadIdx.x, ty4 = (tid >> 4) << 2, tx4 = (tid & 15) << 2;
    for (int e = tid; e < NC_*64; e += 256) {
        int c = e >> 6, tt = e & 63;
        Et[c][tt] = event[(n*NC_ + c)*L_ + l0 + tt];
        Wt[c][tt] = w[tt*NC_ + c];
    }
    __syncthreads();
    float acc[4][4] = {};
#pragma unroll
    for (int c = 0; c < NC_; ++c) {
        const float4 a = *(const float4*)(&Wt[c][ty4]);
        const float4 x4 = *(const float4*)(&Et[c][tx4]);
        acc[0][0]+=a.x*x4.x; acc[0][1]+=a.x*x4.y; acc[0][2]+=a.x*x4.z; acc[0][3]+=a.x*x4.w;
        acc[1][0]+=a.y*x4.x; acc[1][1]+=a.y*x4.y; acc[1][2]+=a.y*x4.z; acc[1][3]+=a.y*x4.w;
        acc[2][0]+=a.z*x4.x; acc[2][1]+=a.z*x4.y; acc[2][2]+=a.z*x4.z; acc[2][3]+=a.z*x4.w;
        acc[3][0]+=a.w*x4.x; acc[3][1]+=a.w*x4.y; acc[3][2]+=a.w*x4.z; acc[3][3]+=a.w*x4.w;
    }
#pragma unroll
    for (int i = 0; i < 4; ++i)
#pragma unroll
        for (int j = 0; j < 4; ++j) {
            int d = ty4 + i, l = l0 + tx4 + j;
            size_t o = (size_t)(n*D_ + d)*L_ + l;
            float v = acc[i][j] + b[d] + g_tproj[n*D_ + d];
            g_fra[o] = v;
            __half h = __float2half(v);
            g_fh[o] = h;
            g_fl[o] = __float2half(v - __half2float(h));
        }
}

// ================== per-layer HMMA: z=0 conv (5 taps), z=1 q/k/v ==================
#define LA_SMEM (16384 + 65536)

__device__ __forceinline__ void mm64(float acc[2][4][4], uint32_t Ah,
                                     uint32_t Bh, uint32_t Bl, int wm, int wn, int lane) {
    const int lrow = lane & 15, lhalf = lane >> 4;
    const int bk = (lane & 7) + (((lane >> 3) & 1) << 3);
    const int bn8 = (lane >> 4) << 3;
#pragma unroll
    for (int pass = 0; pass < 2; ++pass) {
        uint32_t Bb = pass ? Bl : Bh;
#pragma unroll
        for (int k0 = 0; k0 < 4; ++k0) {
            uint32_t a[2][4];
#pragma unroll
            for (int mt = 0; mt < 2; ++mt) {
                int m = wm*32 + mt*16 + lrow;
                int ch = (k0*2 + lhalf) ^ (m & 7);
                ldsm_x4(a[mt], Ah + m*128 + ch*16);
            }
            uint32_t b[4][2];
#pragma unroll
            for (int ng = 0; ng < 2; ++ng) {
                int k = k0*16 + bk;
                int n = wn*32 + ng*16 + bn8;
                int ch = (n >> 3) ^ (k & 7);
                uint32_t r[4];
                ldsm_x4t(r, Bb + k*256 + ch*16);
                b[ng*2 + 0][0] = r[0]; b[ng*2 + 0][1] = r[1];
                b[ng*2 + 1][0] = r[2]; b[ng*2 + 1][1] = r[3];
            }
#pragma unroll
            for (int mt = 0; mt < 2; ++mt)
#pragma unroll
                for (int nt = 0; nt < 4; ++nt)
                    mma_fp16(acc[mt][nt], a[mt][0], a[mt][1], a[mt][2], a[mt][3],
                             b[nt][0], b[nt][1]);
        }
    }
}

__global__ void __launch_bounds__(256) layer_mm_kernel(const float* __restrict__ convb,
                                                       const float* __restrict__ qb,
                                                       const float* __restrict__ kb,
                                                       const float* __restrict__ vb,
                                                       int layer, int dil) {
    extern __shared__ char dsm[];
    char* smA = dsm;            // 2 x 8KB
    char* smB = dsm + 16384;    // 2 x 32KB (hi 16KB + lo 16KB)
    const int tid = threadIdx.x, lane = tid & 31, wid = tid >> 5;
    const int wm = wid >> 2, wn = wid & 3;
    const int l0 = blockIdx.x * 128, nb = blockIdx.y, z = blockIdx.z;
    const __half* fh = g_fh + (size_t)nb * D_ * L_;
    const __half* fl = g_fl + (size_t)nb * D_ * L_;
    const float* fb = g_fra + (size_t)nb * D_ * L_;

    auto loadA = [&](int slot, int buf) {
        const __half* src = g_AW + (size_t)(layer*8 + slot) * 4096;
        char* dh = smA + buf * 8192;
#pragma unroll
        for (int e = tid; e < 512; e += 256) {
            int m = e >> 3, c = e & 7;
            int off = m*128 + ((c ^ (m & 7)) << 4);
            cp16(smem_u32(dh + off), src + m*64 + c*8);
        }
    };
    auto loadB = [&](int shift, int buf) {
        char* dh = smB + buf * 32768;
        char* dl = dh + 16384;
        if ((shift & 7) == 0) {
#pragma unroll
            for (int e = tid; e < 1024; e += 256) {
                int k = e >> 4, c = e & 15;
                int gl = l0 + c*8 + shift;
                int off = k*256 + ((c ^ (k & 7)) << 4);
                if (gl >= 0 && gl + 8 <= L_) {
                    cp16(smem_u32(dh + off), fh + (size_t)k * L_ + gl);
                    cp16(smem_u32(dl + off), fl + (size_t)k * L_ + gl);
                } else {
                    __half* ph = (__half*)(dh + off);
                    __half* pl = (__half*)(dl + off);
#pragma unroll
                    for (int u = 0; u < 8; ++u) {
                        int l = gl + u;
                        bool ok = ((unsigned)l < (unsigned)L_);
                        ph[u] = ok ? fh[(size_t)k * L_ + l] : __half(0.f);
                        pl[u] = ok ? fl[(size_t)k * L_ + l] : __half(0.f);
                    }
                }
            }
        } else {
#pragma unroll
            for (int e = tid; e < 1024; e += 256) {
                int k = e >> 4, c = e & 15;
                int gl = l0 + c*8 + shift;
                int off = k*256 + ((c ^ (k & 7)) << 4);
                const float* src = fb + (size_t)k * L_;
                __half hb[8], lb[8];
#pragma unroll
                for (int u = 0; u < 8; ++u) {
                    int l = gl + u;
                    float v = ((unsigned)l < (unsigned)L_) ? __ldg(src + l) : 0.f;
                    __half h = __float2half(v);
                    hb[u] = h;
                    lb[u] = __float2half(v - __half2float(h));
                }
                *(uint4*)(dh + off) = *(uint4*)hb;
                *(uint4*)(dl + off) = *(uint4*)lb;
            }
        }
    };

    float acc[2][4][4];
#pragma unroll
    for (int i = 0; i < 2; ++i)
#pragma unroll
        for (int j = 0; j < 4; ++j)
#pragma unroll
            for (int q = 0; q < 4; ++q) acc[i][j][q] = 0.f;

    const int grp = lane >> 2, qd = (lane & 3) * 2;
    auto epilogue = [&](__half* dst, const float* bias, const __half* qkc) {
#pragma unroll
        for (int mt = 0; mt < 2; ++mt)
#pragma unroll
            for (int nt = 0; nt < 4; ++nt) {
                int m = wm*32 + mt*16 + grp;
                int n = wn*32 + nt*8 + qd;
                float v0 = acc[mt][nt][0] + bias[m];
                float v1 = acc[mt][nt][1] + bias[m];
                float v2 = acc[mt][nt][2] + bias[m + 8];
                float v3 = acc[mt][nt][3] + bias[m + 8];
                if (qkc) {
                    __half2 e0 = *(const __half2*)(qkc + (size_t)m * NCOL_ + n);
                    __half2 e1 = *(const __half2*)(qkc + (size_t)(m + 8) * NCOL_ + n);
                    v0 += __low2float(e0); v1 += __high2float(e0);
                    v2 += __low2float(e1); v3 += __high2float(e1);
                }
                *(__half2*)(dst + (size_t)(nb*D_ + m) * L_ + l0 + n)     = __floats2half2_rn(v0, v1);
                *(__half2*)(dst + (size_t)(nb*D_ + m + 8) * L_ + l0 + n) = __floats2half2_rn(v2, v3);
                acc[mt][nt][0] = acc[mt][nt][1] = acc[mt][nt][2] = acc[mt][nt][3] = 0.f;
            }
    };

    if (z == 0) {
        // dilated conv: 5 taps accumulated, one epilogue
        const int tapshift[5] = {-2*dil, -dil, dil, 2*dil, 0};
        loadB(tapshift[0], 0);
        loadA(0, 0);
        CP_COMMIT();
        for (int it = 0; it < 5; ++it) {
            __syncthreads();
            if (it < 4) {
                loadB(tapshift[it + 1], (it + 1) & 1);
                loadA(it + 1, (it + 1) & 1);
                CP_COMMIT();
                CP_WAIT1();
            } else {
                CP_WAIT0();
            }
            __syncthreads();
            uint32_t Ah = smem_u32(smA + (it & 1) * 8192);
            uint32_t Bh = smem_u32(smB + (it & 1) * 32768);
            mm64(acc, Ah, Bh, Bh + 16384, wm, wn, lane);
        }
        epilogue(g_out1, convb + layer*64, nullptr);
    } else {
        // q/k/v: single B tile (shift 0), 3 A slots
        loadB(0, 0);
        loadA(5, 0);
        CP_COMMIT();
        const uint32_t Bh = smem_u32(smB);
        for (int it = 0; it < 3; ++it) {
            __syncthreads();
            if (it < 2) {
                loadA(6 + it, (it + 1) & 1);
                CP_COMMIT();
                CP_WAIT1();
            } else {
                CP_WAIT0();
            }
            __syncthreads();
            uint32_t Ah = smem_u32(smA + (it & 1) * 8192);
            mm64(acc, Ah, Bh, Bh + 16384, wm, wn, lane);
            if (it == 0)
                epilogue(g_xq, qb + layer*64, g_QKCh + (size_t)(layer*2)*64*NCOL_ + nb*L_ + l0);
            else if (it == 1)
                epilogue(g_xk, kb + layer*64, g_QKCh + (size_t)(layer*2 + 1)*64*NCOL_ + nb*L_ + l0);
            else
                epilogue(g_xv, vb + layer*64, nullptr);
        }
    }
}

// ---------------- fused attention: scores + softmax + apply + IN partials ----------
__global__ void __launch_bounds__(256) attn_fused_kernel(int dil) {
    __shared__ float satt[5][64];
    const int n = blockIdx.y, l0 = blockIdx.x * 64;
    const int tid = threadIdx.x;

    // ---- stage A: scores + softmax (4 lanes per l) ----
    {
        const int g = tid & 3, l = tid >> 2;
        const int lg = l0 + l;
        const __half* qp = g_xq + (size_t)n * D_ * L_ + lg;
        const __half* kp = g_xk + (size_t)n * D_ * L_;
        bool v[5]; int pc[5];
#pragma unroll
        for (int j = 0; j < 5; ++j) {
            int p = lg + (j - 2) * dil;
            v[j] = ((unsigned)p < (unsigned)L_);
            pc[j] = v[j] ? p : lg;
        }
        float dot[5] = {};
#pragma unroll 4
        for (int c = g; c < 64; c += 4) {
            float qv = __half2float(__ldg(qp + c * L_));
#pragma unroll
            for (int j = 0; j < 5; ++j)
                dot[j] += qv * __half2float(__ldg(kp + c*L_ + pc[j]));
        }
#pragma unroll
        for (int j = 0; j < 5; ++j) {
            dot[j] += __shfl_xor_sync(0xffffffffu, dot[j], 1);
            dot[j] += __shfl_xor_sync(0xffffffffu, dot[j], 2);
        }
        const float LVALID = logf(1.0f + 1e-6f);
        const float LINV   = logf(1e-6f);
        float lg5[5];
#pragma unroll
        for (int j = 0; j < 5; ++j) lg5[j] = v[j] ? dot[j]*0.125f + LVALID : LINV;
        float mx = lg5[0];
#pragma unroll
        for (int j = 1; j < 5; ++j) mx = fmaxf(mx, lg5[j]);
        float e[5], s = 0.f;
#pragma unroll
        for (int j = 0; j < 5; ++j) { e[j] = expf(lg5[j] - mx); s += e[j]; }
        float inv = 1.f / s;
        if (g == 0) {
#pragma unroll
            for (int j = 0; j < 5; ++j) satt[j][l] = v[j] ? e[j]*inv : 0.f;
        }
    }
    __syncthreads();

    // ---- stage B: r = att @ v_win, y = out1 + r, per-channel partial stats ----
    const int tx = tid & 15, ty = tid >> 4;
    const int c0 = ty * 4, lx = tx * 4;
    float s1[4] = {}, s2[4] = {};
#pragma unroll
    for (int ci = 0; ci < 4; ++ci) {
        int c = c0 + ci;
        const __half* vp = g_xv + (size_t)(n*D_ + c) * L_;
        const __half* op = g_out1 + (size_t)(n*D_ + c) * L_ + l0;
        float* yp = g_y + (size_t)(n*D_ + c) * L_ + l0;
        float yv4[4];
#pragma unroll
        for (int lj = 0; lj < 4; ++lj) {
            int l = lx + lj, lgl = l0 + l;
            float r = 0.f;
#pragma unroll
            for (int j = 0; j < 5; ++j) {
                int pp = lgl + (j - 2) * dil;
                if ((unsigned)pp < (unsigned)L_)
                    r += satt[j][l] * __half2float(__ldg(vp + pp));
            }
            float yv = __half2float(op[l]) + r;
            yv4[lj] = yv;
            s1[ci] += yv; s2[ci] += yv * yv;
        }
        *(float4*)(yp + lx) = make_float4(yv4[0], yv4[1], yv4[2], yv4[3]);
    }
#pragma unroll
    for (int off = 8; off; off >>= 1)
#pragma unroll
        for (int ci = 0; ci < 4; ++ci) {
            s1[ci] += __shfl_xor_sync(0xffffffffu, s1[ci], off);
            s2[ci] += __shfl_xor_sync(0xffffffffu, s2[ci], off);
        }
    if (tx == 0) {
#pragma unroll
        for (int ci = 0; ci < 4; ++ci) {
            g_part[((n*D_ + c0 + ci)*128 + blockIdx.x)*2 + 0] = s1[ci];
            g_part[((n*D_ + c0 + ci)*128 + blockIdx.x)*2 + 1] = s2[ci];
        }
    }
}

// ---------------- shared-mem 64x64 micro-matmul (SIMT, for FFN) ----------------
__device__ __forceinline__ void mm_16x16(const float (*Ws)[64], const float (*Xs)[64],
                                         float acc[4][4], int ty4, int tx4) {
#pragma unroll 16
    for (int c = 0; c < 64; ++c) {
        const float4 a = *(const float4*)(&Ws[c][ty4]);
        const float4 b = *(const float4*)(&Xs[c][tx4]);
        acc[0][0] += a.x*b.x; acc[0][1] += a.x*b.y; acc[0][2] += a.x*b.z; acc[0][3] += a.x*b.w;
        acc[1][0] += a.y*b.x; acc[1][1] += a.y*b.y; acc[1][2] += a.y*b.z; acc[1][3] += a.y*b.w;
        acc[2][0] += a.z*b.x; acc[2][1] += a.z*b.y; acc[2][2] += a.z*b.z; acc[2][3] += a.z*b.w;
        acc[3][0] += a.w*b.x; acc[3][1] += a.w*b.y; acc[3][2] += a.w*b.z; acc[3][3] += a.w*b.w;
    }
}

// ---------------- instance-norm stats + FFN + residual; writes fp32 + fp16 ---------
__global__ void __launch_bounds__(256) ffn_kernel(const float* __restrict__ f1b,
                                                  const float* __restrict__ f2b,
                                                  int layer) {
    __shared__ float Xs[64][64];
    __shared__ float Ws[64][64];
    __shared__ float sms[64], srs[64];
    const int n = blockIdx.y, l0 = blockIdx.x * 64;
    const int tid = threadIdx.x, ty4 = (tid >> 4) << 2, tx4 = (tid & 15) << 2;
    if (tid < 64) {
        float s = 0.f, s2 = 0.f;
        for (int bq = 0; bq < 128; ++bq) {
            s  += g_part[((n*D_ + tid)*128 + bq)*2 + 0];
            s2 += g_part[((n*D_ + tid)*128 + bq)*2 + 1];
        }
        float mean = s / (float)L_;
        float var = s2 / (float)L_ - mean*mean;
        sms[tid] = mean;
        srs[tid] = rsqrtf(var + 1e-5f);
    }
    __syncthreads();
    {
        const float* wsrc = g_f1T + (size_t)layer * 4096;
        for (int e = tid; e < 4096; e += 256) {
            int c = e >> 6, tt = e & 63;
            Xs[c][tt] = (g_y[(size_t)(n*D_ + c)*L_ + l0 + tt] - sms[c]) * srs[c];
            ((float*)Ws)[e] = wsrc[e];
        }
    }
    __syncthreads();
    float acc[4][4] = {};
    mm_16x16(Ws, Xs, acc, ty4, tx4);
    __syncthreads();
#pragma unroll
    for (int i = 0; i < 4; ++i)
#pragma unroll
        for (int j = 0; j < 4; ++j)
            Xs[ty4 + i][tx4 + j] = fmaxf(acc[i][j] + f1b[layer*64 + ty4 + i], 0.f);
    {
        const float* wsrc = g_f2T + (size_t)layer * 4096;
        for (int e = tid; e < 4096; e += 256) ((float*)Ws)[e] = wsrc[e];
    }
    __syncthreads();
    float a2[4][4] = {};
    mm_16x16(Ws, Xs, a2, ty4, tx4);
#pragma unroll
    for (int i = 0; i < 4; ++i)
#pragma unroll
        for (int j = 0; j < 4; ++j) {
            int d = ty4 + i, l = l0 + tx4 + j;
            size_t o = (size_t)(n*D_ + d)*L_ + l;
            float nv = g_fra[o] + a2[i][j] + f2b[layer*64 + d];
            g_fra[o] = nv;
            __half h = __float2half(nv);
            g_fh[o] = h;
            g_fl[o] = __float2half(nv - __half2float(h));
        }
}

// ---------------- conv_out (1x1, 64->48) ----------------
__global__ void __launch_bounds__(256) conv_out_kernel(const float* __restrict__ w,
                                                       const float* __restrict__ b,
                                                       float* __restrict__ out) {
    __shared__ float Xs[64][64];
    __shared__ float Wt[64][NC_];
    const int n = blockIdx.y, l0 = blockIdx.x * 64;
    const int tid = threadIdx.x, ty = tid >> 4, tx = tid & 15;
    for (int e = tid; e < 4096; e += 256) {
        int c = e >> 6, tt = e & 63;
        Xs[c][tt] = g_fra[(size_t)(n*D_ + c)*L_ + l0 + tt];
    }
    for (int e = tid; e < 64*NC_; e += 256) {
        int c = e / NC_, o = e % NC_;
        Wt[c][o] = w[o*64 + c];
    }
    __syncthreads();
    if (ty < 12) {
        const int ty4 = ty*4, tx4 = tx*4;
        float acc[4][4] = {};
#pragma unroll 16
        for (int c = 0; c < 64; ++c) {
            const float4 a = *(const float4*)(&Wt[c][ty4]);
            const float4 x4 = *(const float4*)(&Xs[c][tx4]);
            acc[0][0]+=a.x*x4.x; acc[0][1]+=a.x*x4.y; acc[0][2]+=a.x*x4.z; acc[0][3]+=a.x*x4.w;
            acc[1][0]+=a.y*x4.x; acc[1][1]+=a.y*x4.y; acc[1][2]+=a.y*x4.z; acc[1][3]+=a.y*x4.w;
            acc[2][0]+=a.z*x4.x; acc[2][1]+=a.z*x4.y; acc[2][2]+=a.z*x4.z; acc[2][3]+=a.z*x4.w;
            acc[3][0]+=a.w*x4.x; acc[3][1]+=a.w*x4.y; acc[3][2]+=a.w*x4.z; acc[3][3]+=a.w*x4.w;
        }
#pragma unroll
        for (int i = 0; i < 4; ++i)
#pragma unroll
            for (int j = 0; j < 4; ++j) {
                int o = ty4 + i, l = l0 + tx4 + j;
                out[(size_t)(n*NC_ + o)*L_ + l] = acc[i][j] + b[o];
            }
    }
}

// ---------------- host side ----------------
extern "C" void kernel_launch(void* const* d_in, const int* in_sizes, int n_in,
                              void* d_out, int out_size) {
    (void)in_sizes; (void)n_in; (void)out_size;
    const float* x     = (const float*)d_in[0];
    const int*   t     = (const int*)  d_in[1];
    const float* event = (const float*)d_in[2];
    const float* tw1   = (const float*)d_in[3];
    const float* tb1   = (const float*)d_in[4];
    const float* tw2   = (const float*)d_in[5];
    const float* tb2   = (const float*)d_in[6];
    const float* tpw   = (const float*)d_in[7];
    const float* tpb   = (const float*)d_in[8];
    const float* ciw   = (const float*)d_in[9];
    const float* cib   = (const float*)d_in[10];
    const float* cow   = (const float*)d_in[11];
    const float* cob   = (const float*)d_in[12];
    const float* lcw   = (const float*)d_in[13];
    const float* lcb   = (const float*)d_in[14];
    const float* qw    = (const float*)d_in[15];
    const float* qb    = (const float*)d_in[16];
    const float* kw    = (const float*)d_in[17];
    const float* kb    = (const float*)d_in[18];
    const float* vw    = (const float*)d_in[19];
    const float* vb    = (const float*)d_in[20];
    const float* f1w   = (const float*)d_in[21];
    const float* f1b   = (const float*)d_in[22];
    const float* f2w   = (const float*)d_in[23];
    const float* f2b   = (const float*)d_in[24];

    cudaFuncSetAttribute(layer_mm_kernel, cudaFuncAttributeMaxDynamicSharedMemorySize, LA_SMEM);
    cudaFuncSetAttribute(gemm_fp16_kernel, cudaFuncAttributeMaxDynamicSharedMemorySize, GM_SMEM);

    pack_wp_kernel<<<(M_*CR_)/256, 256>>>(qw, kw);
    xt_kernel<<<dim3(L_/32, CR_/32, B_), 256>>>(x);
    pack_aw_kernel<<<(NL_*8*64*64)/256, 256>>>(lcw, qw, kw, vw, f1w, f2w);
    temb1_kernel<<<dim3(64, B_), 256>>>(t, tw1, tb1);
    temb2_kernel<<<dim3(64, B_), 256>>>(tw2, tb2);
    gemm_fp16_kernel<<<dim3(M_/GM_BM, NCOL_/GM_BN), 256, GM_SMEM>>>();
    tembp_kernel<<<dim3(8, B_), 256>>>(tpw, tpb);
    conv_in_kernel<<<dim3(L_/64, B_), 256>>>(event, ciw, cib);

    for (int i = 0; i < NL_; ++i) {
        int dil = 1 << i;
        layer_mm_kernel<<<dim3(L_/128, B_, 2), 256, LA_SMEM>>>(lcb, qb, kb, vb, i, dil);
        attn_fused_kernel<<<dim3(L_/64, B_), 256>>>(dil);
        ffn_kernel<<<dim3(L_/64, B_), 256>>>(f1b, f2b, i);
    }
    conv_out_kernel<<<dim3(L_/64, B_), 256>>>(cow, cob, (float*)d_out);
}

// round 9
// speedup vs baseline: 4.6752x; 1.0432x over previous
#include <cuda_runtime.h>
#include <cuda_bf16.h>
#include <cuda_fp16.h>
#include <math.h>
#include <stdint.h>

#define B_  2
#define L_  8192
#define D_  64
#define CR_ 2048
#define NC_ 48
#define TE_ 512
#define NL_ 8
#define M_  1024        // NL*2*D rows of the batched cross GEMM
#define NCOL_ (B_*L_)   // 16384 columns

// ---------------- scratch (device globals; no allocation allowed) ----------------
__device__ __half g_Wp[(size_t)M_*CR_];        // A = W fp16, K-major
__device__ __half g_Xp[(size_t)NCOL_*CR_];     // B = x fp16, K-major per col
__device__ __half g_QKCh[(size_t)M_*NCOL_];    // cross-projection results fp16 [m][n*L+l]
__device__ __half g_AW[NL_*8*64*64];     // layer weights fp16 [i][slot][m][k]; slots: taps{0,1,3,4,2},q,k,v
__device__ __half g_fh[B_*D_*L_];        // fra fp16
__device__ float g_f1T [NL_*64*64];
__device__ float g_f2T [NL_*64*64];
__device__ float g_fra [B_*D_*L_];
__device__ __half g_xq  [B_*D_*L_];
__device__ __half g_xk  [B_*D_*L_];
__device__ __half g_xv  [B_*D_*L_];
__device__ __half g_out1[B_*D_*L_];
__device__ float g_y   [B_*D_*L_];
__device__ float g_part[B_*D_*128*2];
__device__ float g_tproj[B_*D_];
__device__ float g_t1[B_*TE_];
__device__ float g_t2[B_*TE_];

__device__ __forceinline__ uint32_t smem_u32(const void* p) {
    return (uint32_t)__cvta_generic_to_shared(p);
}
__device__ __forceinline__ void ldsm_x4(uint32_t* r, uint32_t addr) {
    asm volatile("ldmatrix.sync.aligned.m8n8.x4.shared.b16 {%0,%1,%2,%3}, [%4];"
                 : "=r"(r[0]), "=r"(r[1]), "=r"(r[2]), "=r"(r[3]) : "r"(addr));
}
__device__ __forceinline__ void ldsm_x4t(uint32_t* r, uint32_t addr) {
    asm volatile("ldmatrix.sync.aligned.m8n8.x4.trans.shared.b16 {%0,%1,%2,%3}, [%4];"
                 : "=r"(r[0]), "=r"(r[1]), "=r"(r[2]), "=r"(r[3]) : "r"(addr));
}
__device__ __forceinline__ void mma_fp16(float c[4], uint32_t a0, uint32_t a1, uint32_t a2,
                                         uint32_t a3, uint32_t b0, uint32_t b1) {
    asm volatile("mma.sync.aligned.m16n8k16.row.col.f32.f16.f16.f32 "
                 "{%0,%1,%2,%3}, {%4,%5,%6,%7}, {%8,%9}, {%0,%1,%2,%3};"
                 : "+f"(c[0]), "+f"(c[1]), "+f"(c[2]), "+f"(c[3])
                 : "r"(a0), "r"(a1), "r"(a2), "r"(a3), "r"(b0), "r"(b1));
}
__device__ __forceinline__ void cp16(uint32_t saddr, const void* gptr) {
    asm volatile("cp.async.cg.shared.global [%0], [%1], 16;" :: "r"(saddr), "l"(gptr));
}
#define CP_COMMIT() asm volatile("cp.async.commit_group;")
#define CP_WAIT2() asm volatile("cp.async.wait_group 2;")
#define CP_WAIT1() asm volatile("cp.async.wait_group 1;")
#define CP_WAIT0() asm volatile("cp.async.wait_group 0;")

// ================== fp16 HMMA cross GEMM, 3-stage pipeline ==================
#define GM_BM 128
#define GM_BN 128
#define GM_BK 32
#define GM_NT (CR_/GM_BK)   // 64
#define APAD 40
#define GM_ST 3
#define GM_TILE (128*APAD)                // __half elements per operand tile
#define GM_SMEM (GM_ST*2*GM_TILE*2)       // bytes

__global__ void __launch_bounds__(256) gemm_fp16_kernel() {
    extern __shared__ __half gsm[];
    __half* As = gsm;                     // GM_ST tiles
    __half* Bs = gsm + GM_ST*GM_TILE;
    const int tid = threadIdx.x, lane = tid & 31, wid = tid >> 5;
    const int wm = wid >> 2, wn = wid & 3;
    const int m0 = blockIdx.x * GM_BM;
    const int col0 = blockIdx.y * GM_BN;
    const int ldr = tid >> 1, ldc = (tid & 1) * 2;

    float acc[4][4][4];
#pragma unroll
    for (int i = 0; i < 4; ++i)
#pragma unroll
        for (int j = 0; j < 4; ++j)
#pragma unroll
            for (int q = 0; q < 4; ++q) acc[i][j][q] = 0.f;

    const int lrow = lane & 15, lhalf = lane >> 4;

    auto load_tile = [&](int kt, int buf) {
        const size_t gk = (size_t)kt * GM_BK;
        __half* ab = As + buf * GM_TILE;
        __half* bb = Bs + buf * GM_TILE;
#pragma unroll
        for (int s = 0; s < 2; ++s) {
            int c = ldc + s;
            cp16(smem_u32(ab + ldr * APAD + c * 8),
                 g_Wp + (size_t)(m0 + ldr) * CR_ + gk + c * 8);
            cp16(smem_u32(bb + ldr * APAD + c * 8),
                 g_Xp + (size_t)(col0 + ldr) * CR_ + gk + c * 8);
        }
        CP_COMMIT();
    };

    load_tile(0, 0);
    load_tile(1, 1);
    for (int kt = 0; kt < GM_NT; ++kt) {
        const int cur = kt % GM_ST;
        CP_WAIT1();
        __syncthreads();
        if (kt + 2 < GM_NT) load_tile(kt + 2, (kt + 2) % GM_ST);
        const __half* ab = As + cur * GM_TILE;
        const __half* bb = Bs + cur * GM_TILE;
#pragma unroll
        for (int kk2 = 0; kk2 < 2; ++kk2) {
            uint32_t a[4][4];
#pragma unroll
            for (int mt = 0; mt < 4; ++mt)
                ldsm_x4(a[mt], smem_u32(ab + (wm*64 + mt*16 + lrow) * APAD + kk2*16 + lhalf*8));
            uint32_t b[4][2];
#pragma unroll
            for (int nb2 = 0; nb2 < 2; ++nb2) {
                uint32_t r[4];
                ldsm_x4(r, smem_u32(bb + (wn*32 + nb2*16 + lrow) * APAD + kk2*16 + lhalf*8));
                b[nb2*2 + 0][0] = r[0]; b[nb2*2 + 0][1] = r[2];
                b[nb2*2 + 1][0] = r[1]; b[nb2*2 + 1][1] = r[3];
            }
#pragma unroll
            for (int mt = 0; mt < 4; ++mt)
#pragma unroll
                for (int nt = 0; nt < 4; ++nt)
                    mma_fp16(acc[mt][nt], a[mt][0], a[mt][1], a[mt][2], a[mt][3],
                             b[nt][0], b[nt][1]);
        }
    }
    const int grp = lane >> 2, qd = (lane & 3) * 2;
#pragma unroll
    for (int mt = 0; mt < 4; ++mt)
#pragma unroll
        for (int nt = 0; nt < 4; ++nt) {
            int m = m0 + wm*64 + mt*16 + grp;
            int n = col0 + wn*32 + nt*8 + qd;
            *(__half2*)(g_QKCh + (size_t)m * NCOL_ + n)       = __floats2half2_rn(acc[mt][nt][0], acc[mt][nt][1]);
            *(__half2*)(g_QKCh + (size_t)(m + 8) * NCOL_ + n) = __floats2half2_rn(acc[mt][nt][2], acc[mt][nt][3]);
        }
}

// ---------------- packing kernels ----------------
__global__ void pack_wp_kernel(const float* __restrict__ qw, const float* __restrict__ kw) {
    int idx = blockIdx.x * 256 + threadIdx.x;
    int m = idx >> 11, c = idx & 2047;
    int i = m >> 7, r = m & 127, s = r >> 6, d = r & 63;
    const float* src = s ? kw : qw;
    g_Wp[(size_t)m * CR_ + c] = __float2half(src[(i*64 + d)*2112 + 64 + c]);
}

__global__ void __launch_bounds__(256) xt_kernel(const float* __restrict__ x) {
    __shared__ float ts[32][33];
    const int lb = blockIdx.x * 32, kb = blockIdx.y * 32, n = blockIdx.z;
    const int tx = threadIdx.x & 31, ty = threadIdx.x >> 5;
#pragma unroll
    for (int r = ty; r < 32; r += 8)
        ts[r][tx] = x[((size_t)n * CR_ + kb + r) * L_ + lb + tx];
    __syncthreads();
#pragma unroll
    for (int r = ty; r < 32; r += 8)
        g_Xp[(size_t)(n * L_ + lb + r) * CR_ + kb + tx] = __float2half(ts[tx][r]);
}

// pack per-layer weights into fp16 A-layout [m][k]
__global__ void pack_aw_kernel(const float* __restrict__ convw, const float* __restrict__ qw,
                               const float* __restrict__ kw,   const float* __restrict__ vw,
                               const float* __restrict__ f1w,  const float* __restrict__ f2w) {
    int idx = blockIdx.x * 256 + threadIdx.x;     // NL_*8*4096
    if (idx < NL_*8*64*64) {
        int c = idx & 63, m = (idx >> 6) & 63, s = (idx >> 12) & 7, i = idx >> 15;
        const int tapmap[5] = {0, 1, 3, 4, 2};
        float v;
        if (s < 5)      v = convw[((i*64 + m)*64 + c)*5 + tapmap[s]];
        else if (s == 5) v = qw[(i*64 + m)*2112 + c];
        else if (s == 6) v = kw[(i*64 + m)*2112 + c];
        else             v = vw[(i*64 + m)*64 + c];
        g_AW[(size_t)(i*8 + s) * 4096 + m*64 + c] = __float2half(v);
    }
    if (idx < NL_*64*64) {
        int d = idx & 63, c = (idx >> 6) & 63, i = idx >> 12;
        g_f1T[idx] = f1w[(i*64 + d)*64 + c];
        g_f2T[idx] = f2w[(i*64 + d)*64 + c];
    }
}

// ---------------- timestep embedding (coalesced, 3 stages) ----------------
__global__ void temb1_kernel(const int* __restrict__ t, const float* __restrict__ w1,
                             const float* __restrict__ b1) {
    __shared__ float se[TE_];
    const int n = blockIdx.y, tid = threadIdx.x;
    const float tv = (float)t[n];
    if (tid < 256) {
        float f = expf((float)tid * (-logf(10000.0f) / 255.0f));
        se[tid] = sinf(tv * f);
        se[tid + 256] = cosf(tv * f);
    }
    __syncthreads();
    const int w = tid >> 5, lane = tid & 31;
    const int o = blockIdx.x * 8 + w;
    const float* wr = w1 + (size_t)o * TE_;
    float s = 0.f;
    for (int c = lane; c < TE_; c += 32) s += se[c] * wr[c];
#pragma unroll
    for (int off = 16; off; off >>= 1) s += __shfl_xor_sync(0xffffffffu, s, off);
    if (!lane) { s += b1[o]; g_t1[n*TE_ + o] = s / (1.f + expf(-s)); }
}
__global__ void temb2_kernel(const float* __restrict__ w2, const float* __restrict__ b2) {
    __shared__ float se[TE_];
    const int n = blockIdx.y, tid = threadIdx.x;
    se[tid] = g_t1[n*TE_ + tid];
    se[tid + 256] = g_t1[n*TE_ + tid + 256];
    __syncthreads();
    const int w = tid >> 5, lane = tid & 31;
    const int o = blockIdx.x * 8 + w;
    const float* wr = w2 + (size_t)o * TE_;
    float s = 0.f;
    for (int c = lane; c < TE_; c += 32) s += se[c] * wr[c];
#pragma unroll
    for (int off = 16; off; off >>= 1) s += __shfl_xor_sync(0xffffffffu, s, off);
    if (!lane) g_t2[n*TE_ + o] = s + b2[o];
}
__global__ void tembp_kernel(const float* __restrict__ wp, const float* __restrict__ bp) {
    __shared__ float se[TE_];
    const int n = blockIdx.y, tid = threadIdx.x;
    {
        float v0 = g_t2[n*TE_ + tid], v1 = g_t2[n*TE_ + tid + 256];
        se[tid]       = v0 / (1.f + expf(-v0));
        se[tid + 256] = v1 / (1.f + expf(-v1));
    }
    __syncthreads();
    const int w = tid >> 5, lane = tid & 31;
    const int o = blockIdx.x * 8 + w;
    const float* wr = wp + (size_t)o * TE_;
    float s = 0.f;
    for (int c = lane; c < TE_; c += 32) s += se[c] * wr[c];
#pragma unroll
    for (int off = 16; off; off >>= 1) s += __shfl_xor_sync(0xffffffffu, s, off);
    if (!lane) g_tproj[n*D_ + o] = s + bp[o];
}

// ---------------- conv_in (1x1, 48->64) + time proj; writes fp32 + fp16 ------
__global__ void __launch_bounds__(256) conv_in_kernel(const float* __restrict__ event,
                                                      const float* __restrict__ w,
                                                      const float* __restrict__ b) {
    __shared__ float Et[NC_][64];
    __shared__ float Wt[NC_][64];
    const int n = blockIdx.y, l0 = blockIdx.x * 64;
    const int tid = threadIdx.x, ty4 = (tid >> 4) << 2, tx4 = (tid & 15) << 2;
    for (int e = tid; e < NC_*64; e += 256) {
        int c = e >> 6, tt = e & 63;
        Et[c][tt] = event[(n*NC_ + c)*L_ + l0 + tt];
        Wt[c][tt] = w[tt*NC_ + c];
    }
    __syncthreads();
    float acc[4][4] = {};
#pragma unroll
    for (int c = 0; c < NC_; ++c) {
        const float4 a = *(const float4*)(&Wt[c][ty4]);
        const float4 x4 = *(const float4*)(&Et[c][tx4]);
        acc[0][0]+=a.x*x4.x; acc[0][1]+=a.x*x4.y; acc[0][2]+=a.x*x4.z; acc[0][3]+=a.x*x4.w;
        acc[1][0]+=a.y*x4.x; acc[1][1]+=a.y*x4.y; acc[1][2]+=a.y*x4.z; acc[1][3]+=a.y*x4.w;
        acc[2][0]+=a.z*x4.x; acc[2][1]+=a.z*x4.y; acc[2][2]+=a.z*x4.z; acc[2][3]+=a.z*x4.w;
        acc[3][0]+=a.w*x4.x; acc[3][1]+=a.w*x4.y; acc[3][2]+=a.w*x4.z; acc[3][3]+=a.w*x4.w;
    }
#pragma unroll
    for (int i = 0; i < 4; ++i)
#pragma unroll
        for (int j = 0; j < 4; ++j) {
            int d = ty4 + i, l = l0 + tx4 + j;
            size_t o = (size_t)(n*D_ + d)*L_ + l;
            float v = acc[i][j] + b[d] + g_tproj[n*D_ + d];
            g_fra[o] = v;
            g_fh[o] = __float2half(v);
        }
}

// ================== per-layer HMMA: z=0 conv (5 taps), z=1 q/k/v ==================
// smem: A 5 x 8KB = 40KB ; B 3 x 16KB = 48KB -> 88KB, 2 blocks/SM
#define LA_SMEM (40960 + 49152)

__device__ __forceinline__ void mm64(float acc[2][4][4], uint32_t Ah,
                                     uint32_t Bh, int wm, int wn, int lane) {
    const int lrow = lane & 15, lhalf = lane >> 4;
    const int bk = (lane & 7) + (((lane >> 3) & 1) << 3);
    const int bn8 = (lane >> 4) << 3;
#pragma unroll
    for (int k0 = 0; k0 < 4; ++k0) {
        uint32_t a[2][4];
#pragma unroll
        for (int mt = 0; mt < 2; ++mt) {
            int m = wm*32 + mt*16 + lrow;
            int ch = (k0*2 + lhalf) ^ (m & 7);
            ldsm_x4(a[mt], Ah + m*128 + ch*16);
        }
        uint32_t b[4][2];
#pragma unroll
        for (int ng = 0; ng < 2; ++ng) {
            int k = k0*16 + bk;
            int n = wn*32 + ng*16 + bn8;
            int ch = (n >> 3) ^ (k & 7);
            uint32_t r[4];
            ldsm_x4t(r, Bh + k*256 + ch*16);
            b[ng*2 + 0][0] = r[0]; b[ng*2 + 0][1] = r[1];
            b[ng*2 + 1][0] = r[2]; b[ng*2 + 1][1] = r[3];
        }
#pragma unroll
        for (int mt = 0; mt < 2; ++mt)
#pragma unroll
            for (int nt = 0; nt < 4; ++nt)
                mma_fp16(acc[mt][nt], a[mt][0], a[mt][1], a[mt][2], a[mt][3],
                         b[nt][0], b[nt][1]);
    }
}

__global__ void __launch_bounds__(256) layer_mm_kernel(const float* __restrict__ convb,
                                                       const float* __restrict__ qb,
                                                       const float* __restrict__ kb,
                                                       const float* __restrict__ vb,
                                                       int layer, int dil) {
    extern __shared__ char dsm[];
    char* smA = dsm;            // 5 x 8KB
    char* smB = dsm + 40960;    // 3 x 16KB
    const int tid = threadIdx.x, lane = tid & 31, wid = tid >> 5;
    const int wm = wid >> 2, wn = wid & 3;
    const int l0 = blockIdx.x * 128, nb = blockIdx.y, z = blockIdx.z;
    const __half* fh = g_fh + (size_t)nb * D_ * L_;
    const float* fb = g_fra + (size_t)nb * D_ * L_;

    auto loadA = [&](int slot, int buf) {
        const __half* src = g_AW + (size_t)(layer*8 + slot) * 4096;
        char* dh = smA + buf * 8192;
#pragma unroll
        for (int e = tid; e < 512; e += 256) {
            int m = e >> 3, c = e & 7;
            int off = m*128 + ((c ^ (m & 7)) << 4);
            cp16(smem_u32(dh + off), src + m*64 + c*8);
        }
    };
    auto loadB = [&](int shift, int buf) {
        char* dh = smB + buf * 16384;
        if ((shift & 7) == 0) {
#pragma unroll
            for (int e = tid; e < 1024; e += 256) {
                int k = e >> 4, c = e & 15;
                int gl = l0 + c*8 + shift;
                int off = k*256 + ((c ^ (k & 7)) << 4);
                if (gl >= 0 && gl + 8 <= L_) {
                    cp16(smem_u32(dh + off), fh + (size_t)k * L_ + gl);
                } else {
                    __half* ph = (__half*)(dh + off);
#pragma unroll
                    for (int u = 0; u < 8; ++u) {
                        int l = gl + u;
                        ph[u] = ((unsigned)l < (unsigned)L_) ? fh[(size_t)k * L_ + l] : __half(0.f);
                    }
                }
            }
        } else {
#pragma unroll
            for (int e = tid; e < 1024; e += 256) {
                int k = e >> 4, c = e & 15;
                int gl = l0 + c*8 + shift;
                int off = k*256 + ((c ^ (k & 7)) << 4);
                const float* src = fb + (size_t)k * L_;
                __half hb[8];
#pragma unroll
                for (int u = 0; u < 8; ++u) {
                    int l = gl + u;
                    hb[u] = __float2half(((unsigned)l < (unsigned)L_) ? __ldg(src + l) : 0.f);
                }
                *(uint4*)(dh + off) = *(uint4*)hb;
            }
        }
    };

    float acc[2][4][4];
#pragma unroll
    for (int i = 0; i < 2; ++i)
#pragma unroll
        for (int j = 0; j < 4; ++j)
#pragma unroll
            for (int q = 0; q < 4; ++q) acc[i][j][q] = 0.f;

    const int grp = lane >> 2, qd = (lane & 3) * 2;
    auto epilogue = [&](__half* dst, const float* bias, const __half* qkc) {
#pragma unroll
        for (int mt = 0; mt < 2; ++mt)
#pragma unroll
            for (int nt = 0; nt < 4; ++nt) {
                int m = wm*32 + mt*16 + grp;
                int n = wn*32 + nt*8 + qd;
                float v0 = acc[mt][nt][0] + bias[m];
                float v1 = acc[mt][nt][1] + bias[m];
                float v2 = acc[mt][nt][2] + bias[m + 8];
                float v3 = acc[mt][nt][3] + bias[m + 8];
                if (qkc) {
                    __half2 e0 = *(const __half2*)(qkc + (size_t)m * NCOL_ + n);
                    __half2 e1 = *(const __half2*)(qkc + (size_t)(m + 8) * NCOL_ + n);
                    v0 += __low2float(e0); v1 += __high2float(e0);
                    v2 += __low2float(e1); v3 += __high2float(e1);
                }
                *(__half2*)(dst + (size_t)(nb*D_ + m) * L_ + l0 + n)     = __floats2half2_rn(v0, v1);
                *(__half2*)(dst + (size_t)(nb*D_ + m + 8) * L_ + l0 + n) = __floats2half2_rn(v2, v3);
                acc[mt][nt][0] = acc[mt][nt][1] = acc[mt][nt][2] = acc[mt][nt][3] = 0.f;
            }
    };

    if (z == 0) {
        // dilated conv: 5 taps, A tiles all prefetched, B triple-buffered
        const int tapshift[5] = {-2*dil, -dil, dil, 2*dil, 0};
#pragma unroll
        for (int s = 0; s < 5; ++s) loadA(s, s);
        CP_COMMIT();                       // group: all A
        loadB(tapshift[0], 0); CP_COMMIT();
        loadB(tapshift[1], 1); CP_COMMIT();
        for (int it = 0; it < 5; ++it) {
            if (it + 2 < 5) { loadB(tapshift[it + 2], (it + 2) % 3); CP_COMMIT(); }
            if (it < 3) CP_WAIT2();
            else if (it == 3) CP_WAIT1();
            else CP_WAIT0();
            __syncthreads();
            mm64(acc, smem_u32(smA + it * 8192), smem_u32(smB + (it % 3) * 16384),
                 wm, wn, lane);
        }
        epilogue(g_out1, convb + layer*64, nullptr);
    } else {
        // q/k/v: one B tile, 3 A slots, all prefetched, no intra-loop syncs
        loadB(0, 0);
        loadA(5, 0); loadA(6, 1); loadA(7, 2);
        CP_COMMIT();
        CP_WAIT0();
        __syncthreads();
        const uint32_t Bh = smem_u32(smB);
        mm64(acc, smem_u32(smA), Bh, wm, wn, lane);
        epilogue(g_xq, qb + layer*64, g_QKCh + (size_t)(layer*2)*64*NCOL_ + nb*L_ + l0);
        mm64(acc, smem_u32(smA + 8192), Bh, wm, wn, lane);
        epilogue(g_xk, kb + layer*64, g_QKCh + (size_t)(layer*2 + 1)*64*NCOL_ + nb*L_ + l0);
        mm64(acc, smem_u32(smA + 16384), Bh, wm, wn, lane);
        epilogue(g_xv, vb + layer*64, nullptr);
    }
}

// ---------------- fused attention: scores + softmax + apply + IN partials ----------
__global__ void __launch_bounds__(256) attn_fused_kernel(int dil) {
    __shared__ float satt[5][64];
    const int n = blockIdx.y, l0 = blockIdx.x * 64;
    const int tid = threadIdx.x;

    // ---- stage A: scores + softmax (4 lanes per l) ----
    {
        const int g = tid & 3, l = tid >> 2;
        const int lg = l0 + l;
        const __half* qp = g_xq + (size_t)n * D_ * L_ + lg;
        const __half* kp = g_xk + (size_t)n * D_ * L_;
        bool v[5]; int pc[5];
#pragma unroll
        for (int j = 0; j < 5; ++j) {
            int p = lg + (j - 2) * dil;
            v[j] = ((unsigned)p < (unsigned)L_);
            pc[j] = v[j] ? p : lg;
        }
        float dot[5] = {};
#pragma unroll 4
        for (int c = g; c < 64; c += 4) {
            float qv = __half2float(__ldg(qp + c * L_));
#pragma unroll
            for (int j = 0; j < 5; ++j)
                dot[j] += qv * __half2float(__ldg(kp + c*L_ + pc[j]));
        }
#pragma unroll
        for (int j = 0; j < 5; ++j) {
            dot[j] += __shfl_xor_sync(0xffffffffu, dot[j], 1);
            dot[j] += __shfl_xor_sync(0xffffffffu, dot[j], 2);
        }
        const float LVALID = logf(1.0f + 1e-6f);
        const float LINV   = logf(1e-6f);
        float lg5[5];
#pragma unroll
        for (int j = 0; j < 5; ++j) lg5[j] = v[j] ? dot[j]*0.125f + LVALID : LINV;
        float mx = lg5[0];
#pragma unroll
        for (int j = 1; j < 5; ++j) mx = fmaxf(mx, lg5[j]);
        float e[5], s = 0.f;
#pragma unroll
        for (int j = 0; j < 5; ++j) { e[j] = expf(lg5[j] - mx); s += e[j]; }
        float inv = 1.f / s;
        if (g == 0) {
#pragma unroll
            for (int j = 0; j < 5; ++j) satt[j][l] = v[j] ? e[j]*inv : 0.f;
        }
    }
    __syncthreads();

    // ---- stage B: r = att @ v_win, y = out1 + r, per-channel partial stats ----
    const int tx = tid & 15, ty = tid >> 4;
    const int c0 = ty * 4, lx = tx * 4;
    float s1[4] = {}, s2[4] = {};
#pragma unroll
    for (int ci = 0; ci < 4; ++ci) {
        int c = c0 + ci;
        const __half* vp = g_xv + (size_t)(n*D_ + c) * L_;
        const __half* op = g_out1 + (size_t)(n*D_ + c) * L_ + l0;
        float* yp = g_y + (size_t)(n*D_ + c) * L_ + l0;
        float yv4[4];
#pragma unroll
        for (int lj = 0; lj < 4; ++lj) {
            int l = lx + lj, lgl = l0 + l;
            float r = 0.f;
#pragma unroll
            for (int j = 0; j < 5; ++j) {
                int pp = lgl + (j - 2) * dil;
                if ((unsigned)pp < (unsigned)L_)
                    r += satt[j][l] * __half2float(__ldg(vp + pp));
            }
            float yv = __half2float(op[l]) + r;
            yv4[lj] = yv;
            s1[ci] += yv; s2[ci] += yv * yv;
        }
        *(float4*)(yp + lx) = make_float4(yv4[0], yv4[1], yv4[2], yv4[3]);
    }
#pragma unroll
    for (int off = 8; off; off >>= 1)
#pragma unroll
        for (int ci = 0; ci < 4; ++ci) {
            s1[ci] += __shfl_xor_sync(0xffffffffu, s1[ci], off);
            s2[ci] += __shfl_xor_sync(0xffffffffu, s2[ci], off);
        }
    if (tx == 0) {
#pragma unroll
        for (int ci = 0; ci < 4; ++ci) {
            g_part[((n*D_ + c0 + ci)*128 + blockIdx.x)*2 + 0] = s1[ci];
            g_part[((n*D_ + c0 + ci)*128 + blockIdx.x)*2 + 1] = s2[ci];
        }
    }
}

// ---------------- shared-mem 64x64 micro-matmul (SIMT, for FFN) ----------------
__device__ __forceinline__ void mm_16x16(const float (*Ws)[64], const float (*Xs)[64],
                                         float acc[4][4], int ty4, int tx4) {
#pragma unroll 16
    for (int c = 0; c < 64; ++c) {
        const float4 a = *(const float4*)(&Ws[c][ty4]);
        const float4 b = *(const float4*)(&Xs[c][tx4]);
        acc[0][0] += a.x*b.x; acc[0][1] += a.x*b.y; acc[0][2] += a.x*b.z; acc[0][3] += a.x*b.w;
        acc[1][0] += a.y*b.x; acc[1][1] += a.y*b.y; acc[1][2] += a.y*b.z; acc[1][3] += a.y*b.w;
        acc[2][0] += a.z*b.x; acc[2][1] += a.z*b.y; acc[2][2] += a.z*b.z; acc[2][3] += a.z*b.w;
        acc[3][0] += a.w*b.x; acc[3][1] += a.w*b.y; acc[3][2] += a.w*b.z; acc[3][3] += a.w*b.w;
    }
}

// ---------------- instance-norm stats + FFN + residual; writes fp32 + fp16 ---------
__global__ void __launch_bounds__(256) ffn_kernel(const float* __restrict__ f1b,
                                                  const float* __restrict__ f2b,
                                                  int layer) {
    __shared__ float Xs[64][64];
    __shared__ float Ws[64][64];
    __shared__ float sms[64], srs[64];
    const int n = blockIdx.y, l0 = blockIdx.x * 64;
    const int tid = threadIdx.x, ty4 = (tid >> 4) << 2, tx4 = (tid & 15) << 2;
    if (tid < 64) {
        float s = 0.f, s2 = 0.f;
        for (int bq = 0; bq < 128; ++bq) {
            s  += g_part[((n*D_ + tid)*128 + bq)*2 + 0];
            s2 += g_part[((n*D_ + tid)*128 + bq)*2 + 1];
        }
        float mean = s / (float)L_;
        float var = s2 / (float)L_ - mean*mean;
        sms[tid] = mean;
        srs[tid] = rsqrtf(var + 1e-5f);
    }
    __syncthreads();
    {
        const float* wsrc = g_f1T + (size_t)layer * 4096;
        for (int e = tid; e < 4096; e += 256) {
            int c = e >> 6, tt = e & 63;
            Xs[c][tt] = (g_y[(size_t)(n*D_ + c)*L_ + l0 + tt] - sms[c]) * srs[c];
            ((float*)Ws)[e] = wsrc[e];
        }
    }
    __syncthreads();
    float acc[4][4] = {};
    mm_16x16(Ws, Xs, acc, ty4, tx4);
    __syncthreads();
#pragma unroll
    for (int i = 0; i < 4; ++i)
#pragma unroll
        for (int j = 0; j < 4; ++j)
            Xs[ty4 + i][tx4 + j] = fmaxf(acc[i][j] + f1b[layer*64 + ty4 + i], 0.f);
    {
        const float* wsrc = g_f2T + (size_t)layer * 4096;
        for (int e = tid; e < 4096; e += 256) ((float*)Ws)[e] = wsrc[e];
    }
    __syncthreads();
    float a2[4][4] = {};
    mm_16x16(Ws, Xs, a2, ty4, tx4);
#pragma unroll
    for (int i = 0; i < 4; ++i)
#pragma unroll
        for (int j = 0; j < 4; ++j) {
            int d = ty4 + i, l = l0 + tx4 + j;
            size_t o = (size_t)(n*D_ + d)*L_ + l;
            float nv = g_fra[o] + a2[i][j] + f2b[layer*64 + d];
            g_fra[o] = nv;
            g_fh[o] = __float2half(nv);
        }
}

// ---------------- conv_out (1x1, 64->48) ----------------
__global__ void __launch_bounds__(256) conv_out_kernel(const float* __restrict__ w,
                                                       const float* __restrict__ b,
                                                       float* __restrict__ out) {
    __shared__ float Xs[64][64];
    __shared__ float Wt[64][NC_];
    const int n = blockIdx.y, l0 = blockIdx.x * 64;
    const int tid = threadIdx.x, ty = tid >> 4, tx = tid & 15;
    for (int e = tid; e < 4096; e += 256) {
        int c = e >> 6, tt = e & 63;
        Xs[c][tt] = g_fra[(size_t)(n*D_ + c)*L_ + l0 + tt];
    }
    for (int e = tid; e < 64*NC_; e += 256) {
        int c = e / NC_, o = e % NC_;
        Wt[c][o] = w[o*64 + c];
    }
    __syncthreads();
    if (ty < 12) {
        const int ty4 = ty*4, tx4 = tx*4;
        float acc[4][4] = {};
#pragma unroll 16
        for (int c = 0; c < 64; ++c) {
            const float4 a = *(const float4*)(&Wt[c][ty4]);
            const float4 x4 = *(const float4*)(&Xs[c][tx4]);
            acc[0][0]+=a.x*x4.x; acc[0][1]+=a.x*x4.y; acc[0][2]+=a.x*x4.z; acc[0][3]+=a.x*x4.w;
            acc[1][0]+=a.y*x4.x; acc[1][1]+=a.y*x4.y; acc[1][2]+=a.y*x4.z; acc[1][3]+=a.y*x4.w;
            acc[2][0]+=a.z*x4.x; acc[2][1]+=a.z*x4.y; acc[2][2]+=a.z*x4.z; acc[2][3]+=a.z*x4.w;
            acc[3][0]+=a.w*x4.x; acc[3][1]+=a.w*x4.y; acc[3][2]+=a.w*x4.z; acc[3][3]+=a.w*x4.w;
        }
#pragma unroll
        for (int i = 0; i < 4; ++i)
#pragma unroll
            for (int j = 0; j < 4; ++j) {
                int o = ty4 + i, l = l0 + tx4 + j;
                out[(size_t)(n*NC_ + o)*L_ + l] = acc[i][j] + b[o];
            }
    }
}

// ---------------- host side ----------------
extern "C" void kernel_launch(void* const* d_in, const int* in_sizes, int n_in,
                              void* d_out, int out_size) {
    (void)in_sizes; (void)n_in; (void)out_size;
    const float* x     = (const float*)d_in[0];
    const int*   t     = (const int*)  d_in[1];
    const float* event = (const float*)d_in[2];
    const float* tw1   = (const float*)d_in[3];
    const float* tb1   = (const float*)d_in[4];
    const float* tw2   = (const float*)d_in[5];
    const float* tb2   = (const float*)d_in[6];
    const float* tpw   = (const float*)d_in[7];
    const float* tpb   = (const float*)d_in[8];
    const float* ciw   = (const float*)d_in[9];
    const float* cib   = (const float*)d_in[10];
    const float* cow   = (const float*)d_in[11];
    const float* cob   = (const float*)d_in[12];
    const float* lcw   = (const float*)d_in[13];
    const float* lcb   = (const float*)d_in[14];
    const float* qw    = (const float*)d_in[15];
    const float* qb    = (const float*)d_in[16];
    const float* kw    = (const float*)d_in[17];
    const float* kb    = (const float*)d_in[18];
    const float* vw    = (const float*)d_in[19];
    const float* vb    = (const float*)d_in[20];
    const float* f1w   = (const float*)d_in[21];
    const float* f1b   = (const float*)d_in[22];
    const float* f2w   = (const float*)d_in[23];
    const float* f2b   = (const float*)d_in[24];

    cudaFuncSetAttribute(layer_mm_kernel, cudaFuncAttributeMaxDynamicSharedMemorySize, LA_SMEM);
    cudaFuncSetAttribute(gemm_fp16_kernel, cudaFuncAttributeMaxDynamicSharedMemorySize, GM_SMEM);

    pack_wp_kernel<<<(M_*CR_)/256, 256>>>(qw, kw);
    xt_kernel<<<dim3(L_/32, CR_/32, B_), 256>>>(x);
    pack_aw_kernel<<<(NL_*8*64*64)/256, 256>>>(lcw, qw, kw, vw, f1w, f2w);
    temb1_kernel<<<dim3(64, B_), 256>>>(t, tw1, tb1);
    temb2_kernel<<<dim3(64, B_), 256>>>(tw2, tb2);
    gemm_fp16_kernel<<<dim3(M_/GM_BM, NCOL_/GM_BN), 256, GM_SMEM>>>();
    tembp_kernel<<<dim3(8, B_), 256>>>(tpw, tpb);
    conv_in_kernel<<<dim3(L_/64, B_), 256>>>(event, ciw, cib);

    for (int i = 0; i < NL_; ++i) {
        int dil = 1 << i;
        layer_mm_kernel<<<dim3(L_/128, B_, 2), 256, LA_SMEM>>>(lcb, qb, kb, vb, i, dil);
        attn_fused_kernel<<<dim3(L_/64, B_), 256>>>(dil);
        ffn_kernel<<<dim3(L_/64, B_), 256>>>(f1b, f2b, i);
    }
    conv_out_kernel<<<dim3(L_/64, B_), 256>>>(cow, cob, (float*)d_out);
}

// round 10
// speedup vs baseline: 4.7243x; 1.0105x over previous
#include <cuda_runtime.h>
#include <cuda_bf16.h>
#include <cuda_fp16.h>
#include <math.h>
#include <stdint.h>

#define B_  2
#define L_  8192
#define D_  64
#define CR_ 2048
#define NC_ 48
#define TE_ 512
#define NL_ 8
#define M_  1024        // NL*2*D rows of the batched cross GEMM
#define NCOL_ (B_*L_)   // 16384 columns
#define NBLK 256        // persistent-kernel grid

// ---------------- scratch (device globals; no allocation allowed) ----------------
__device__ __half g_Wp[(size_t)M_*CR_];
__device__ __half g_Xp[(size_t)NCOL_*CR_];
__device__ __half g_QKCh[(size_t)M_*NCOL_];
__device__ __half g_AW[NL_*8*64*64];     // [i][slot][m][k]; slots: taps{0,1,3,4,2},q,k,v
__device__ __half g_fh[B_*D_*L_];
__device__ float g_f1T [NL_*64*64];
__device__ float g_f2T [NL_*64*64];
__device__ float g_fra [B_*D_*L_];
__device__ __half g_xq  [B_*D_*L_];
__device__ __half g_xk  [B_*D_*L_];
__device__ __half g_xv  [B_*D_*L_];
__device__ __half g_out1[B_*D_*L_];
__device__ float g_y   [B_*D_*L_];
__device__ float g_part[B_*D_*128*2];
__device__ float g_tproj[B_*D_];
__device__ float g_t1[B_*TE_];
__device__ float g_t2[B_*TE_];
__device__ unsigned g_barc = 0;
__device__ unsigned g_barg = 0;

__device__ __forceinline__ uint32_t smem_u32(const void* p) {
    return (uint32_t)__cvta_generic_to_shared(p);
}
__device__ __forceinline__ void ldsm_x4(uint32_t* r, uint32_t addr) {
    asm volatile("ldmatrix.sync.aligned.m8n8.x4.shared.b16 {%0,%1,%2,%3}, [%4];"
                 : "=r"(r[0]), "=r"(r[1]), "=r"(r[2]), "=r"(r[3]) : "r"(addr));
}
__device__ __forceinline__ void ldsm_x4t(uint32_t* r, uint32_t addr) {
    asm volatile("ldmatrix.sync.aligned.m8n8.x4.trans.shared.b16 {%0,%1,%2,%3}, [%4];"
                 : "=r"(r[0]), "=r"(r[1]), "=r"(r[2]), "=r"(r[3]) : "r"(addr));
}
__device__ __forceinline__ void mma_fp16(float c[4], uint32_t a0, uint32_t a1, uint32_t a2,
                                         uint32_t a3, uint32_t b0, uint32_t b1) {
    asm volatile("mma.sync.aligned.m16n8k16.row.col.f32.f16.f16.f32 "
                 "{%0,%1,%2,%3}, {%4,%5,%6,%7}, {%8,%9}, {%0,%1,%2,%3};"
                 : "+f"(c[0]), "+f"(c[1]), "+f"(c[2]), "+f"(c[3])
                 : "r"(a0), "r"(a1), "r"(a2), "r"(a3), "r"(b0), "r"(b1));
}
__device__ __forceinline__ void cp16(uint32_t saddr, const void* gptr) {
    asm volatile("cp.async.cg.shared.global [%0], [%1], 16;" :: "r"(saddr), "l"(gptr));
}
#define CP_COMMIT() asm volatile("cp.async.commit_group;")
#define CP_WAIT2() asm volatile("cp.async.wait_group 2;")
#define CP_WAIT1() asm volatile("cp.async.wait_group 1;")
#define CP_WAIT0() asm volatile("cp.async.wait_group 0;")

// grid barrier: all NBLK blocks are co-resident (launch_bounds(256,2) -> 296 slots)
__device__ __forceinline__ void gbar() {
    __syncthreads();
    if (threadIdx.x == 0) {
        __threadfence();
        unsigned gen = g_barg;
        if (atomicAdd(&g_barc, 1u) == NBLK - 1) {
            g_barc = 0;
            __threadfence();
            atomicAdd(&g_barg, 1u);
        } else {
            while (((volatile unsigned*)&g_barg)[0] == gen) { }
        }
        __threadfence();
    }
    __syncthreads();
}

// ================== fp16 HMMA cross GEMM, 3-stage pipeline ==================
#define GM_BM 128
#define GM_BN 128
#define GM_BK 32
#define GM_NT (CR_/GM_BK)
#define APAD 40
#define GM_ST 3
#define GM_TILE (128*APAD)
#define GM_SMEM (GM_ST*2*GM_TILE*2)

__global__ void __launch_bounds__(256) gemm_fp16_kernel() {
    extern __shared__ __half gsm[];
    __half* As = gsm;
    __half* Bs = gsm + GM_ST*GM_TILE;
    const int tid = threadIdx.x, lane = tid & 31, wid = tid >> 5;
    const int wm = wid >> 2, wn = wid & 3;
    const int m0 = blockIdx.x * GM_BM;
    const int col0 = blockIdx.y * GM_BN;
    const int ldr = tid >> 1, ldc = (tid & 1) * 2;

    float acc[4][4][4];
#pragma unroll
    for (int i = 0; i < 4; ++i)
#pragma unroll
        for (int j = 0; j < 4; ++j)
#pragma unroll
            for (int q = 0; q < 4; ++q) acc[i][j][q] = 0.f;

    const int lrow = lane & 15, lhalf = lane >> 4;

    auto load_tile = [&](int kt, int buf) {
        const size_t gk = (size_t)kt * GM_BK;
        __half* ab = As + buf * GM_TILE;
        __half* bb = Bs + buf * GM_TILE;
#pragma unroll
        for (int s = 0; s < 2; ++s) {
            int c = ldc + s;
            cp16(smem_u32(ab + ldr * APAD + c * 8),
                 g_Wp + (size_t)(m0 + ldr) * CR_ + gk + c * 8);
            cp16(smem_u32(bb + ldr * APAD + c * 8),
                 g_Xp + (size_t)(col0 + ldr) * CR_ + gk + c * 8);
        }
        CP_COMMIT();
    };

    load_tile(0, 0);
    load_tile(1, 1);
    for (int kt = 0; kt < GM_NT; ++kt) {
        const int cur = kt % GM_ST;
        CP_WAIT1();
        __syncthreads();
        if (kt + 2 < GM_NT) load_tile(kt + 2, (kt + 2) % GM_ST);
        const __half* ab = As + cur * GM_TILE;
        const __half* bb = Bs + cur * GM_TILE;
#pragma unroll
        for (int kk2 = 0; kk2 < 2; ++kk2) {
            uint32_t a[4][4];
#pragma unroll
            for (int mt = 0; mt < 4; ++mt)
                ldsm_x4(a[mt], smem_u32(ab + (wm*64 + mt*16 + lrow) * APAD + kk2*16 + lhalf*8));
            uint32_t b[4][2];
#pragma unroll
            for (int nb2 = 0; nb2 < 2; ++nb2) {
                uint32_t r[4];
                ldsm_x4(r, smem_u32(bb + (wn*32 + nb2*16 + lrow) * APAD + kk2*16 + lhalf*8));
                b[nb2*2 + 0][0] = r[0]; b[nb2*2 + 0][1] = r[2];
                b[nb2*2 + 1][0] = r[1]; b[nb2*2 + 1][1] = r[3];
            }
#pragma unroll
            for (int mt = 0; mt < 4; ++mt)
#pragma unroll
                for (int nt = 0; nt < 4; ++nt)
                    mma_fp16(acc[mt][nt], a[mt][0], a[mt][1], a[mt][2], a[mt][3],
                             b[nt][0], b[nt][1]);
        }
    }
    const int grp = lane >> 2, qd = (lane & 3) * 2;
#pragma unroll
    for (int mt = 0; mt < 4; ++mt)
#pragma unroll
        for (int nt = 0; nt < 4; ++nt) {
            int m = m0 + wm*64 + mt*16 + grp;
            int n = col0 + wn*32 + nt*8 + qd;
            *(__half2*)(g_QKCh + (size_t)m * NCOL_ + n)       = __floats2half2_rn(acc[mt][nt][0], acc[mt][nt][1]);
            *(__half2*)(g_QKCh + (size_t)(m + 8) * NCOL_ + n) = __floats2half2_rn(acc[mt][nt][2], acc[mt][nt][3]);
        }
}

// ---------------- packing kernels ----------------
__global__ void pack_wp_kernel(const float* __restrict__ qw, const float* __restrict__ kw) {
    int idx = blockIdx.x * 256 + threadIdx.x;
    int m = idx >> 11, c = idx & 2047;
    int i = m >> 7, r = m & 127, s = r >> 6, d = r & 63;
    const float* src = s ? kw : qw;
    g_Wp[(size_t)m * CR_ + c] = __float2half(src[(i*64 + d)*2112 + 64 + c]);
}

__global__ void __launch_bounds__(256) xt_kernel(const float* __restrict__ x) {
    __shared__ float ts[32][33];
    const int lb = blockIdx.x * 32, kb = blockIdx.y * 32, n = blockIdx.z;
    const int tx = threadIdx.x & 31, ty = threadIdx.x >> 5;
#pragma unroll
    for (int r = ty; r < 32; r += 8)
        ts[r][tx] = x[((size_t)n * CR_ + kb + r) * L_ + lb + tx];
    __syncthreads();
#pragma unroll
    for (int r = ty; r < 32; r += 8)
        g_Xp[(size_t)(n * L_ + lb + r) * CR_ + kb + tx] = __float2half(ts[tx][r]);
}

__global__ void pack_aw_kernel(const float* __restrict__ convw, const float* __restrict__ qw,
                               const float* __restrict__ kw,   const float* __restrict__ vw,
                               const float* __restrict__ f1w,  const float* __restrict__ f2w) {
    int idx = blockIdx.x * 256 + threadIdx.x;
    if (idx < NL_*8*64*64) {
        int c = idx & 63, m = (idx >> 6) & 63, s = (idx >> 12) & 7, i = idx >> 15;
        const int tapmap[5] = {0, 1, 3, 4, 2};
        float v;
        if (s < 5)      v = convw[((i*64 + m)*64 + c)*5 + tapmap[s]];
        else if (s == 5) v = qw[(i*64 + m)*2112 + c];
        else if (s == 6) v = kw[(i*64 + m)*2112 + c];
        else             v = vw[(i*64 + m)*64 + c];
        g_AW[(size_t)(i*8 + s) * 4096 + m*64 + c] = __float2half(v);
    }
    if (idx < NL_*64*64) {
        int d = idx & 63, c = (idx >> 6) & 63, i = idx >> 12;
        g_f1T[idx] = f1w[(i*64 + d)*64 + c];
        g_f2T[idx] = f2w[(i*64 + d)*64 + c];
    }
}

// ---------------- timestep embedding ----------------
__global__ void temb1_kernel(const int* __restrict__ t, const float* __restrict__ w1,
                             const float* __restrict__ b1) {
    __shared__ float se[TE_];
    const int n = blockIdx.y, tid = threadIdx.x;
    const float tv = (float)t[n];
    if (tid < 256) {
        float f = expf((float)tid * (-logf(10000.0f) / 255.0f));
        se[tid] = sinf(tv * f);
        se[tid + 256] = cosf(tv * f);
    }
    __syncthreads();
    const int w = tid >> 5, lane = tid & 31;
    const int o = blockIdx.x * 8 + w;
    const float* wr = w1 + (size_t)o * TE_;
    float s = 0.f;
    for (int c = lane; c < TE_; c += 32) s += se[c] * wr[c];
#pragma unroll
    for (int off = 16; off; off >>= 1) s += __shfl_xor_sync(0xffffffffu, s, off);
    if (!lane) { s += b1[o]; g_t1[n*TE_ + o] = s / (1.f + expf(-s)); }
}
__global__ void temb2_kernel(const float* __restrict__ w2, const float* __restrict__ b2) {
    __shared__ float se[TE_];
    const int n = blockIdx.y, tid = threadIdx.x;
    se[tid] = g_t1[n*TE_ + tid];
    se[tid + 256] = g_t1[n*TE_ + tid + 256];
    __syncthreads();
    const int w = tid >> 5, lane = tid & 31;
    const int o = blockIdx.x * 8 + w;
    const float* wr = w2 + (size_t)o * TE_;
    float s = 0.f;
    for (int c = lane; c < TE_; c += 32) s += se[c] * wr[c];
#pragma unroll
    for (int off = 16; off; off >>= 1) s += __shfl_xor_sync(0xffffffffu, s, off);
    if (!lane) g_t2[n*TE_ + o] = s + b2[o];
}
__global__ void tembp_kernel(const float* __restrict__ wp, const float* __restrict__ bp) {
    __shared__ float se[TE_];
    const int n = blockIdx.y, tid = threadIdx.x;
    {
        float v0 = g_t2[n*TE_ + tid], v1 = g_t2[n*TE_ + tid + 256];
        se[tid]       = v0 / (1.f + expf(-v0));
        se[tid + 256] = v1 / (1.f + expf(-v1));
    }
    __syncthreads();
    const int w = tid >> 5, lane = tid & 31;
    const int o = blockIdx.x * 8 + w;
    const float* wr = wp + (size_t)o * TE_;
    float s = 0.f;
    for (int c = lane; c < TE_; c += 32) s += se[c] * wr[c];
#pragma unroll
    for (int off = 16; off; off >>= 1) s += __shfl_xor_sync(0xffffffffu, s, off);
    if (!lane) g_tproj[n*D_ + o] = s + bp[o];
}

// ---------------- conv_in ----------------
__global__ void __launch_bounds__(256) conv_in_kernel(const float* __restrict__ event,
                                                      const float* __restrict__ w,
                                                      const float* __restrict__ b) {
    __shared__ float Et[NC_][64];
    __shared__ float Wt[NC_][64];
    const int n = blockIdx.y, l0 = blockIdx.x * 64;
    const int tid = threadIdx.x, ty4 = (tid >> 4) << 2, tx4 = (tid & 15) << 2;
    for (int e = tid; e < NC_*64; e += 256) {
        int c = e >> 6, tt = e & 63;
        Et[c][tt] = event[(n*NC_ + c)*L_ + l0 + tt];
        Wt[c][tt] = w[tt*NC_ + c];
    }
    __syncthreads();
    float acc[4][4] = {};
#pragma unroll
    for (int c = 0; c < NC_; ++c) {
        const float4 a = *(const float4*)(&Wt[c][ty4]);
        const float4 x4 = *(const float4*)(&Et[c][tx4]);
        acc[0][0]+=a.x*x4.x; acc[0][1]+=a.x*x4.y; acc[0][2]+=a.x*x4.z; acc[0][3]+=a.x*x4.w;
        acc[1][0]+=a.y*x4.x; acc[1][1]+=a.y*x4.y; acc[1][2]+=a.y*x4.z; acc[1][3]+=a.y*x4.w;
        acc[2][0]+=a.z*x4.x; acc[2][1]+=a.z*x4.y; acc[2][2]+=a.z*x4.z; acc[2][3]+=a.z*x4.w;
        acc[3][0]+=a.w*x4.x; acc[3][1]+=a.w*x4.y; acc[3][2]+=a.w*x4.z; acc[3][3]+=a.w*x4.w;
    }
#pragma unroll
    for (int i = 0; i < 4; ++i)
#pragma unroll
        for (int j = 0; j < 4; ++j) {
            int d = ty4 + i, l = l0 + tx4 + j;
            size_t o = (size_t)(n*D_ + d)*L_ + l;
            float v = acc[i][j] + b[d] + g_tproj[n*D_ + d];
            g_fra[o] = v;
            g_fh[o] = __float2half(v);
        }
}

// ================== persistent layers kernel ==================
#define LA_SMEM (40960 + 49152)   // 88 KB: A 5x8KB | B 3x16KB (phases alias this)

__device__ __forceinline__ void mm64(float acc[2][4][4], uint32_t Ah,
                                     uint32_t Bh, int wm, int wn, int lane) {
    const int lrow = lane & 15, lhalf = lane >> 4;
    const int bk = (lane & 7) + (((lane >> 3) & 1) << 3);
    const int bn8 = (lane >> 4) << 3;
#pragma unroll
    for (int k0 = 0; k0 < 4; ++k0) {
        uint32_t a[2][4];
#pragma unroll
        for (int mt = 0; mt < 2; ++mt) {
            int m = wm*32 + mt*16 + lrow;
            int ch = (k0*2 + lhalf) ^ (m & 7);
            ldsm_x4(a[mt], Ah + m*128 + ch*16);
        }
        uint32_t b[4][2];
#pragma unroll
        for (int ng = 0; ng < 2; ++ng) {
            int k = k0*16 + bk;
            int n = wn*32 + ng*16 + bn8;
            int ch = (n >> 3) ^ (k & 7);
            uint32_t r[4];
            ldsm_x4t(r, Bh + k*256 + ch*16);
            b[ng*2 + 0][0] = r[0]; b[ng*2 + 0][1] = r[1];
            b[ng*2 + 1][0] = r[2]; b[ng*2 + 1][1] = r[3];
        }
#pragma unroll
        for (int mt = 0; mt < 2; ++mt)
#pragma unroll
            for (int nt = 0; nt < 4; ++nt)
                mma_fp16(acc[mt][nt], a[mt][0], a[mt][1], a[mt][2], a[mt][3],
                         b[nt][0], b[nt][1]);
    }
}

__device__ void phaseA(char* dsm, int bidx, int layer, int dil,
                       const float* convb, const float* qb,
                       const float* kb, const float* vb) {
    char* smA = dsm;
    char* smB = dsm + 40960;
    const int tid = threadIdx.x, lane = tid & 31, wid = tid >> 5;
    const int wm = wid >> 2, wn = wid & 3;
    const int l0 = (bidx & 63) * 128;
    const int nb = (bidx >> 6) & 1;
    const int z  = bidx >> 7;
    const __half* fh = g_fh + (size_t)nb * D_ * L_;
    const float* fb = g_fra + (size_t)nb * D_ * L_;

    auto loadA = [&](int slot, int buf) {
        const __half* src = g_AW + (size_t)(layer*8 + slot) * 4096;
        char* dh = smA + buf * 8192;
#pragma unroll
        for (int e = tid; e < 512; e += 256) {
            int m = e >> 3, c = e & 7;
            int off = m*128 + ((c ^ (m & 7)) << 4);
            cp16(smem_u32(dh + off), src + m*64 + c*8);
        }
    };
    auto loadB = [&](int shift, int buf) {
        char* dh = smB + buf * 16384;
        if ((shift & 7) == 0) {
#pragma unroll
            for (int e = tid; e < 1024; e += 256) {
                int k = e >> 4, c = e & 15;
                int gl = l0 + c*8 + shift;
                int off = k*256 + ((c ^ (k & 7)) << 4);
                if (gl >= 0 && gl + 8 <= L_) {
                    cp16(smem_u32(dh + off), fh + (size_t)k * L_ + gl);
                } else {
                    __half* ph = (__half*)(dh + off);
#pragma unroll
                    for (int u = 0; u < 8; ++u) {
                        int l = gl + u;
                        ph[u] = ((unsigned)l < (unsigned)L_) ? fh[(size_t)k * L_ + l] : __half(0.f);
                    }
                }
            }
        } else {
#pragma unroll
            for (int e = tid; e < 1024; e += 256) {
                int k = e >> 4, c = e & 15;
                int gl = l0 + c*8 + shift;
                int off = k*256 + ((c ^ (k & 7)) << 4);
                const float* src = fb + (size_t)k * L_;
                __half hb[8];
#pragma unroll
                for (int u = 0; u < 8; ++u) {
                    int l = gl + u;
                    hb[u] = __float2half(((unsigned)l < (unsigned)L_) ? __ldg(src + l) : 0.f);
                }
                *(uint4*)(dh + off) = *(uint4*)hb;
            }
        }
    };

    float acc[2][4][4];
#pragma unroll
    for (int i = 0; i < 2; ++i)
#pragma unroll
        for (int j = 0; j < 4; ++j)
#pragma unroll
            for (int q = 0; q < 4; ++q) acc[i][j][q] = 0.f;

    const int grp = lane >> 2, qd = (lane & 3) * 2;
    auto epilogue = [&](__half* dst, const float* bias, const __half* qkc) {
#pragma unroll
        for (int mt = 0; mt < 2; ++mt)
#pragma unroll
            for (int nt = 0; nt < 4; ++nt) {
                int m = wm*32 + mt*16 + grp;
                int n = wn*32 + nt*8 + qd;
                float v0 = acc[mt][nt][0] + bias[m];
                float v1 = acc[mt][nt][1] + bias[m];
                float v2 = acc[mt][nt][2] + bias[m + 8];
                float v3 = acc[mt][nt][3] + bias[m + 8];
                if (qkc) {
                    __half2 e0 = *(const __half2*)(qkc + (size_t)m * NCOL_ + n);
                    __half2 e1 = *(const __half2*)(qkc + (size_t)(m + 8) * NCOL_ + n);
                    v0 += __low2float(e0); v1 += __high2float(e0);
                    v2 += __low2float(e1); v3 += __high2float(e1);
                }
                *(__half2*)(dst + (size_t)(nb*D_ + m) * L_ + l0 + n)     = __floats2half2_rn(v0, v1);
                *(__half2*)(dst + (size_t)(nb*D_ + m + 8) * L_ + l0 + n) = __floats2half2_rn(v2, v3);
                acc[mt][nt][0] = acc[mt][nt][1] = acc[mt][nt][2] = acc[mt][nt][3] = 0.f;
            }
    };

    if (z == 0) {
        const int tapshift[5] = {-2*dil, -dil, dil, 2*dil, 0};
#pragma unroll
        for (int s = 0; s < 5; ++s) loadA(s, s);
        CP_COMMIT();
        loadB(tapshift[0], 0); CP_COMMIT();
        loadB(tapshift[1], 1); CP_COMMIT();
        for (int it = 0; it < 5; ++it) {
            if (it + 2 < 5) { loadB(tapshift[it + 2], (it + 2) % 3); CP_COMMIT(); }
            if (it < 3) CP_WAIT2();
            else if (it == 3) CP_WAIT1();
            else CP_WAIT0();
            __syncthreads();
            mm64(acc, smem_u32(smA + it * 8192), smem_u32(smB + (it % 3) * 16384),
                 wm, wn, lane);
        }
        epilogue(g_out1, convb + layer*64, nullptr);
    } else {
        loadB(0, 0);
        loadA(5, 0); loadA(6, 1); loadA(7, 2);
        CP_COMMIT();
        CP_WAIT0();
        __syncthreads();
        const uint32_t Bh = smem_u32(smB);
        mm64(acc, smem_u32(smA), Bh, wm, wn, lane);
        epilogue(g_xq, qb + layer*64, g_QKCh + (size_t)(layer*2)*64*NCOL_ + nb*L_ + l0);
        mm64(acc, smem_u32(smA + 8192), Bh, wm, wn, lane);
        epilogue(g_xk, kb + layer*64, g_QKCh + (size_t)(layer*2 + 1)*64*NCOL_ + nb*L_ + l0);
        mm64(acc, smem_u32(smA + 16384), Bh, wm, wn, lane);
        epilogue(g_xv, vb + layer*64, nullptr);
    }
}

__device__ void phaseB(char* dsm, int bidx, int dil) {
    float (*satt)[64] = (float(*)[64])dsm;
    const int n = bidx >> 7, l0 = (bidx & 127) * 64;
    const int tid = threadIdx.x;
    {
        const int g = tid & 3, l = tid >> 2;
        const int lg = l0 + l;
        const __half* qp = g_xq + (size_t)n * D_ * L_ + lg;
        const __half* kp = g_xk + (size_t)n * D_ * L_;
        bool v[5]; int pc[5];
#pragma unroll
        for (int j = 0; j < 5; ++j) {
            int p = lg + (j - 2) * dil;
            v[j] = ((unsigned)p < (unsigned)L_);
            pc[j] = v[j] ? p : lg;
        }
        float dot[5] = {};
#pragma unroll 4
        for (int c = g; c < 64; c += 4) {
            float qv = __half2float(__ldg(qp + c * L_));
#pragma unroll
            for (int j = 0; j < 5; ++j)
                dot[j] += qv * __half2float(__ldg(kp + c*L_ + pc[j]));
        }
#pragma unroll
        for (int j = 0; j < 5; ++j) {
            dot[j] += __shfl_xor_sync(0xffffffffu, dot[j], 1);
            dot[j] += __shfl_xor_sync(0xffffffffu, dot[j], 2);
        }
        const float LVALID = logf(1.0f + 1e-6f);
        const float LINV   = logf(1e-6f);
        float lg5[5];
#pragma unroll
        for (int j = 0; j < 5; ++j) lg5[j] = v[j] ? dot[j]*0.125f + LVALID : LINV;
        float mx = lg5[0];
#pragma unroll
        for (int j = 1; j < 5; ++j) mx = fmaxf(mx, lg5[j]);
        float e[5], s = 0.f;
#pragma unroll
        for (int j = 0; j < 5; ++j) { e[j] = expf(lg5[j] - mx); s += e[j]; }
        float inv = 1.f / s;
        if (g == 0) {
#pragma unroll
            for (int j = 0; j < 5; ++j) satt[j][l] = v[j] ? e[j]*inv : 0.f;
        }
    }
    __syncthreads();

    const int tx = tid & 15, ty = tid >> 4;
    const int c0 = ty * 4, lx = tx * 4;
    float s1[4] = {}, s2[4] = {};
#pragma unroll
    for (int ci = 0; ci < 4; ++ci) {
        int c = c0 + ci;
        const __half* vp = g_xv + (size_t)(n*D_ + c) * L_;
        const __half* op = g_out1 + (size_t)(n*D_ + c) * L_ + l0;
        float* yp = g_y + (size_t)(n*D_ + c) * L_ + l0;
        float yv4[4];
#pragma unroll
        for (int lj = 0; lj < 4; ++lj) {
            int l = lx + lj, lgl = l0 + l;
            float r = 0.f;
#pragma unroll
            for (int j = 0; j < 5; ++j) {
                int pp = lgl + (j - 2) * dil;
                if ((unsigned)pp < (unsigned)L_)
                    r += satt[j][l] * __half2float(__ldg(vp + pp));
            }
            float yv = __half2float(op[l]) + r;
            yv4[lj] = yv;
            s1[ci] += yv; s2[ci] += yv * yv;
        }
        *(float4*)(yp + lx) = make_float4(yv4[0], yv4[1], yv4[2], yv4[3]);
    }
#pragma unroll
    for (int off = 8; off; off >>= 1)
#pragma unroll
        for (int ci = 0; ci < 4; ++ci) {
            s1[ci] += __shfl_xor_sync(0xffffffffu, s1[ci], off);
            s2[ci] += __shfl_xor_sync(0xffffffffu, s2[ci], off);
        }
    if (tx == 0) {
#pragma unroll
        for (int ci = 0; ci < 4; ++ci) {
            g_part[((n*D_ + c0 + ci)*128 + (bidx & 127))*2 + 0] = s1[ci];
            g_part[((n*D_ + c0 + ci)*128 + (bidx & 127))*2 + 1] = s2[ci];
        }
    }
}

__device__ __forceinline__ void mm_16x16(const float (*Ws)[64], const float (*Xs)[64],
                                         float acc[4][4], int ty4, int tx4) {
#pragma unroll 16
    for (int c = 0; c < 64; ++c) {
        const float4 a = *(const float4*)(&Ws[c][ty4]);
        const float4 b = *(const float4*)(&Xs[c][tx4]);
        acc[0][0] += a.x*b.x; acc[0][1] += a.x*b.y; acc[0][2] += a.x*b.z; acc[0][3] += a.x*b.w;
        acc[1][0] += a.y*b.x; acc[1][1] += a.y*b.y; acc[1][2] += a.y*b.z; acc[1][3] += a.y*b.w;
        acc[2][0] += a.z*b.x; acc[2][1] += a.z*b.y; acc[2][2] += a.z*b.z; acc[2][3] += a.z*b.w;
        acc[3][0] += a.w*b.x; acc[3][1] += a.w*b.y; acc[3][2] += a.w*b.z; acc[3][3] += a.w*b.w;
    }
}

__device__ void phaseC(char* dsm, int bidx, int layer,
                       const float* f1b, const float* f2b) {
    float (*Xs)[64] = (float(*)[64])dsm;
    float (*Ws)[64] = (float(*)[64])(dsm + 16384);
    float* sms = (float*)(dsm + 32768);
    float* srs = sms + 64;
    const int n = bidx >> 7, l0 = (bidx & 127) * 64;
    const int tid = threadIdx.x, ty4 = (tid >> 4) << 2, tx4 = (tid & 15) << 2;
    if (tid < 64) {
        float s = 0.f, s2 = 0.f;
        for (int bq = 0; bq < 128; ++bq) {
            s  += g_part[((n*D_ + tid)*128 + bq)*2 + 0];
            s2 += g_part[((n*D_ + tid)*128 + bq)*2 + 1];
        }
        float mean = s / (float)L_;
        float var = s2 / (float)L_ - mean*mean;
        sms[tid] = mean;
        srs[tid] = rsqrtf(var + 1e-5f);
    }
    __syncthreads();
    {
        const float* wsrc = g_f1T + (size_t)layer * 4096;
        for (int e = tid; e < 4096; e += 256) {
            int c = e >> 6, tt = e & 63;
            Xs[c][tt] = (g_y[(size_t)(n*D_ + c)*L_ + l0 + tt] - sms[c]) * srs[c];
            ((float*)Ws)[e] = wsrc[e];
        }
    }
    __syncthreads();
    float acc[4][4] = {};
    mm_16x16(Ws, Xs, acc, ty4, tx4);
    __syncthreads();
#pragma unroll
    for (int i = 0; i < 4; ++i)
#pragma unroll
        for (int j = 0; j < 4; ++j)
            Xs[ty4 + i][tx4 + j] = fmaxf(acc[i][j] + f1b[layer*64 + ty4 + i], 0.f);
    {
        const float* wsrc = g_f2T + (size_t)layer * 4096;
        for (int e = tid; e < 4096; e += 256) ((float*)Ws)[e] = wsrc[e];
    }
    __syncthreads();
    float a2[4][4] = {};
    mm_16x16(Ws, Xs, a2, ty4, tx4);
#pragma unroll
    for (int i = 0; i < 4; ++i)
#pragma unroll
        for (int j = 0; j < 4; ++j) {
            int d = ty4 + i, l = l0 + tx4 + j;
            size_t o = (size_t)(n*D_ + d)*L_ + l;
            float nv = g_fra[o] + a2[i][j] + f2b[layer*64 + d];
            g_fra[o] = nv;
            g_fh[o] = __float2half(nv);
        }
}

__device__ void phaseOut(char* dsm, int bidx, const float* w, const float* b, float* out) {
    float (*Xs)[64] = (float(*)[64])dsm;
    float (*Wt)[NC_] = (float(*)[NC_])(dsm + 16384);
    const int n = bidx >> 7, l0 = (bidx & 127) * 64;
    const int tid = threadIdx.x, ty = tid >> 4, tx = tid & 15;
    for (int e = tid; e < 4096; e += 256) {
        int c = e >> 6, tt = e & 63;
        Xs[c][tt] = g_fra[(size_t)(n*D_ + c)*L_ + l0 + tt];
    }
    for (int e = tid; e < 64*NC_; e += 256) {
        int c = e / NC_, o = e % NC_;
        Wt[c][o] = w[o*64 + c];
    }
    __syncthreads();
    if (ty < 12) {
        const int ty4 = ty*4, tx4 = tx*4;
        float acc[4][4] = {};
#pragma unroll 16
        for (int c = 0; c < 64; ++c) {
            const float4 a = *(const float4*)(&Wt[c][ty4]);
            const float4 x4 = *(const float4*)(&Xs[c][tx4]);
            acc[0][0]+=a.x*x4.x; acc[0][1]+=a.x*x4.y; acc[0][2]+=a.x*x4.z; acc[0][3]+=a.x*x4.w;
            acc[1][0]+=a.y*x4.x; acc[1][1]+=a.y*x4.y; acc[1][2]+=a.y*x4.z; acc[1][3]+=a.y*x4.w;
            acc[2][0]+=a.z*x4.x; acc[2][1]+=a.z*x4.y; acc[2][2]+=a.z*x4.z; acc[2][3]+=a.z*x4.w;
            acc[3][0]+=a.w*x4.x; acc[3][1]+=a.w*x4.y; acc[3][2]+=a.w*x4.z; acc[3][3]+=a.w*x4.w;
        }
#pragma unroll
        for (int i = 0; i < 4; ++i)
#pragma unroll
            for (int j = 0; j < 4; ++j) {
                int o = ty4 + i, l = l0 + tx4 + j;
                out[(size_t)(n*NC_ + o)*L_ + l] = acc[i][j] + b[o];
            }
    }
}

__global__ void __launch_bounds__(256, 2) layers_kernel(
        const float* __restrict__ convb, const float* __restrict__ qb,
        const float* __restrict__ kb,   const float* __restrict__ vb,
        const float* __restrict__ f1b,  const float* __restrict__ f2b,
        const float* __restrict__ cow,  const float* __restrict__ cob,
        float* __restrict__ out) {
    extern __shared__ char dsm[];
    const int bidx = blockIdx.x;
    for (int layer = 0; layer < NL_; ++layer) {
        const int dil = 1 << layer;
        phaseA(dsm, bidx, layer, dil, convb, qb, kb, vb);
        gbar();
        phaseB(dsm, bidx, dil);
        gbar();
        phaseC(dsm, bidx, layer, f1b, f2b);
        gbar();
    }
    phaseOut(dsm, bidx, cow, cob, out);
}

// ---------------- host side ----------------
extern "C" void kernel_launch(void* const* d_in, const int* in_sizes, int n_in,
                              void* d_out, int out_size) {
    (void)in_sizes; (void)n_in; (void)out_size;
    const float* x     = (const float*)d_in[0];
    const int*   t     = (const int*)  d_in[1];
    const float* event = (const float*)d_in[2];
    const float* tw1   = (const float*)d_in[3];
    const float* tb1   = (const float*)d_in[4];
    const float* tw2   = (const float*)d_in[5];
    const float* tb2   = (const float*)d_in[6];
    const float* tpw   = (const float*)d_in[7];
    const float* tpb   = (const float*)d_in[8];
    const float* ciw   = (const float*)d_in[9];
    const float* cib   = (const float*)d_in[10];
    const float* cow   = (const float*)d_in[11];
    const float* cob   = (const float*)d_in[12];
    const float* lcw   = (const float*)d_in[13];
    const float* lcb   = (const float*)d_in[14];
    const float* qw    = (const float*)d_in[15];
    const float* qb    = (const float*)d_in[16];
    const float* kw    = (const float*)d_in[17];
    const float* kb    = (const float*)d_in[18];
    const float* vw    = (const float*)d_in[19];
    const float* vb    = (const float*)d_in[20];
    const float* f1w   = (const float*)d_in[21];
    const float* f1b   = (const float*)d_in[22];
    const float* f2w   = (const float*)d_in[23];
    const float* f2b   = (const float*)d_in[24];

    cudaFuncSetAttribute(layers_kernel, cudaFuncAttributeMaxDynamicSharedMemorySize, LA_SMEM);
    cudaFuncSetAttribute(gemm_fp16_kernel, cudaFuncAttributeMaxDynamicSharedMemorySize, GM_SMEM);

    pack_wp_kernel<<<(M_*CR_)/256, 256>>>(qw, kw);
    xt_kernel<<<dim3(L_/32, CR_/32, B_), 256>>>(x);
    pack_aw_kernel<<<(NL_*8*64*64)/256, 256>>>(lcw, qw, kw, vw, f1w, f2w);
    temb1_kernel<<<dim3(64, B_), 256>>>(t, tw1, tb1);
    temb2_kernel<<<dim3(64, B_), 256>>>(tw2, tb2);
    gemm_fp16_kernel<<<dim3(M_/GM_BM, NCOL_/GM_BN), 256, GM_SMEM>>>();
    tembp_kernel<<<dim3(8, B_), 256>>>(tpw, tpb);
    conv_in_kernel<<<dim3(L_/64, B_), 256>>>(event, ciw, cib);

    layers_kernel<<<NBLK, 256, LA_SMEM>>>(lcb, qb, kb, vb, f1b, f2b, cow, cob, (float*)d_out);
}